// round 2
// baseline (speedup 1.0000x reference)
#include <cuda_runtime.h>

// ============================================================================
// AllegroLayer edge-MLP, fp32 with f32x2 packed FMA (sm_103a).
//
// Trick: x@W1 decomposes by row-blocks of W1. node_i / node_j contributions
// are precomputed per-node into g_proj[n][0:64] / g_proj[n][64:128] (kernel A),
// so the per-edge GEMM only covers edge_feats (K=64) and rbf (K=16), and the
// gather becomes a 512B read from an L2-resident 25.6MB table.
//
// edge_index dtype is detected at runtime (JAX default config downcasts the
// declared int64 to int32; we handle both).
// ============================================================================

#define N_NODES_MAX 50048
__device__ float g_proj[(size_t)N_NODES_MAX * 128];
__device__ int g_is64;

typedef unsigned long long ull;

__device__ __forceinline__ ull pk2(float lo, float hi) {
    ull r;
    asm("mov.b64 %0, {%1, %2};" : "=l"(r) : "f"(lo), "f"(hi));
    return r;
}
__device__ __forceinline__ void upk2(ull v, float& lo, float& hi) {
    asm("mov.b64 {%0, %1}, %2;" : "=f"(lo), "=f"(hi) : "l"(v));
}
// Packed dual-FMA: d.lo += a.lo*b.lo; d.hi += a.hi*b.hi  (one instruction)
__device__ __forceinline__ void fma2(ull& d, ull a, ull b) {
    asm("fma.rn.f32x2 %0, %1, %2, %0;" : "+l"(d) : "l"(a), "l"(b));
}
__device__ __forceinline__ float silu_f(float x) {
    return __fdividef(x, 1.f + __expf(-x));
}

// One K-step of the per-thread GEMM: acc[0..31] (packed pairs over 64 output
// cols) += xk * W[k][:]. W row read via broadcast LDS.128 (conflict-free).
__device__ __forceinline__ void gemm_step(ull* acc, float xk, const float* wrow) {
    ull xk2 = pk2(xk, xk);
    const ulonglong2* w = (const ulonglong2*)wrow;
#pragma unroll
    for (int m = 0; m < 16; ++m) {
        ulonglong2 ww = w[m];
        fma2(acc[2 * m],     xk2, ww.x);
        fma2(acc[2 * m + 1], xk2, ww.y);
    }
}

// ============================================================================
// Kernel 0: detect edge_index dtype. If the buffer holds int64 values, the
// odd 32-bit words are high words of small non-negative indices -> all zero.
// If int32, odd words are random indices in [0, 50000) -> ~surely nonzero.
// ============================================================================
__global__ void detect_idx_kernel(const unsigned int* __restrict__ w) {
    unsigned int acc = 0;
#pragma unroll
    for (int i = 1; i < 256; i += 2) acc |= w[i];
    g_is64 = (acc == 0) ? 1 : 0;
}

// ============================================================================
// Kernel A: per-node projections.
//   g_proj[n][j]      = sum_d nf[n][d] * W1[64+d][j]     (node_i slot)
//   g_proj[n][64+j]   = sum_d nf[n][d] * W1[128+d][j]    (node_j slot)
// ============================================================================
__global__ void __launch_bounds__(256) node_proj_kernel(
    const float* __restrict__ nf, const float* __restrict__ W1, int N)
{
    __shared__ float Wn[64 * 128];   // [d][jj]: jj<64 -> i-slot, jj>=64 -> j-slot
    __shared__ float nfs[16 * 65];   // padded (65) for conflict-free reads

    int tid = threadIdx.x;
    for (int i = tid; i < 64 * 128; i += 256) {
        int d = i >> 7, jj = i & 127;
        Wn[i] = (jj < 64) ? W1[(64 + d) * 64 + jj]
                          : W1[(128 + d) * 64 + (jj - 64)];
    }
    int n0 = blockIdx.x * 16;
    for (int i = tid; i < 16 * 64; i += 256) {
        int nl = i >> 6, d = i & 63;
        int n = n0 + nl;
        nfs[nl * 65 + d] = (n < N) ? nf[(size_t)n * 64 + d] : 0.f;
    }
    __syncthreads();

    int nl = tid & 15;
    int j0 = (tid >> 4) * 8;       // 16 groups of 8 cols cover 128
    float acc[8] = {0.f, 0.f, 0.f, 0.f, 0.f, 0.f, 0.f, 0.f};
#pragma unroll 4
    for (int d = 0; d < 64; ++d) {
        float v = nfs[nl * 65 + d];
        const float4* w = (const float4*)(Wn + d * 128 + j0);
        float4 w0 = w[0], w1 = w[1];
        acc[0] += v * w0.x; acc[1] += v * w0.y; acc[2] += v * w0.z; acc[3] += v * w0.w;
        acc[4] += v * w1.x; acc[5] += v * w1.y; acc[6] += v * w1.z; acc[7] += v * w1.w;
    }
    int n = n0 + nl;
    if (n < N) {
        float4* o = (float4*)(g_proj + (size_t)n * 128 + j0);
        o[0] = make_float4(acc[0], acc[1], acc[2], acc[3]);
        o[1] = make_float4(acc[4], acc[5], acc[6], acc[7]);
    }
}

// ============================================================================
// Kernel B: main edge MLP. 128 edges/CTA, 1 edge/thread.
// ============================================================================
#define SM_XS   0
#define SM_RS   (128 * 68)                  // 8704
#define SM_W1E  (SM_RS + 128 * 20)          // 11264
#define SM_W1R  (SM_W1E + 64 * 64)          // 15360
#define SM_W2   (SM_W1R + 16 * 64)          // 16384
#define SM_W3   (SM_W2 + 64 * 64)           // 20480
#define SM_B1   (SM_W3 + 64 * 64)           // 24576
#define SM_B2   (SM_B1 + 64)
#define SM_B3   (SM_B2 + 64)
#define SM_G    (SM_B3 + 64)
#define SM_BT   (SM_G + 64)
#define SM_FLOATS (SM_BT + 64)              // 24896
#define SMEM_BYTES (SM_FLOATS * 4)          // 99584

__global__ void __launch_bounds__(128) edge_mlp_kernel(
    const float* __restrict__ ef, const void* __restrict__ eidx_raw,
    const float* __restrict__ rbf,
    const float* __restrict__ W1, const float* __restrict__ b1,
    const float* __restrict__ W2, const float* __restrict__ b2,
    const float* __restrict__ W3, const float* __restrict__ b3,
    const float* __restrict__ gamma, const float* __restrict__ beta,
    float* __restrict__ out, int E)
{
    extern __shared__ float sm[];
    int tid = threadIdx.x;
    long long base = (long long)blockIdx.x * 128;

    // ---- stage weights (once per CTA) ----
    for (int i = tid; i < 64 * 64; i += 128) sm[SM_W1E + i] = W1[i];
    for (int i = tid; i < 16 * 64; i += 128) sm[SM_W1R + i] = W1[192 * 64 + i];
    for (int i = tid; i < 64 * 64; i += 128) sm[SM_W2 + i] = W2[i];
    for (int i = tid; i < 64 * 64; i += 128) sm[SM_W3 + i] = W3[i];
    if (tid < 64) {
        sm[SM_B1 + tid] = b1[tid];
        sm[SM_B2 + tid] = b2[tid];
        sm[SM_B3 + tid] = b3[tid];
        sm[SM_G + tid]  = gamma[tid];
        sm[SM_BT + tid] = beta[tid];
    }

    // ---- stage edge_feats tile (coalesced float4) ----
#pragma unroll
    for (int it = 0; it < 16; ++it) {
        int i4 = it * 128 + tid;          // 0..2047
        int r = i4 >> 4, k4 = i4 & 15;
        long long e = base + r;
        float4 v = (e < E) ? ((const float4*)ef)[e * 16 + k4]
                           : make_float4(0.f, 0.f, 0.f, 0.f);
        *(float4*)&sm[SM_XS + r * 68 + k4 * 4] = v;
    }
    // ---- stage rbf tile ----
#pragma unroll
    for (int it = 0; it < 4; ++it) {
        int i4 = it * 128 + tid;          // 0..511
        int r = i4 >> 2, k4 = i4 & 3;
        long long e = base + r;
        float4 v = (e < E) ? ((const float4*)rbf)[e * 4 + k4]
                           : make_float4(0.f, 0.f, 0.f, 0.f);
        *(float4*)&sm[SM_RS + r * 20 + k4 * 4] = v;
    }
    __syncthreads();

    long long e = base + tid;
    bool valid = (e < E);
    long long row = 0, col = 0;
    if (valid) {
        if (g_is64) {
            const long long* p = (const long long*)eidx_raw;
            row = p[e];
            col = p[(long long)E + e];
        } else {
            const int* p = (const int*)eidx_raw;
            row = p[e];
            col = p[(long long)E + e];
        }
        // defensive clamp: bad index -> wrong value, never a crash
        if (row < 0) row = 0; if (row >= N_NODES_MAX) row = N_NODES_MAX - 1;
        if (col < 0) col = 0; if (col >= N_NODES_MAX) col = N_NODES_MAX - 1;
    }
    const float4* pI = (const float4*)(g_proj + row * 128);       // node_i proj
    const float4* pJ = (const float4*)(g_proj + col * 128 + 64);  // node_j proj

    // ---- layer 1: acc = b1 + proj_i + proj_j + edge@W1e + rbf@W1r ----
    ull acc[32];
#pragma unroll
    for (int m = 0; m < 16; ++m) {
        float4 bb = ((const float4*)&sm[SM_B1])[m];
        float4 a = pI[m];
        float4 b = pJ[m];
        acc[2 * m]     = pk2(bb.x + a.x + b.x, bb.y + a.y + b.y);
        acc[2 * m + 1] = pk2(bb.z + a.z + b.z, bb.w + a.w + b.w);
    }
    const float* xrow = sm + SM_XS + tid * 68;
    const float* rrow = sm + SM_RS + tid * 20;
#pragma unroll
    for (int k = 0; k < 64; ++k)
        gemm_step(acc, xrow[k], sm + SM_W1E + k * 64);
#pragma unroll
    for (int k = 0; k < 16; ++k)
        gemm_step(acc, rrow[k], sm + SM_W1R + k * 64);

    float h[64];
#pragma unroll
    for (int p = 0; p < 32; ++p) {
        float a, b;
        upk2(acc[p], a, b);
        h[2 * p] = silu_f(a);
        h[2 * p + 1] = silu_f(b);
    }

    // ---- layer 2 ----
#pragma unroll
    for (int m = 0; m < 16; ++m) {
        float4 bb = ((const float4*)&sm[SM_B2])[m];
        acc[2 * m]     = pk2(bb.x, bb.y);
        acc[2 * m + 1] = pk2(bb.z, bb.w);
    }
#pragma unroll
    for (int k = 0; k < 64; ++k)
        gemm_step(acc, h[k], sm + SM_W2 + k * 64);
#pragma unroll
    for (int p = 0; p < 32; ++p) {
        float a, b;
        upk2(acc[p], a, b);
        h[2 * p] = silu_f(a);
        h[2 * p + 1] = silu_f(b);
    }

    // ---- layer 3 ----
#pragma unroll
    for (int m = 0; m < 16; ++m) {
        float4 bb = ((const float4*)&sm[SM_B3])[m];
        acc[2 * m]     = pk2(bb.x, bb.y);
        acc[2 * m + 1] = pk2(bb.z, bb.w);
    }
#pragma unroll
    for (int k = 0; k < 64; ++k)
        gemm_step(acc, h[k], sm + SM_W3 + k * 64);

    // ---- residual + LayerNorm ----
    float y[64];
    float s1 = 0.f, s2 = 0.f;
#pragma unroll
    for (int p = 0; p < 32; ++p) {
        float a, b;
        upk2(acc[p], a, b);
        float ya = xrow[2 * p] + a;
        float yb = xrow[2 * p + 1] + b;
        y[2 * p] = ya;
        y[2 * p + 1] = yb;
        s1 += ya + yb;
        s2 += ya * ya + yb * yb;
    }
    float mu  = s1 * (1.f / 64.f);
    float var = s2 * (1.f / 64.f) - mu * mu;
    float inv = rsqrtf(var + 1e-5f);

    if (valid) {
        float4* o = (float4*)(out + e * 64);
#pragma unroll
        for (int m = 0; m < 16; ++m) {
            float4 g4 = ((const float4*)&sm[SM_G])[m];
            float4 t4 = ((const float4*)&sm[SM_BT])[m];
            float4 r4;
            r4.x = (y[4 * m + 0] - mu) * inv * g4.x + t4.x;
            r4.y = (y[4 * m + 1] - mu) * inv * g4.y + t4.y;
            r4.z = (y[4 * m + 2] - mu) * inv * g4.z + t4.z;
            r4.w = (y[4 * m + 3] - mu) * inv * g4.w + t4.w;
            o[m] = r4;
        }
    }
}

// ============================================================================
// Launch
// ============================================================================
extern "C" void kernel_launch(void* const* d_in, const int* in_sizes, int n_in,
                              void* d_out, int out_size) {
    const float* ef   = (const float*)d_in[0];
    const float* nf   = (const float*)d_in[1];
    const void*  eidx = (const void*)d_in[2];
    const float* rbf  = (const float*)d_in[3];
    const float* W1   = (const float*)d_in[4];
    const float* b1   = (const float*)d_in[5];
    const float* W2   = (const float*)d_in[6];
    const float* b2   = (const float*)d_in[7];
    const float* W3   = (const float*)d_in[8];
    const float* b3   = (const float*)d_in[9];
    const float* gam  = (const float*)d_in[10];
    const float* bet  = (const float*)d_in[11];
    float* out = (float*)d_out;

    int E = in_sizes[0] / 64;
    int N = in_sizes[1] / 64;
    if (N > N_NODES_MAX) N = N_NODES_MAX;

    detect_idx_kernel<<<1, 1>>>((const unsigned int*)eidx);
    node_proj_kernel<<<(N + 15) / 16, 256>>>(nf, W1, N);

    cudaFuncSetAttribute(edge_mlp_kernel,
                         cudaFuncAttributeMaxDynamicSharedMemorySize, SMEM_BYTES);
    int nblk = (E + 127) / 128;
    edge_mlp_kernel<<<nblk, 128, SMEM_BYTES>>>(
        ef, eidx, rbf, W1, b1, W2, b2, W3, b3, gam, bet, out, E);
}

// round 7
// speedup vs baseline: 1.9335x; 1.9335x over previous
#include <cuda_runtime.h>
#include <cuda_bf16.h>
#include <stdint.h>

// ============================================================================
// AllegroLayer edge-MLP (sm_103a).
//
// Dual-path: tcgen05 split-bf16 (hi/lo) when compiled for the arch-specific
// sm_103a target; fp32 f32x2 packed-FMA fallback otherwise (the harness also
// emits a plain compute_103 pass where tcgen05 does not exist).
//
//  - node_i/node_j contributions to layer 1 precomputed per node (g_proj).
//  - tcgen05: per 128-edge tile, A in TMEM (bf16 hi|lo), W in SMEM (SW128),
//    kind::f16 M=128 N=64, fp32 accum. x@W ~= xh@Wh + xl@Wh + xh@Wl.
//  - Persistent CTAs; weights staged once per CTA.
//  - CRITICAL: allocating warp relinquishes the TMEM alloc permit right after
//    alloc — with 2 persistent CTAs/SM, holding it deadlocks the peer CTA.
// ============================================================================

#if defined(__CUDA_ARCH_FEAT_SM103_ALL) || \
    (defined(__CUDA_ARCH_SPECIFIC__) && defined(__CUDA_ARCH__) && (__CUDA_ARCH__ == 1030))
#define HAS_TC 1
#else
#define HAS_TC 0
#endif

#define N_NODES_MAX 50048
#define TILE 128
// idesc kind::f16: dtype=F32(1<<4), atype=BF16(1<<7), btype=BF16(1<<10),
// N/8=8 (<<17), M/16=8 (<<24)
#define IDESC 0x8100490u

__device__ float g_proj[(size_t)N_NODES_MAX * 128];
__device__ int g_is64;
__device__ __align__(16) unsigned char g_wimg[65536];

// weight-image offsets (pre-swizzled bf16 hi/lo tiles, bytes)
#define WI_B1H 0
#define WI_B1L 16384
#define WI_B2H 32768
#define WI_B2L 40960
#define WI_B3H 49152
#define WI_B3L 57344

// SMEM byte offsets (shared by both paths; SM_W holds either the 64KB bf16
// image (tcgen05) or 52KB of fp32 weights (fallback))
#define SM_W    0
#define SM_XS   65536                       // 128 rows * 81 floats = 41472 B
#define SM_VEC  (65536 + 41472)             // 107008
#define SM_B1V  SM_VEC
#define SM_B2V  (SM_VEC + 256)
#define SM_B3V  (SM_VEC + 512)
#define SM_GV   (SM_VEC + 768)
#define SM_BTV  (SM_VEC + 1024)
#define SM_PTR  (SM_VEC + 1280)
#define SM_MBAR (SM_VEC + 1288)
#define SMEM_BYTES (SM_VEC + 1312)          // 108320

// fallback fp32 weight offsets (floats, within SM_W region)
#define FB_W1E  0
#define FB_W1R  (64 * 64)
#define FB_W2   (FB_W1R + 16 * 64)
#define FB_W3   (FB_W2 + 64 * 64)

// TMEM column map (alloc 256 per CTA; 2 CTAs/SM -> 512 total)
#define TM_AHI 0
#define TM_ALO 64
#define TM_D   128

typedef unsigned long long ull;

// ---------------------------------------------------------------------------
// Common helpers
// ---------------------------------------------------------------------------
__device__ __forceinline__ uint32_t smem_u32(const void* p) {
    uint32_t a;
    asm("{ .reg .u64 t; cvta.to.shared.u64 t, %1; cvt.u32.u64 %0, t; }"
        : "=r"(a) : "l"(p));
    return a;
}
__device__ __forceinline__ uint32_t pkbf(float a, float b) {
    __nv_bfloat162 t = __floats2bfloat162_rn(a, b);
    return *(uint32_t*)&t;
}
__device__ __forceinline__ float silu_f(float x) {
    return __fdividef(x, 1.f + __expf(-x));
}
__device__ __forceinline__ ull pk2(float lo, float hi) {
    ull r;
    asm("mov.b64 %0, {%1, %2};" : "=l"(r) : "f"(lo), "f"(hi));
    return r;
}
__device__ __forceinline__ void upk2(ull v, float& lo, float& hi) {
    asm("mov.b64 {%0, %1}, %2;" : "=f"(lo), "=f"(hi) : "l"(v));
}
__device__ __forceinline__ void fma2(ull& d, ull a, ull b) {
    asm("fma.rn.f32x2 %0, %1, %2, %0;" : "+l"(d) : "l"(a), "l"(b));
}

#if HAS_TC
// ---------------------------------------------------------------------------
// tcgen05 helpers (only compiled on the arch-specific pass)
// ---------------------------------------------------------------------------
__device__ __forceinline__ uint32_t elect_one() {
    uint32_t p;
    asm volatile("{\n\t.reg .pred p;\n\telect.sync _|p, 0xFFFFFFFF;\n\t"
                 "selp.b32 %0, 1, 0, p;\n\t}" : "=r"(p));
    return p;
}
__device__ __forceinline__ uint64_t mkdesc(uint32_t addr) {
    return ((uint64_t)2 << 61) | ((uint64_t)1 << 46) | ((uint64_t)64 << 32) |
           ((uint64_t)1 << 16) | ((addr >> 4) & 0x3FFF);
}
#define TC_ALLOC(sa, n) \
    asm volatile("tcgen05.alloc.cta_group::1.sync.aligned.shared::cta.b32 [%0], %1;" \
                 :: "r"(sa), "r"((uint32_t)(n)) : "memory")
#define TC_RELINQ() \
    asm volatile("tcgen05.relinquish_alloc_permit.cta_group::1.sync.aligned;")
#define TC_DEALLOC(t, n) \
    asm volatile("tcgen05.dealloc.cta_group::1.sync.aligned.b32 %0, %1;" :: "r"(t), "r"((uint32_t)(n)))
#define TC_COMMIT(mb) \
    asm volatile("tcgen05.commit.cta_group::1.mbarrier::arrive::one.shared::cluster.b64 [%0];" \
                 :: "r"(mb) : "memory")
#define TC_WAIT_ST() asm volatile("tcgen05.wait::st.sync.aligned;" ::: "memory")
#define TC_WAIT_LD() asm volatile("tcgen05.wait::ld.sync.aligned;" ::: "memory")
#define TC_FENCE_BEFORE() asm volatile("tcgen05.fence::before_thread_sync;" ::: "memory")
#define TC_FENCE_AFTER()  asm volatile("tcgen05.fence::after_thread_sync;" ::: "memory")
#define MB_INIT(mb, c) \
    asm volatile("mbarrier.init.shared.b64 [%0], %1;" :: "r"(mb), "r"((uint32_t)(c)) : "memory")
#define MB_WAIT(mb, par) do { \
    uint32_t _m = (mb), _p = (par), _d; \
    asm volatile("{\n\t.reg .pred p;\n\t" \
        "mbarrier.try_wait.parity.acquire.cta.shared::cta.b64 p, [%1], %2;\n\t" \
        "selp.b32 %0, 1, 0, p;\n\t}" : "=r"(_d) : "r"(_m), "r"(_p) : "memory"); \
    if (!_d) { \
        asm volatile("{\n\t.reg .pred P1;\n\tWL_%=:\n\t" \
            "mbarrier.try_wait.parity.acquire.cta.shared::cta.b64 P1, [%0], %1, 0x989680;\n\t" \
            "@P1 bra.uni WD_%=;\n\tbra.uni WL_%=;\n\tWD_%=:\n\t}" \
            :: "r"(_m), "r"(_p) : "memory"); \
    } } while (0)

#define TMST_X16(addr, r) \
    asm volatile("tcgen05.st.sync.aligned.32x32b.x16.b32 [%0], " \
        "{%1,%2,%3,%4,%5,%6,%7,%8,%9,%10,%11,%12,%13,%14,%15,%16};" \
        :: "r"(addr), \
        "r"((r)[0]),"r"((r)[1]),"r"((r)[2]),"r"((r)[3]),"r"((r)[4]),"r"((r)[5]),"r"((r)[6]),"r"((r)[7]), \
        "r"((r)[8]),"r"((r)[9]),"r"((r)[10]),"r"((r)[11]),"r"((r)[12]),"r"((r)[13]),"r"((r)[14]),"r"((r)[15]) \
        : "memory")
#define TMST_X8(addr, r) \
    asm volatile("tcgen05.st.sync.aligned.32x32b.x8.b32 [%0], " \
        "{%1,%2,%3,%4,%5,%6,%7,%8};" \
        :: "r"(addr), \
        "r"((r)[0]),"r"((r)[1]),"r"((r)[2]),"r"((r)[3]),"r"((r)[4]),"r"((r)[5]),"r"((r)[6]),"r"((r)[7]) \
        : "memory")
#define TMLD_X32(r, addr) \
    asm volatile("tcgen05.ld.sync.aligned.32x32b.x32.b32 " \
        "{%0,%1,%2,%3,%4,%5,%6,%7,%8,%9,%10,%11,%12,%13,%14,%15," \
        "%16,%17,%18,%19,%20,%21,%22,%23,%24,%25,%26,%27,%28,%29,%30,%31}, [%32];" \
        : "=r"((r)[0]),"=r"((r)[1]),"=r"((r)[2]),"=r"((r)[3]),"=r"((r)[4]),"=r"((r)[5]),"=r"((r)[6]),"=r"((r)[7]), \
          "=r"((r)[8]),"=r"((r)[9]),"=r"((r)[10]),"=r"((r)[11]),"=r"((r)[12]),"=r"((r)[13]),"=r"((r)[14]),"=r"((r)[15]), \
          "=r"((r)[16]),"=r"((r)[17]),"=r"((r)[18]),"=r"((r)[19]),"=r"((r)[20]),"=r"((r)[21]),"=r"((r)[22]),"=r"((r)[23]), \
          "=r"((r)[24]),"=r"((r)[25]),"=r"((r)[26]),"=r"((r)[27]),"=r"((r)[28]),"=r"((r)[29]),"=r"((r)[30]),"=r"((r)[31]) \
        : "r"(addr))

__device__ __forceinline__ void mma_f16_ts(uint32_t d, uint32_t a, uint64_t bd,
                                           uint32_t en) {
    asm volatile("{\n\t.reg .pred p;\n\tsetp.ne.u32 p, %5, 0;\n\t"
                 "tcgen05.mma.cta_group::1.kind::f16 [%0], [%1], %2, %3, "
                 "{%4, %4, %4, %4}, p;\n\t}"
                 :: "r"(d), "r"(a), "l"(bd), "r"(IDESC), "r"(0u), "r"(en)
                 : "memory");
}
#endif  // HAS_TC

// ---------------------------------------------------------------------------
// Kernel 0: detect edge_index dtype (int64 vs int32)
// ---------------------------------------------------------------------------
__global__ void detect_idx_kernel(const unsigned int* __restrict__ w) {
    unsigned int acc = 0;
#pragma unroll
    for (int i = 1; i < 256; i += 2) acc |= w[i];
    g_is64 = (acc == 0) ? 1 : 0;
}

// ---------------------------------------------------------------------------
// Kernel P: build hi/lo bf16 weight tiles in pre-swizzled SW128 image layout.
// ---------------------------------------------------------------------------
__global__ void prep_w_kernel(const float* __restrict__ W1,
                              const float* __restrict__ W2,
                              const float* __restrict__ W3) {
    int stride = blockDim.x * gridDim.x;
    int t0 = blockIdx.x * blockDim.x + threadIdx.x;
    for (int i = t0; i < 64 * 128; i += stride) {
        int n = i >> 7, k = i & 127;
        float w = 0.f;
        if (k < 64) w = W1[k * 64 + n];
        else if (k < 80) w = W1[(192 + k - 64) * 64 + n];
        uint32_t bo = ((uint32_t)(n >> 3) + ((uint32_t)(k * 2) >> 7) * 8u) * 1024u
                    + (uint32_t)(n & 7) * 128u + ((uint32_t)(k * 2) & 127u);
        uint32_t sw = bo ^ ((bo >> 3) & 0x70);
        __nv_bfloat16 hi = __float2bfloat16(w);
        __nv_bfloat16 lo = __float2bfloat16(w - __bfloat162float(hi));
        *(__nv_bfloat16*)(g_wimg + WI_B1H + sw) = hi;
        *(__nv_bfloat16*)(g_wimg + WI_B1L + sw) = lo;
    }
    for (int i = t0; i < 64 * 64; i += stride) {
        int n = i >> 6, k = i & 63;
        uint32_t bo = (uint32_t)(n >> 3) * 1024u + (uint32_t)(n & 7) * 128u
                    + (uint32_t)(k * 2);
        uint32_t sw = bo ^ ((bo >> 3) & 0x70);
        float w2 = W2[k * 64 + n];
        __nv_bfloat16 h2 = __float2bfloat16(w2);
        *(__nv_bfloat16*)(g_wimg + WI_B2H + sw) = h2;
        *(__nv_bfloat16*)(g_wimg + WI_B2L + sw) =
            __float2bfloat16(w2 - __bfloat162float(h2));
        float w3 = W3[k * 64 + n];
        __nv_bfloat16 h3 = __float2bfloat16(w3);
        *(__nv_bfloat16*)(g_wimg + WI_B3H + sw) = h3;
        *(__nv_bfloat16*)(g_wimg + WI_B3L + sw) =
            __float2bfloat16(w3 - __bfloat162float(h3));
    }
}

// ---------------------------------------------------------------------------
// Kernel A: per-node projections (fp32, exact)
// ---------------------------------------------------------------------------
__global__ void __launch_bounds__(256) node_proj_kernel(
    const float* __restrict__ nf, const float* __restrict__ W1, int N)
{
    __shared__ float Wn[64 * 128];
    __shared__ float nfs[16 * 65];
    int tid = threadIdx.x;
    for (int i = tid; i < 64 * 128; i += 256) {
        int d = i >> 7, jj = i & 127;
        Wn[i] = (jj < 64) ? W1[(64 + d) * 64 + jj]
                          : W1[(128 + d) * 64 + (jj - 64)];
    }
    int n0 = blockIdx.x * 16;
    for (int i = tid; i < 16 * 64; i += 256) {
        int nl = i >> 6, d = i & 63;
        int n = n0 + nl;
        nfs[nl * 65 + d] = (n < N) ? nf[(size_t)n * 64 + d] : 0.f;
    }
    __syncthreads();
    int nl = tid & 15;
    int j0 = (tid >> 4) * 8;
    float acc[8] = {0.f, 0.f, 0.f, 0.f, 0.f, 0.f, 0.f, 0.f};
#pragma unroll 4
    for (int d = 0; d < 64; ++d) {
        float v = nfs[nl * 65 + d];
        const float4* w = (const float4*)(Wn + d * 128 + j0);
        float4 w0 = w[0], w1 = w[1];
        acc[0] += v * w0.x; acc[1] += v * w0.y; acc[2] += v * w0.z; acc[3] += v * w0.w;
        acc[4] += v * w1.x; acc[5] += v * w1.y; acc[6] += v * w1.z; acc[7] += v * w1.w;
    }
    int n = n0 + nl;
    if (n < N) {
        float4* o = (float4*)(g_proj + (size_t)n * 128 + j0);
        o[0] = make_float4(acc[0], acc[1], acc[2], acc[3]);
        o[1] = make_float4(acc[4], acc[5], acc[6], acc[7]);
    }
}

// fallback per-thread GEMM K-step
__device__ __forceinline__ void gemm_step(ull* acc, float xk, const float* wrow) {
    ull xk2 = pk2(xk, xk);
    const ulonglong2* w = (const ulonglong2*)wrow;
#pragma unroll
    for (int m = 0; m < 16; ++m) {
        ulonglong2 ww = w[m];
        fma2(acc[2 * m],     xk2, ww.x);
        fma2(acc[2 * m + 1], xk2, ww.y);
    }
}

// ---------------------------------------------------------------------------
// Kernel B: persistent edge MLP (tcgen05 or fp32 fallback).
// ---------------------------------------------------------------------------
__global__ void __launch_bounds__(128) edge_tc_kernel(
    const float* __restrict__ ef, const void* __restrict__ eidx_raw,
    const float* __restrict__ rbf,
    const float* __restrict__ W1, const float* __restrict__ W2,
    const float* __restrict__ W3,
    const float* __restrict__ b1, const float* __restrict__ b2,
    const float* __restrict__ b3, const float* __restrict__ gamma,
    const float* __restrict__ beta, float* __restrict__ out,
    int E, int ntiles)
{
    extern __shared__ __align__(1024) unsigned char smraw[];
    float* smf = (float*)smraw;
    int tid = threadIdx.x, wid = tid >> 5;
    int is64 = g_is64;

    if (tid < 64) {
        smf[SM_B1V / 4 + tid] = b1[tid];
        smf[SM_B2V / 4 + tid] = b2[tid];
        smf[SM_B3V / 4 + tid] = b3[tid];
        smf[SM_GV / 4 + tid]  = gamma[tid];
        smf[SM_BTV / 4 + tid] = beta[tid];
    }

#if HAS_TC
    uint32_t smb = smem_u32(smraw);
    // stage pre-swizzled bf16 weight image (64KB) once
    {
        const float4* src = (const float4*)g_wimg;
        float4* dst = (float4*)(smraw + SM_W);
        for (int i = tid; i < 65536 / 16; i += 128) dst[i] = src[i];
    }
    if (tid == 0) MB_INIT(smb + SM_MBAR, 1);
    if (wid == 0) {
        TC_ALLOC(smb + SM_PTR, 256);
        // CRITICAL: give up the alloc permit immediately. This CTA is
        // persistent; holding the permit deadlocks the co-resident CTA's
        // tcgen05.alloc on the same SM.
        TC_RELINQ();
    }
    __syncthreads();
    uint32_t tm;
    asm("ld.shared.b32 %0, [%1];" : "=r"(tm) : "r"(smb + SM_PTR));
    uint32_t wo = (uint32_t)(tid >> 5) << 21;

    uint64_t d_b1h = mkdesc(smb + SM_W + WI_B1H);
    uint64_t d_b1l = mkdesc(smb + SM_W + WI_B1L);
    uint64_t d_b2h = mkdesc(smb + SM_W + WI_B2H);
    uint64_t d_b2l = mkdesc(smb + SM_W + WI_B2L);
    uint64_t d_b3h = mkdesc(smb + SM_W + WI_B3H);
    uint64_t d_b3l = mkdesc(smb + SM_W + WI_B3L);
    uint32_t ph = 0;

    for (int t = blockIdx.x; t < ntiles; t += gridDim.x) {
        long long base = (long long)t * TILE;
        __syncthreads();
        for (int i = tid; i < TILE * 64; i += 128) {
            int r = i >> 6, c = i & 63;
            long long e = base + r; if (e >= E) e = E - 1;
            smf[SM_XS / 4 + r * 81 + c] = ef[e * 64 + c];
        }
        for (int i = tid; i < TILE * 16; i += 128) {
            int r = i >> 4, c = i & 15;
            long long e = base + r; if (e >= E) e = E - 1;
            smf[SM_XS / 4 + r * 81 + 64 + c] = rbf[e * 16 + c];
        }
        __syncthreads();

        long long e = base + tid;
        long long eld = (e < E) ? e : (long long)(E - 1);
        long long nrow, ncol;
        if (is64) {
            const long long* p = (const long long*)eidx_raw;
            nrow = p[eld]; ncol = p[(long long)E + eld];
        } else {
            const int* p = (const int*)eidx_raw;
            nrow = p[eld]; ncol = p[(long long)E + eld];
        }
        if (nrow < 0) nrow = 0; if (nrow >= N_NODES_MAX) nrow = N_NODES_MAX - 1;
        if (ncol < 0) ncol = 0; if (ncol >= N_NODES_MAX) ncol = N_NODES_MAX - 1;

        const float* xr = smf + SM_XS / 4 + tid * 81;

        // ---- convert x (80 vals) to hi/lo bf16x2, store A to TMEM ----
        {
#pragma unroll
            for (int half = 0; half < 2; ++half) {
                uint32_t ah[16], al[16];
#pragma unroll
                for (int c = 0; c < 16; ++c) {
                    int cc = half * 16 + c;
                    float a = xr[2 * cc], b = xr[2 * cc + 1];
                    uint32_t p = pkbf(a, b);
                    __nv_bfloat162 hp = *(__nv_bfloat162*)&p;
                    ah[c] = p;
                    al[c] = pkbf(a - __bfloat162float(hp.x),
                                 b - __bfloat162float(hp.y));
                }
                TMST_X16(tm + TM_AHI + half * 16 + wo, ah);
                TMST_X16(tm + TM_ALO + half * 16 + wo, al);
            }
            uint32_t ah[8], al[8];
#pragma unroll
            for (int c = 0; c < 8; ++c) {
                int cc = 32 + c;
                float a = xr[2 * cc], b = xr[2 * cc + 1];
                uint32_t p = pkbf(a, b);
                __nv_bfloat162 hp = *(__nv_bfloat162*)&p;
                ah[c] = p;
                al[c] = pkbf(a - __bfloat162float(hp.x),
                             b - __bfloat162float(hp.y));
            }
            TMST_X8(tm + TM_AHI + 32 + wo, ah);
            TMST_X8(tm + TM_ALO + 32 + wo, al);
        }
        TC_WAIT_ST();
        TC_FENCE_BEFORE();
        __syncthreads();

        // ---- layer 1 MMAs: 3 terms x 5 K-steps (K=80) ----
        if (wid == 0 && elect_one()) {
            TC_FENCE_AFTER();
            const int doff1[5] = {0, 2, 4, 6, 512};
#pragma unroll
            for (int s = 0; s < 5; ++s)
                mma_f16_ts(tm + TM_D, tm + TM_AHI + s * 8, d_b1h + doff1[s], s > 0);
#pragma unroll
            for (int s = 0; s < 5; ++s)
                mma_f16_ts(tm + TM_D, tm + TM_ALO + s * 8, d_b1h + doff1[s], 1);
#pragma unroll
            for (int s = 0; s < 5; ++s)
                mma_f16_ts(tm + TM_D, tm + TM_AHI + s * 8, d_b1l + doff1[s], 1);
            TC_COMMIT(smb + SM_MBAR);
        }
        MB_WAIT(smb + SM_MBAR, ph); ph ^= 1;
        TC_FENCE_AFTER();

        // ---- epilogue 1: h = silu(d + b1 + proj_i + proj_j), two halves ----
        {
            const float4* pI = (const float4*)(g_proj + nrow * 128);
            const float4* pJ = (const float4*)(g_proj + ncol * 128 + 64);
            const float4* Bv = (const float4*)(smraw + SM_B1V);
#pragma unroll
            for (int half = 0; half < 2; ++half) {
                uint32_t dr[32];
                TMLD_X32(dr, tm + TM_D + half * 32 + wo);
                TC_WAIT_LD();
                uint32_t hh[16], hl[16];
#pragma unroll
                for (int q = 0; q < 8; ++q) {
                    int qq = half * 8 + q;
                    float4 pi = pI[qq], pj = pJ[qq], bb = Bv[qq];
                    float v0 = silu_f(__uint_as_float(dr[4 * q + 0]) + bb.x + pi.x + pj.x);
                    float v1 = silu_f(__uint_as_float(dr[4 * q + 1]) + bb.y + pi.y + pj.y);
                    float v2 = silu_f(__uint_as_float(dr[4 * q + 2]) + bb.z + pi.z + pj.z);
                    float v3 = silu_f(__uint_as_float(dr[4 * q + 3]) + bb.w + pi.w + pj.w);
                    uint32_t p0 = pkbf(v0, v1), p1 = pkbf(v2, v3);
                    __nv_bfloat162 h0 = *(__nv_bfloat162*)&p0;
                    __nv_bfloat162 h1 = *(__nv_bfloat162*)&p1;
                    hh[2 * q] = p0; hh[2 * q + 1] = p1;
                    hl[2 * q]     = pkbf(v0 - __bfloat162float(h0.x), v1 - __bfloat162float(h0.y));
                    hl[2 * q + 1] = pkbf(v2 - __bfloat162float(h1.x), v3 - __bfloat162float(h1.y));
                }
                TMST_X16(tm + TM_AHI + half * 16 + wo, hh);
                TMST_X16(tm + TM_ALO + half * 16 + wo, hl);
            }
        }
        TC_WAIT_ST();
        TC_FENCE_BEFORE();
        __syncthreads();

        // ---- layer 2 MMAs ----
        if (wid == 0 && elect_one()) {
            TC_FENCE_AFTER();
#pragma unroll
            for (int s = 0; s < 4; ++s)
                mma_f16_ts(tm + TM_D, tm + TM_AHI + s * 8, d_b2h + s * 2, s > 0);
#pragma unroll
            for (int s = 0; s < 4; ++s)
                mma_f16_ts(tm + TM_D, tm + TM_ALO + s * 8, d_b2h + s * 2, 1);
#pragma unroll
            for (int s = 0; s < 4; ++s)
                mma_f16_ts(tm + TM_D, tm + TM_AHI + s * 8, d_b2l + s * 2, 1);
            TC_COMMIT(smb + SM_MBAR);
        }
        MB_WAIT(smb + SM_MBAR, ph); ph ^= 1;
        TC_FENCE_AFTER();

        // ---- epilogue 2: h = silu(d + b2), two halves ----
        {
            const float4* Bv = (const float4*)(smraw + SM_B2V);
#pragma unroll
            for (int half = 0; half < 2; ++half) {
                uint32_t dr[32];
                TMLD_X32(dr, tm + TM_D + half * 32 + wo);
                TC_WAIT_LD();
                uint32_t hh[16], hl[16];
#pragma unroll
                for (int q = 0; q < 8; ++q) {
                    int qq = half * 8 + q;
                    float4 bb = Bv[qq];
                    float v0 = silu_f(__uint_as_float(dr[4 * q + 0]) + bb.x);
                    float v1 = silu_f(__uint_as_float(dr[4 * q + 1]) + bb.y);
                    float v2 = silu_f(__uint_as_float(dr[4 * q + 2]) + bb.z);
                    float v3 = silu_f(__uint_as_float(dr[4 * q + 3]) + bb.w);
                    uint32_t p0 = pkbf(v0, v1), p1 = pkbf(v2, v3);
                    __nv_bfloat162 h0 = *(__nv_bfloat162*)&p0;
                    __nv_bfloat162 h1 = *(__nv_bfloat162*)&p1;
                    hh[2 * q] = p0; hh[2 * q + 1] = p1;
                    hl[2 * q]     = pkbf(v0 - __bfloat162float(h0.x), v1 - __bfloat162float(h0.y));
                    hl[2 * q + 1] = pkbf(v2 - __bfloat162float(h1.x), v3 - __bfloat162float(h1.y));
                }
                TMST_X16(tm + TM_AHI + half * 16 + wo, hh);
                TMST_X16(tm + TM_ALO + half * 16 + wo, hl);
            }
        }
        TC_WAIT_ST();
        TC_FENCE_BEFORE();
        __syncthreads();

        // ---- layer 3 MMAs ----
        if (wid == 0 && elect_one()) {
            TC_FENCE_AFTER();
#pragma unroll
            for (int s = 0; s < 4; ++s)
                mma_f16_ts(tm + TM_D, tm + TM_AHI + s * 8, d_b3h + s * 2, s > 0);
#pragma unroll
            for (int s = 0; s < 4; ++s)
                mma_f16_ts(tm + TM_D, tm + TM_ALO + s * 8, d_b3h + s * 2, 1);
#pragma unroll
            for (int s = 0; s < 4; ++s)
                mma_f16_ts(tm + TM_D, tm + TM_AHI + s * 8, d_b3l + s * 2, 1);
            TC_COMMIT(smb + SM_MBAR);
        }
        MB_WAIT(smb + SM_MBAR, ph); ph ^= 1;
        TC_FENCE_AFTER();

        // ---- final: y = x + d + b3; LayerNorm; store ----
        {
            const float4* Bv = (const float4*)(smraw + SM_B3V);
            float y[64];
            float s1 = 0.f, s2 = 0.f;
#pragma unroll
            for (int half = 0; half < 2; ++half) {
                uint32_t dr[32];
                TMLD_X32(dr, tm + TM_D + half * 32 + wo);
                TC_WAIT_LD();
#pragma unroll
                for (int q = 0; q < 8; ++q) {
                    int qq = half * 8 + q;
                    float4 bb = Bv[qq];
                    float v0 = xr[4 * qq + 0] + __uint_as_float(dr[4 * q + 0]) + bb.x;
                    float v1 = xr[4 * qq + 1] + __uint_as_float(dr[4 * q + 1]) + bb.y;
                    float v2 = xr[4 * qq + 2] + __uint_as_float(dr[4 * q + 2]) + bb.z;
                    float v3 = xr[4 * qq + 3] + __uint_as_float(dr[4 * q + 3]) + bb.w;
                    y[4 * qq + 0] = v0; y[4 * qq + 1] = v1;
                    y[4 * qq + 2] = v2; y[4 * qq + 3] = v3;
                    s1 += v0 + v1 + v2 + v3;
                    s2 += v0 * v0 + v1 * v1 + v2 * v2 + v3 * v3;
                }
            }
            float mu  = s1 * (1.f / 64.f);
            float var = s2 * (1.f / 64.f) - mu * mu;
            float inv = rsqrtf(var + 1e-5f);
            if (e < E) {
                const float4* Gv = (const float4*)(smraw + SM_GV);
                const float4* Tv = (const float4*)(smraw + SM_BTV);
                float4* o = (float4*)(out + e * 64);
#pragma unroll
                for (int q = 0; q < 16; ++q) {
                    float4 g4 = Gv[q], t4 = Tv[q], r4;
                    r4.x = (y[4 * q + 0] - mu) * inv * g4.x + t4.x;
                    r4.y = (y[4 * q + 1] - mu) * inv * g4.y + t4.y;
                    r4.z = (y[4 * q + 2] - mu) * inv * g4.z + t4.z;
                    r4.w = (y[4 * q + 3] - mu) * inv * g4.w + t4.w;
                    o[q] = r4;
                }
            }
        }
    }
    __syncthreads();
    if (wid == 0) TC_DEALLOC(tm, 256);

#else  // ================= fp32 f32x2 fallback (non-arch-specific pass) =====

    float* wsm = smf + SM_W / 4;
    for (int i = tid; i < 64 * 64; i += 128) wsm[FB_W1E + i] = W1[i];
    for (int i = tid; i < 16 * 64; i += 128) wsm[FB_W1R + i] = W1[192 * 64 + i];
    for (int i = tid; i < 64 * 64; i += 128) wsm[FB_W2 + i] = W2[i];
    for (int i = tid; i < 64 * 64; i += 128) wsm[FB_W3 + i] = W3[i];
    __syncthreads();

    for (int t = blockIdx.x; t < ntiles; t += gridDim.x) {
        long long base = (long long)t * TILE;
        __syncthreads();
        for (int i = tid; i < TILE * 64; i += 128) {
            int r = i >> 6, c = i & 63;
            long long e = base + r; if (e >= E) e = E - 1;
            smf[SM_XS / 4 + r * 81 + c] = ef[e * 64 + c];
        }
        for (int i = tid; i < TILE * 16; i += 128) {
            int r = i >> 4, c = i & 15;
            long long e = base + r; if (e >= E) e = E - 1;
            smf[SM_XS / 4 + r * 81 + 64 + c] = rbf[e * 16 + c];
        }
        __syncthreads();

        long long e = base + tid;
        long long eld = (e < E) ? e : (long long)(E - 1);
        long long nrow, ncol;
        if (is64) {
            const long long* p = (const long long*)eidx_raw;
            nrow = p[eld]; ncol = p[(long long)E + eld];
        } else {
            const int* p = (const int*)eidx_raw;
            nrow = p[eld]; ncol = p[(long long)E + eld];
        }
        if (nrow < 0) nrow = 0; if (nrow >= N_NODES_MAX) nrow = N_NODES_MAX - 1;
        if (ncol < 0) ncol = 0; if (ncol >= N_NODES_MAX) ncol = N_NODES_MAX - 1;

        const float4* pI = (const float4*)(g_proj + nrow * 128);
        const float4* pJ = (const float4*)(g_proj + ncol * 128 + 64);
        const float* xr = smf + SM_XS / 4 + tid * 81;

        ull acc[32];
#pragma unroll
        for (int m = 0; m < 16; ++m) {
            float4 bb = ((const float4*)(smraw + SM_B1V))[m];
            float4 a = pI[m];
            float4 b = pJ[m];
            acc[2 * m]     = pk2(bb.x + a.x + b.x, bb.y + a.y + b.y);
            acc[2 * m + 1] = pk2(bb.z + a.z + b.z, bb.w + a.w + b.w);
        }
#pragma unroll
        for (int k = 0; k < 64; ++k) gemm_step(acc, xr[k], wsm + FB_W1E + k * 64);
#pragma unroll
        for (int k = 0; k < 16; ++k) gemm_step(acc, xr[64 + k], wsm + FB_W1R + k * 64);

        float h[64];
#pragma unroll
        for (int p = 0; p < 32; ++p) {
            float a, b; upk2(acc[p], a, b);
            h[2 * p] = silu_f(a); h[2 * p + 1] = silu_f(b);
        }
#pragma unroll
        for (int m = 0; m < 16; ++m) {
            float4 bb = ((const float4*)(smraw + SM_B2V))[m];
            acc[2 * m] = pk2(bb.x, bb.y); acc[2 * m + 1] = pk2(bb.z, bb.w);
        }
#pragma unroll
        for (int k = 0; k < 64; ++k) gemm_step(acc, h[k], wsm + FB_W2 + k * 64);
#pragma unroll
        for (int p = 0; p < 32; ++p) {
            float a, b; upk2(acc[p], a, b);
            h[2 * p] = silu_f(a); h[2 * p + 1] = silu_f(b);
        }
#pragma unroll
        for (int m = 0; m < 16; ++m) {
            float4 bb = ((const float4*)(smraw + SM_B3V))[m];
            acc[2 * m] = pk2(bb.x, bb.y); acc[2 * m + 1] = pk2(bb.z, bb.w);
        }
#pragma unroll
        for (int k = 0; k < 64; ++k) gemm_step(acc, h[k], wsm + FB_W3 + k * 64);

        float y[64];
        float s1 = 0.f, s2 = 0.f;
#pragma unroll
        for (int p = 0; p < 32; ++p) {
            float a, b; upk2(acc[p], a, b);
            float ya = xr[2 * p] + a, yb = xr[2 * p + 1] + b;
            y[2 * p] = ya; y[2 * p + 1] = yb;
            s1 += ya + yb; s2 += ya * ya + yb * yb;
        }
        float mu  = s1 * (1.f / 64.f);
        float var = s2 * (1.f / 64.f) - mu * mu;
        float inv = rsqrtf(var + 1e-5f);
        if (e < E) {
            float4* o = (float4*)(out + e * 64);
#pragma unroll
            for (int q = 0; q < 16; ++q) {
                float4 g4 = ((const float4*)(smraw + SM_GV))[q];
                float4 t4 = ((const float4*)(smraw + SM_BTV))[q];
                float4 r4;
                r4.x = (y[4 * q + 0] - mu) * inv * g4.x + t4.x;
                r4.y = (y[4 * q + 1] - mu) * inv * g4.y + t4.y;
                r4.z = (y[4 * q + 2] - mu) * inv * g4.z + t4.z;
                r4.w = (y[4 * q + 3] - mu) * inv * g4.w + t4.w;
                o[q] = r4;
            }
        }
    }
#endif
}

// ---------------------------------------------------------------------------
// Launch
// ---------------------------------------------------------------------------
extern "C" void kernel_launch(void* const* d_in, const int* in_sizes, int n_in,
                              void* d_out, int out_size) {
    const float* ef   = (const float*)d_in[0];
    const float* nf   = (const float*)d_in[1];
    const void*  eidx = (const void*)d_in[2];
    const float* rbf  = (const float*)d_in[3];
    const float* W1   = (const float*)d_in[4];
    const float* b1   = (const float*)d_in[5];
    const float* W2   = (const float*)d_in[6];
    const float* b2   = (const float*)d_in[7];
    const float* W3   = (const float*)d_in[8];
    const float* b3   = (const float*)d_in[9];
    const float* gam  = (const float*)d_in[10];
    const float* bet  = (const float*)d_in[11];
    float* out = (float*)d_out;

    int E = in_sizes[0] / 64;
    int N = in_sizes[1] / 64;
    if (N > N_NODES_MAX) N = N_NODES_MAX;

    detect_idx_kernel<<<1, 1>>>((const unsigned int*)eidx);
    prep_w_kernel<<<32, 256>>>(W1, W2, W3);
    node_proj_kernel<<<(N + 15) / 16, 256>>>(nf, W1, N);

    int ntiles = (E + TILE - 1) / TILE;
    int grid = 2 * 148;
    if (grid > ntiles) grid = ntiles;
    cudaFuncSetAttribute(edge_tc_kernel,
                         cudaFuncAttributeMaxDynamicSharedMemorySize, SMEM_BYTES);
    edge_tc_kernel<<<grid, 128, SMEM_BYTES>>>(
        ef, eidx, rbf, W1, W2, W3, b1, b2, b3, gam, bet, out, E, ntiles);
}

// round 10
// speedup vs baseline: 3.0380x; 1.5713x over previous
#include <cuda_runtime.h>
#include <cuda_bf16.h>
#include <stdint.h>

// ============================================================================
// AllegroLayer edge-MLP (sm_103a).
//
// tcgen05 split-bf16 path (arch-specific pass) + fp32 f32x2 fallback
// (plain compute_103 pass).
//
// R8: latency-oriented restructure.
//  - 1 CTA/SM, 256 threads = 2 warpgroup pipelines sharing one weight image.
//  - Double-buffered ef tile per pipeline; next tile staged between
//    MMA-commit and mbarrier-wait (hides DRAM latency).
//  - edge_index carried one tile ahead; g_proj prefetched to L2; rbf
//    prefetched to L1 and loaded to registers (not SMEM).
//  - silu via tanh.approx (1 MUFU instead of 2).
//  - TMEM: one 512-col alloc, 256-col slot per warpgroup.
// ============================================================================

#if defined(__CUDA_ARCH_FEAT_SM103_ALL) || \
    (defined(__CUDA_ARCH_SPECIFIC__) && defined(__CUDA_ARCH__) && (__CUDA_ARCH__ == 1030))
#define HAS_TC 1
#else
#define HAS_TC 0
#endif

#define N_NODES_MAX 50048
#define TILE 128
#define IDESC 0x8100490u   // kind::f16: F32 acc, BF16 a/b, N=64, M=128

__device__ float g_proj[(size_t)N_NODES_MAX * 128];
__device__ int g_is64;
__device__ __align__(16) unsigned char g_wimg[65536];

// weight-image offsets (pre-swizzled bf16 hi/lo tiles, bytes)
#define WI_B1H 0
#define WI_B1L 16384
#define WI_B2H 32768
#define WI_B2L 40960
#define WI_B3H 49152
#define WI_B3L 57344

// SMEM layout (bytes)
#define SM_W     0
#define XBUF_B   34816                      // 128 rows * 68 floats
#define SM_XS    65536
#define XS_OFF(wg, buf) (SM_XS + ((wg) * 2 + (buf)) * XBUF_B)
#define SM_VEC   (SM_XS + 4 * XBUF_B)       // 204800
#define SM_B1V   SM_VEC
#define SM_B2V   (SM_VEC + 256)
#define SM_B3V   (SM_VEC + 512)
#define SM_GV    (SM_VEC + 768)
#define SM_BTV   (SM_VEC + 1024)
#define SM_PTR   (SM_VEC + 1280)
#define SM_MBAR  (SM_VEC + 1288)            // 2 x 8B
#define SMEM_BYTES (SM_VEC + 1312)          // 206112

// fallback fp32 weight offsets (floats, within SM_W)
#define FB_W1E  0
#define FB_W1R  (64 * 64)
#define FB_W2   (FB_W1R + 16 * 64)
#define FB_W3   (FB_W2 + 64 * 64)

// TMEM per-wg slot layout (slot base = wg*256)
#define TM_AHI 0
#define TM_ALO 64
#define TM_D   128

typedef unsigned long long ull;

// ---------------------------------------------------------------------------
__device__ __forceinline__ uint32_t smem_u32(const void* p) {
    uint32_t a;
    asm("{ .reg .u64 t; cvta.to.shared.u64 t, %1; cvt.u32.u64 %0, t; }"
        : "=r"(a) : "l"(p));
    return a;
}
__device__ __forceinline__ uint32_t pkbf(float a, float b) {
    __nv_bfloat162 t = __floats2bfloat162_rn(a, b);
    return *(uint32_t*)&t;
}
// silu via tanh.approx: 1 MUFU + 1 FMUL + 1 FFMA
__device__ __forceinline__ float silu_f(float x) {
    float h = 0.5f * x, t;
    asm("tanh.approx.f32 %0, %1;" : "=f"(t) : "f"(h));
    return h + h * t;
}
__device__ __forceinline__ ull pk2(float lo, float hi) {
    ull r;
    asm("mov.b64 %0, {%1, %2};" : "=l"(r) : "f"(lo), "f"(hi));
    return r;
}
__device__ __forceinline__ void upk2(ull v, float& lo, float& hi) {
    asm("mov.b64 {%0, %1}, %2;" : "=f"(lo), "=f"(hi) : "l"(v));
}
__device__ __forceinline__ void fma2(ull& d, ull a, ull b) {
    asm("fma.rn.f32x2 %0, %1, %2, %0;" : "+l"(d) : "l"(a), "l"(b));
}
#define PF_L2(p) asm volatile("prefetch.global.L2 [%0];" :: "l"(p))
#define PF_L1(p) asm volatile("prefetch.global.L1 [%0];" :: "l"(p))
#define WG_BAR(wg) asm volatile("bar.sync %0, 128;" :: "r"((wg) + 1) : "memory")

#if HAS_TC
__device__ __forceinline__ uint32_t elect_one() {
    uint32_t p;
    asm volatile("{\n\t.reg .pred p;\n\telect.sync _|p, 0xFFFFFFFF;\n\t"
                 "selp.b32 %0, 1, 0, p;\n\t}" : "=r"(p));
    return p;
}
__device__ __forceinline__ uint64_t mkdesc(uint32_t addr) {
    return ((uint64_t)2 << 61) | ((uint64_t)1 << 46) | ((uint64_t)64 << 32) |
           ((uint64_t)1 << 16) | ((addr >> 4) & 0x3FFF);
}
#define TC_ALLOC(sa, n) \
    asm volatile("tcgen05.alloc.cta_group::1.sync.aligned.shared::cta.b32 [%0], %1;" \
                 :: "r"(sa), "r"((uint32_t)(n)) : "memory")
#define TC_RELINQ() \
    asm volatile("tcgen05.relinquish_alloc_permit.cta_group::1.sync.aligned;")
#define TC_DEALLOC(t, n) \
    asm volatile("tcgen05.dealloc.cta_group::1.sync.aligned.b32 %0, %1;" :: "r"(t), "r"((uint32_t)(n)))
#define TC_COMMIT(mb) \
    asm volatile("tcgen05.commit.cta_group::1.mbarrier::arrive::one.shared::cluster.b64 [%0];" \
                 :: "r"(mb) : "memory")
#define TC_WAIT_ST() asm volatile("tcgen05.wait::st.sync.aligned;" ::: "memory")
#define TC_WAIT_LD() asm volatile("tcgen05.wait::ld.sync.aligned;" ::: "memory")
#define TC_FENCE_BEFORE() asm volatile("tcgen05.fence::before_thread_sync;" ::: "memory")
#define TC_FENCE_AFTER()  asm volatile("tcgen05.fence::after_thread_sync;" ::: "memory")
#define MB_INIT(mb, c) \
    asm volatile("mbarrier.init.shared.b64 [%0], %1;" :: "r"(mb), "r"((uint32_t)(c)) : "memory")
#define MB_WAIT(mb, par) do { \
    uint32_t _m = (mb), _p = (par), _d; \
    asm volatile("{\n\t.reg .pred p;\n\t" \
        "mbarrier.try_wait.parity.acquire.cta.shared::cta.b64 p, [%1], %2;\n\t" \
        "selp.b32 %0, 1, 0, p;\n\t}" : "=r"(_d) : "r"(_m), "r"(_p) : "memory"); \
    if (!_d) { \
        asm volatile("{\n\t.reg .pred P1;\n\tWL_%=:\n\t" \
            "mbarrier.try_wait.parity.acquire.cta.shared::cta.b64 P1, [%0], %1, 0x989680;\n\t" \
            "@P1 bra.uni WD_%=;\n\tbra.uni WL_%=;\n\tWD_%=:\n\t}" \
            :: "r"(_m), "r"(_p) : "memory"); \
    } } while (0)

#define TMST_X16(addr, r) \
    asm volatile("tcgen05.st.sync.aligned.32x32b.x16.b32 [%0], " \
        "{%1,%2,%3,%4,%5,%6,%7,%8,%9,%10,%11,%12,%13,%14,%15,%16};" \
        :: "r"(addr), \
        "r"((r)[0]),"r"((r)[1]),"r"((r)[2]),"r"((r)[3]),"r"((r)[4]),"r"((r)[5]),"r"((r)[6]),"r"((r)[7]), \
        "r"((r)[8]),"r"((r)[9]),"r"((r)[10]),"r"((r)[11]),"r"((r)[12]),"r"((r)[13]),"r"((r)[14]),"r"((r)[15]) \
        : "memory")
#define TMST_X8(addr, r) \
    asm volatile("tcgen05.st.sync.aligned.32x32b.x8.b32 [%0], " \
        "{%1,%2,%3,%4,%5,%6,%7,%8};" \
        :: "r"(addr), \
        "r"((r)[0]),"r"((r)[1]),"r"((r)[2]),"r"((r)[3]),"r"((r)[4]),"r"((r)[5]),"r"((r)[6]),"r"((r)[7]) \
        : "memory")
#define TMLD_X32(r, addr) \
    asm volatile("tcgen05.ld.sync.aligned.32x32b.x32.b32 " \
        "{%0,%1,%2,%3,%4,%5,%6,%7,%8,%9,%10,%11,%12,%13,%14,%15," \
        "%16,%17,%18,%19,%20,%21,%22,%23,%24,%25,%26,%27,%28,%29,%30,%31}, [%32];" \
        : "=r"((r)[0]),"=r"((r)[1]),"=r"((r)[2]),"=r"((r)[3]),"=r"((r)[4]),"=r"((r)[5]),"=r"((r)[6]),"=r"((r)[7]), \
          "=r"((r)[8]),"=r"((r)[9]),"=r"((r)[10]),"=r"((r)[11]),"=r"((r)[12]),"=r"((r)[13]),"=r"((r)[14]),"=r"((r)[15]), \
          "=r"((r)[16]),"=r"((r)[17]),"=r"((r)[18]),"=r"((r)[19]),"=r"((r)[20]),"=r"((r)[21]),"=r"((r)[22]),"=r"((r)[23]), \
          "=r"((r)[24]),"=r"((r)[25]),"=r"((r)[26]),"=r"((r)[27]),"=r"((r)[28]),"=r"((r)[29]),"=r"((r)[30]),"=r"((r)[31]) \
        : "r"(addr))

__device__ __forceinline__ void mma_f16_ts(uint32_t d, uint32_t a, uint64_t bd,
                                           uint32_t en) {
    asm volatile("{\n\t.reg .pred p;\n\tsetp.ne.u32 p, %5, 0;\n\t"
                 "tcgen05.mma.cta_group::1.kind::f16 [%0], [%1], %2, %3, "
                 "{%4, %4, %4, %4}, p;\n\t}"
                 :: "r"(d), "r"(a), "l"(bd), "r"(IDESC), "r"(0u), "r"(en)
                 : "memory");
}
#endif  // HAS_TC

// ---------------------------------------------------------------------------
// Kernel 0: detect edge_index dtype (int64 vs int32)
// ---------------------------------------------------------------------------
__global__ void detect_idx_kernel(const unsigned int* __restrict__ w) {
    unsigned int acc = 0;
#pragma unroll
    for (int i = 1; i < 256; i += 2) acc |= w[i];
    g_is64 = (acc == 0) ? 1 : 0;
}

// ---------------------------------------------------------------------------
// Kernel P: build hi/lo bf16 weight tiles in pre-swizzled SW128 image layout.
// ---------------------------------------------------------------------------
__global__ void prep_w_kernel(const float* __restrict__ W1,
                              const float* __restrict__ W2,
                              const float* __restrict__ W3) {
    int stride = blockDim.x * gridDim.x;
    int t0 = blockIdx.x * blockDim.x + threadIdx.x;
    for (int i = t0; i < 64 * 128; i += stride) {
        int n = i >> 7, k = i & 127;
        float w = 0.f;
        if (k < 64) w = W1[k * 64 + n];
        else if (k < 80) w = W1[(192 + k - 64) * 64 + n];
        uint32_t bo = ((uint32_t)(n >> 3) + ((uint32_t)(k * 2) >> 7) * 8u) * 1024u
                    + (uint32_t)(n & 7) * 128u + ((uint32_t)(k * 2) & 127u);
        uint32_t sw = bo ^ ((bo >> 3) & 0x70);
        __nv_bfloat16 hi = __float2bfloat16(w);
        __nv_bfloat16 lo = __float2bfloat16(w - __bfloat162float(hi));
        *(__nv_bfloat16*)(g_wimg + WI_B1H + sw) = hi;
        *(__nv_bfloat16*)(g_wimg + WI_B1L + sw) = lo;
    }
    for (int i = t0; i < 64 * 64; i += stride) {
        int n = i >> 6, k = i & 63;
        uint32_t bo = (uint32_t)(n >> 3) * 1024u + (uint32_t)(n & 7) * 128u
                    + (uint32_t)(k * 2);
        uint32_t sw = bo ^ ((bo >> 3) & 0x70);
        float w2 = W2[k * 64 + n];
        __nv_bfloat16 h2 = __float2bfloat16(w2);
        *(__nv_bfloat16*)(g_wimg + WI_B2H + sw) = h2;
        *(__nv_bfloat16*)(g_wimg + WI_B2L + sw) =
            __float2bfloat16(w2 - __bfloat162float(h2));
        float w3 = W3[k * 64 + n];
        __nv_bfloat16 h3 = __float2bfloat16(w3);
        *(__nv_bfloat16*)(g_wimg + WI_B3H + sw) = h3;
        *(__nv_bfloat16*)(g_wimg + WI_B3L + sw) =
            __float2bfloat16(w3 - __bfloat162float(h3));
    }
}

// ---------------------------------------------------------------------------
// Kernel A: per-node projections (fp32, exact)
// ---------------------------------------------------------------------------
__global__ void __launch_bounds__(256) node_proj_kernel(
    const float* __restrict__ nf, const float* __restrict__ W1, int N)
{
    __shared__ float Wn[64 * 128];
    __shared__ float nfs[16 * 65];
    int tid = threadIdx.x;
    for (int i = tid; i < 64 * 128; i += 256) {
        int d = i >> 7, jj = i & 127;
        Wn[i] = (jj < 64) ? W1[(64 + d) * 64 + jj]
                          : W1[(128 + d) * 64 + (jj - 64)];
    }
    int n0 = blockIdx.x * 16;
    for (int i = tid; i < 16 * 64; i += 256) {
        int nl = i >> 6, d = i & 63;
        int n = n0 + nl;
        nfs[nl * 65 + d] = (n < N) ? nf[(size_t)n * 64 + d] : 0.f;
    }
    __syncthreads();
    int nl = tid & 15;
    int j0 = (tid >> 4) * 8;
    float acc[8] = {0.f, 0.f, 0.f, 0.f, 0.f, 0.f, 0.f, 0.f};
#pragma unroll 4
    for (int d = 0; d < 64; ++d) {
        float v = nfs[nl * 65 + d];
        const float4* w = (const float4*)(Wn + d * 128 + j0);
        float4 w0 = w[0], w1 = w[1];
        acc[0] += v * w0.x; acc[1] += v * w0.y; acc[2] += v * w0.z; acc[3] += v * w0.w;
        acc[4] += v * w1.x; acc[5] += v * w1.y; acc[6] += v * w1.z; acc[7] += v * w1.w;
    }
    int n = n0 + nl;
    if (n < N) {
        float4* o = (float4*)(g_proj + (size_t)n * 128 + j0);
        o[0] = make_float4(acc[0], acc[1], acc[2], acc[3]);
        o[1] = make_float4(acc[4], acc[5], acc[6], acc[7]);
    }
}

// fallback per-thread GEMM K-step
__device__ __forceinline__ void gemm_step(ull* acc, float xk, const float* wrow) {
    ull xk2 = pk2(xk, xk);
    const ulonglong2* w = (const ulonglong2*)wrow;
#pragma unroll
    for (int m = 0; m < 16; ++m) {
        ulonglong2 ww = w[m];
        fma2(acc[2 * m],     xk2, ww.x);
        fma2(acc[2 * m + 1], xk2, ww.y);
    }
}

// index load helper
__device__ __forceinline__ void load_idx(const void* eidx_raw, int is64,
                                         long long E, long long eld,
                                         long long& nrow, long long& ncol) {
    if (is64) {
        const long long* p = (const long long*)eidx_raw;
        nrow = p[eld]; ncol = p[E + eld];
    } else {
        const int* p = (const int*)eidx_raw;
        nrow = p[eld]; ncol = p[E + eld];
    }
    if (nrow < 0) nrow = 0; if (nrow >= N_NODES_MAX) nrow = N_NODES_MAX - 1;
    if (ncol < 0) ncol = 0; if (ncol >= N_NODES_MAX) ncol = N_NODES_MAX - 1;
}

// ---------------------------------------------------------------------------
// Kernel B: persistent edge MLP. 256 threads = 2 warpgroup pipelines.
// ---------------------------------------------------------------------------
__global__ void __launch_bounds__(256) edge_tc_kernel(
    const float* __restrict__ ef, const void* __restrict__ eidx_raw,
    const float* __restrict__ rbf,
    const float* __restrict__ W1, const float* __restrict__ W2,
    const float* __restrict__ W3,
    const float* __restrict__ b1, const float* __restrict__ b2,
    const float* __restrict__ b3, const float* __restrict__ gamma,
    const float* __restrict__ beta, float* __restrict__ out,
    int E, int ntiles)
{
    extern __shared__ __align__(1024) unsigned char smraw[];
    float* smf = (float*)smraw;
    int tid = threadIdx.x;
    int wg = tid >> 7;                 // 0 or 1
    int wg_tid = tid & 127;
    int warp_in_wg = (tid >> 5) & 3;
    int is64 = g_is64;
    long long pipes = (long long)gridDim.x * 2;

    if (tid < 64) {
        smf[SM_B1V / 4 + tid] = b1[tid];
        smf[SM_B2V / 4 + tid] = b2[tid];
        smf[SM_B3V / 4 + tid] = b3[tid];
        smf[SM_GV / 4 + tid]  = gamma[tid];
        smf[SM_BTV / 4 + tid] = beta[tid];
    }

#if HAS_TC
    uint32_t smb = smem_u32(smraw);
    // stage pre-swizzled bf16 weight image (64KB) once, whole CTA
    {
        const float4* src = (const float4*)g_wimg;
        float4* dst = (float4*)(smraw + SM_W);
        for (int i = tid; i < 65536 / 16; i += 256) dst[i] = src[i];
    }
    if (tid == 0) { MB_INIT(smb + SM_MBAR, 1); MB_INIT(smb + SM_MBAR + 8, 1); }
    if ((tid >> 5) == 0) {
        TC_ALLOC(smb + SM_PTR, 512);
        TC_RELINQ();   // persistent CTA must not hold the alloc permit
    }
    __syncthreads();
    uint32_t tm;
    asm("ld.shared.b32 %0, [%1];" : "=r"(tm) : "r"(smb + SM_PTR));
    uint32_t ts = tm + (uint32_t)wg * 256;          // per-wg TMEM slot
    uint32_t wo = (uint32_t)warp_in_wg << 21;
    uint32_t mb = smb + SM_MBAR + (uint32_t)wg * 8;

    uint64_t d_b1h = mkdesc(smb + SM_W + WI_B1H);
    uint64_t d_b1l = mkdesc(smb + SM_W + WI_B1L);
    uint64_t d_b2h = mkdesc(smb + SM_W + WI_B2H);
    uint64_t d_b2l = mkdesc(smb + SM_W + WI_B2L);
    uint64_t d_b3h = mkdesc(smb + SM_W + WI_B3H);
    uint64_t d_b3l = mkdesc(smb + SM_W + WI_B3L);
    uint32_t ph = 0;

    long long t = (long long)blockIdx.x * 2 + wg;
    long long nrow = 0, ncol = 0;

    // ---- prologue: stage buf0 for first tile; load idx; prefetch ----
    if (t < ntiles) {
        long long base = t * TILE;
        int xo = XS_OFF(wg, 0) / 4;
        for (int i = wg_tid; i < TILE * 16; i += 128) {
            int r = i >> 4, c4 = i & 15;
            long long e = base + r; if (e >= E) e = E - 1;
            *(float4*)&smf[xo + r * 68 + c4 * 4] = ((const float4*)ef)[e * 16 + c4];
        }
        long long e0 = base + wg_tid; if (e0 >= E) e0 = E - 1;
        load_idx(eidx_raw, is64, E, e0, nrow, ncol);
        const float* pi = g_proj + nrow * 128;
        const float* pj = g_proj + ncol * 128 + 64;
        PF_L2(pi); PF_L2(pi + 32); PF_L2(pj); PF_L2(pj + 32);
        PF_L1(rbf + e0 * 16);
    }

    int it = 0;
    for (; t < ntiles; t += pipes, ++it) {
        long long base = t * TILE;
        int buf = it & 1;
        const float* xr = smf + XS_OFF(wg, buf) / 4 + wg_tid * 68;
        long long e = base + wg_tid;
        long long eld = (e < E) ? e : (long long)(E - 1);

        WG_BAR(wg);   // staged buffer visible; prev-iter reads done

        // ---- rbf to regs (L1-prefetched) ----
        float rb[16];
        {
            const float4* rp = (const float4*)(rbf + eld * 16);
            float4 r0 = rp[0], r1 = rp[1], r2 = rp[2], r3 = rp[3];
            rb[0]=r0.x; rb[1]=r0.y; rb[2]=r0.z; rb[3]=r0.w;
            rb[4]=r1.x; rb[5]=r1.y; rb[6]=r1.z; rb[7]=r1.w;
            rb[8]=r2.x; rb[9]=r2.y; rb[10]=r2.z; rb[11]=r2.w;
            rb[12]=r3.x; rb[13]=r3.y; rb[14]=r3.z; rb[15]=r3.w;
        }

        // ---- convert x (64 ef + 16 rbf) to hi/lo bf16x2, store A to TMEM ----
        {
#pragma unroll
            for (int half = 0; half < 2; ++half) {
                uint32_t ah[16], al[16];
#pragma unroll
                for (int c = 0; c < 16; ++c) {
                    int cc = half * 16 + c;
                    float a = xr[2 * cc], b = xr[2 * cc + 1];
                    uint32_t p = pkbf(a, b);
                    __nv_bfloat162 hp = *(__nv_bfloat162*)&p;
                    ah[c] = p;
                    al[c] = pkbf(a - __bfloat162float(hp.x),
                                 b - __bfloat162float(hp.y));
                }
                TMST_X16(ts + TM_AHI + half * 16 + wo, ah);
                TMST_X16(ts + TM_ALO + half * 16 + wo, al);
            }
            uint32_t ah[8], al[8];
#pragma unroll
            for (int c = 0; c < 8; ++c) {
                float a = rb[2 * c], b = rb[2 * c + 1];
                uint32_t p = pkbf(a, b);
                __nv_bfloat162 hp = *(__nv_bfloat162*)&p;
                ah[c] = p;
                al[c] = pkbf(a - __bfloat162float(hp.x),
                             b - __bfloat162float(hp.y));
            }
            TMST_X8(ts + TM_AHI + 32 + wo, ah);
            TMST_X8(ts + TM_ALO + 32 + wo, al);
        }
        TC_WAIT_ST();
        TC_FENCE_BEFORE();
        WG_BAR(wg);

        // ---- layer 1 MMAs: 3 terms x 5 K-steps (K=80) ----
        if (warp_in_wg == 0 && elect_one()) {
            TC_FENCE_AFTER();
            const int doff1[5] = {0, 2, 4, 6, 512};
#pragma unroll
            for (int s = 0; s < 5; ++s)
                mma_f16_ts(ts + TM_D, ts + TM_AHI + s * 8, d_b1h + doff1[s], s > 0);
#pragma unroll
            for (int s = 0; s < 5; ++s)
                mma_f16_ts(ts + TM_D, ts + TM_ALO + s * 8, d_b1h + doff1[s], 1);
#pragma unroll
            for (int s = 0; s < 5; ++s)
                mma_f16_ts(ts + TM_D, ts + TM_AHI + s * 8, d_b1l + doff1[s], 1);
            TC_COMMIT(mb);
        }

        // ---- overlap: stage NEXT tile's ef into alt buffer; prefetch next ----
        long long nrow2 = 0, ncol2 = 0;
        long long tn = t + pipes;
        if (tn < ntiles) {
            long long bn = tn * TILE;
            int xo = XS_OFF(wg, buf ^ 1) / 4;
#pragma unroll 4
            for (int i = wg_tid; i < TILE * 16; i += 128) {
                int r = i >> 4, c4 = i & 15;
                long long en = bn + r; if (en >= E) en = E - 1;
                *(float4*)&smf[xo + r * 68 + c4 * 4] = ((const float4*)ef)[en * 16 + c4];
            }
            long long en0 = bn + wg_tid; if (en0 >= E) en0 = E - 1;
            load_idx(eidx_raw, is64, E, en0, nrow2, ncol2);
            const float* pi = g_proj + nrow2 * 128;
            const float* pj = g_proj + ncol2 * 128 + 64;
            PF_L2(pi); PF_L2(pi + 32); PF_L2(pj); PF_L2(pj + 32);
            PF_L1(rbf + en0 * 16);
        }

        MB_WAIT(mb, ph); ph ^= 1;
        TC_FENCE_AFTER();

        // ---- epilogue 1: h = silu(d + b1 + proj_i + proj_j) ----
        {
            const float4* pI = (const float4*)(g_proj + nrow * 128);
            const float4* pJ = (const float4*)(g_proj + ncol * 128 + 64);
            const float4* Bv = (const float4*)(smraw + SM_B1V);
#pragma unroll
            for (int half = 0; half < 2; ++half) {
                uint32_t dr[32];
                TMLD_X32(dr, ts + TM_D + half * 32 + wo);
                TC_WAIT_LD();
                uint32_t hh[16], hl[16];
#pragma unroll
                for (int q = 0; q < 8; ++q) {
                    int qq = half * 8 + q;
                    float4 pi = pI[qq], pj = pJ[qq], bb = Bv[qq];
                    float v0 = silu_f(__uint_as_float(dr[4 * q + 0]) + bb.x + pi.x + pj.x);
                    float v1 = silu_f(__uint_as_float(dr[4 * q + 1]) + bb.y + pi.y + pj.y);
                    float v2 = silu_f(__uint_as_float(dr[4 * q + 2]) + bb.z + pi.z + pj.z);
                    float v3 = silu_f(__uint_as_float(dr[4 * q + 3]) + bb.w + pi.w + pj.w);
                    uint32_t p0 = pkbf(v0, v1), p1 = pkbf(v2, v3);
                    __nv_bfloat162 h0 = *(__nv_bfloat162*)&p0;
                    __nv_bfloat162 h1 = *(__nv_bfloat162*)&p1;
                    hh[2 * q] = p0; hh[2 * q + 1] = p1;
                    hl[2 * q]     = pkbf(v0 - __bfloat162float(h0.x), v1 - __bfloat162float(h0.y));
                    hl[2 * q + 1] = pkbf(v2 - __bfloat162float(h1.x), v3 - __bfloat162float(h1.y));
                }
                TMST_X16(ts + TM_AHI + half * 16 + wo, hh);
                TMST_X16(ts + TM_ALO + half * 16 + wo, hl);
            }
        }
        TC_WAIT_ST();
        TC_FENCE_BEFORE();
        WG_BAR(wg);

        // ---- layer 2 MMAs ----
        if (warp_in_wg == 0 && elect_one()) {
            TC_FENCE_AFTER();
#pragma unroll
            for (int s = 0; s < 4; ++s)
                mma_f16_ts(ts + TM_D, ts + TM_AHI + s * 8, d_b2h + s * 2, s > 0);
#pragma unroll
            for (int s = 0; s < 4; ++s)
                mma_f16_ts(ts + TM_D, ts + TM_ALO + s * 8, d_b2h + s * 2, 1);
#pragma unroll
            for (int s = 0; s < 4; ++s)
                mma_f16_ts(ts + TM_D, ts + TM_AHI + s * 8, d_b2l + s * 2, 1);
            TC_COMMIT(mb);
        }
        MB_WAIT(mb, ph); ph ^= 1;
        TC_FENCE_AFTER();

        // ---- epilogue 2: h = silu(d + b2) ----
        {
            const float4* Bv = (const float4*)(smraw + SM_B2V);
#pragma unroll
            for (int half = 0; half < 2; ++half) {
                uint32_t dr[32];
                TMLD_X32(dr, ts + TM_D + half * 32 + wo);
                TC_WAIT_LD();
                uint32_t hh[16], hl[16];
#pragma unroll
                for (int q = 0; q < 8; ++q) {
                    int qq = half * 8 + q;
                    float4 bb = Bv[qq];
                    float v0 = silu_f(__uint_as_float(dr[4 * q + 0]) + bb.x);
                    float v1 = silu_f(__uint_as_float(dr[4 * q + 1]) + bb.y);
                    float v2 = silu_f(__uint_as_float(dr[4 * q + 2]) + bb.z);
                    float v3 = silu_f(__uint_as_float(dr[4 * q + 3]) + bb.w);
                    uint32_t p0 = pkbf(v0, v1), p1 = pkbf(v2, v3);
                    __nv_bfloat162 h0 = *(__nv_bfloat162*)&p0;
                    __nv_bfloat162 h1 = *(__nv_bfloat162*)&p1;
                    hh[2 * q] = p0; hh[2 * q + 1] = p1;
                    hl[2 * q]     = pkbf(v0 - __bfloat162float(h0.x), v1 - __bfloat162float(h0.y));
                    hl[2 * q + 1] = pkbf(v2 - __bfloat162float(h1.x), v3 - __bfloat162float(h1.y));
                }
                TMST_X16(ts + TM_AHI + half * 16 + wo, hh);
                TMST_X16(ts + TM_ALO + half * 16 + wo, hl);
            }
        }
        TC_WAIT_ST();
        TC_FENCE_BEFORE();
        WG_BAR(wg);

        // ---- layer 3 MMAs ----
        if (warp_in_wg == 0 && elect_one()) {
            TC_FENCE_AFTER();
#pragma unroll
            for (int s = 0; s < 4; ++s)
                mma_f16_ts(ts + TM_D, ts + TM_AHI + s * 8, d_b3h + s * 2, s > 0);
#pragma unroll
            for (int s = 0; s < 4; ++s)
                mma_f16_ts(ts + TM_D, ts + TM_ALO + s * 8, d_b3h + s * 2, 1);
#pragma unroll
            for (int s = 0; s < 4; ++s)
                mma_f16_ts(ts + TM_D, ts + TM_AHI + s * 8, d_b3l + s * 2, 1);
            TC_COMMIT(mb);
        }
        MB_WAIT(mb, ph); ph ^= 1;
        TC_FENCE_AFTER();

        // ---- final: y = x + d + b3; LayerNorm; store ----
        {
            const float4* Bv = (const float4*)(smraw + SM_B3V);
            float y[64];
            float s1 = 0.f, s2 = 0.f;
#pragma unroll
            for (int half = 0; half < 2; ++half) {
                uint32_t dr[32];
                TMLD_X32(dr, ts + TM_D + half * 32 + wo);
                TC_WAIT_LD();
#pragma unroll
                for (int q = 0; q < 8; ++q) {
                    int qq = half * 8 + q;
                    float4 bb = Bv[qq];
                    float v0 = xr[4 * qq + 0] + __uint_as_float(dr[4 * q + 0]) + bb.x;
                    float v1 = xr[4 * qq + 1] + __uint_as_float(dr[4 * q + 1]) + bb.y;
                    float v2 = xr[4 * qq + 2] + __uint_as_float(dr[4 * q + 2]) + bb.z;
                    float v3 = xr[4 * qq + 3] + __uint_as_float(dr[4 * q + 3]) + bb.w;
                    y[4 * qq + 0] = v0; y[4 * qq + 1] = v1;
                    y[4 * qq + 2] = v2; y[4 * qq + 3] = v3;
                    s1 += v0 + v1 + v2 + v3;
                    s2 += v0 * v0 + v1 * v1 + v2 * v2 + v3 * v3;
                }
            }
            float mu  = s1 * (1.f / 64.f);
            float var = s2 * (1.f / 64.f) - mu * mu;
            float inv = rsqrtf(var + 1e-5f);
            if (e < E) {
                const float4* Gv = (const float4*)(smraw + SM_GV);
                const float4* Tv = (const float4*)(smraw + SM_BTV);
                float4* o = (float4*)(out + e * 64);
#pragma unroll
                for (int q = 0; q < 16; ++q) {
                    float4 g4 = Gv[q], t4 = Tv[q], r4;
                    r4.x = (y[4 * q + 0] - mu) * inv * g4.x + t4.x;
                    r4.y = (y[4 * q + 1] - mu) * inv * g4.y + t4.y;
                    r4.z = (y[4 * q + 2] - mu) * inv * g4.z + t4.z;
                    r4.w = (y[4 * q + 3] - mu) * inv * g4.w + t4.w;
                    o[q] = r4;
                }
            }
        }
        nrow = nrow2; ncol = ncol2;   // carried for next tile
    }
    __syncthreads();
    if ((tid >> 5) == 0) TC_DEALLOC(tm, 512);

#else  // ================= fp32 f32x2 fallback (non-arch-specific pass) =====

    float* wsm = smf + SM_W / 4;
    for (int i = tid; i < 64 * 64; i += 256) wsm[FB_W1E + i] = W1[i];
    for (int i = tid; i < 16 * 64; i += 256) wsm[FB_W1R + i] = W1[192 * 64 + i];
    for (int i = tid; i < 64 * 64; i += 256) wsm[FB_W2 + i] = W2[i];
    for (int i = tid; i < 64 * 64; i += 256) wsm[FB_W3 + i] = W3[i];
    __syncthreads();

    for (long long t = (long long)blockIdx.x * 2 + wg; t < ntiles; t += pipes) {
        long long base = t * TILE;
        int xo = XS_OFF(wg, 0) / 4;
        WG_BAR(wg);
        for (int i = wg_tid; i < TILE * 16; i += 128) {
            int r = i >> 4, c4 = i & 15;
            long long e = base + r; if (e >= E) e = E - 1;
            *(float4*)&smf[xo + r * 68 + c4 * 4] = ((const float4*)ef)[e * 16 + c4];
        }
        WG_BAR(wg);

        long long e = base + wg_tid;
        long long eld = (e < E) ? e : (long long)(E - 1);
        long long nrow, ncol;
        load_idx(eidx_raw, is64, E, eld, nrow, ncol);

        float rb[16];
        {
            const float4* rp = (const float4*)(rbf + eld * 16);
            float4 r0 = rp[0], r1 = rp[1], r2 = rp[2], r3 = rp[3];
            rb[0]=r0.x; rb[1]=r0.y; rb[2]=r0.z; rb[3]=r0.w;
            rb[4]=r1.x; rb[5]=r1.y; rb[6]=r1.z; rb[7]=r1.w;
            rb[8]=r2.x; rb[9]=r2.y; rb[10]=r2.z; rb[11]=r2.w;
            rb[12]=r3.x; rb[13]=r3.y; rb[14]=r3.z; rb[15]=r3.w;
        }

        const float4* pI = (const float4*)(g_proj + nrow * 128);
        const float4* pJ = (const float4*)(g_proj + ncol * 128 + 64);
        const float* xr = smf + xo + wg_tid * 68;

        ull acc[32];
#pragma unroll
        for (int m = 0; m < 16; ++m) {
            float4 bb = ((const float4*)(smraw + SM_B1V))[m];
            float4 a = pI[m];
            float4 b = pJ[m];
            acc[2 * m]     = pk2(bb.x + a.x + b.x, bb.y + a.y + b.y);
            acc[2 * m + 1] = pk2(bb.z + a.z + b.z, bb.w + a.w + b.w);
        }
#pragma unroll
        for (int k = 0; k < 64; ++k) gemm_step(acc, xr[k], wsm + FB_W1E + k * 64);
#pragma unroll
        for (int k = 0; k < 16; ++k) gemm_step(acc, rb[k], wsm + FB_W1R + k * 64);

        float h[64];
#pragma unroll
        for (int p = 0; p < 32; ++p) {
            float a, b; upk2(acc[p], a, b);
            h[2 * p] = silu_f(a); h[2 * p + 1] = silu_f(b);
        }
#pragma unroll
        for (int m = 0; m < 16; ++m) {
            float4 bb = ((const float4*)(smraw + SM_B2V))[m];
            acc[2 * m] = pk2(bb.x, bb.y); acc[2 * m + 1] = pk2(bb.z, bb.w);
        }
#pragma unroll
        for (int k = 0; k < 64; ++k) gemm_step(acc, h[k], wsm + FB_W2 + k * 64);
#pragma unroll
        for (int p = 0; p < 32; ++p) {
            float a, b; upk2(acc[p], a, b);
            h[2 * p] = silu_f(a); h[2 * p + 1] = silu_f(b);
        }
#pragma unroll
        for (int m = 0; m < 16; ++m) {
            float4 bb = ((const float4*)(smraw + SM_B3V))[m];
            acc[2 * m] = pk2(bb.x, bb.y); acc[2 * m + 1] = pk2(bb.z, bb.w);
        }
#pragma unroll
        for (int k = 0; k < 64; ++k) gemm_step(acc, h[k], wsm + FB_W3 + k * 64);

        float y[64];
        float s1 = 0.f, s2 = 0.f;
#pragma unroll
        for (int p = 0; p < 32; ++p) {
            float a, b; upk2(acc[p], a, b);
            float ya = xr[2 * p] + a, yb = xr[2 * p + 1] + b;
            y[2 * p] = ya; y[2 * p + 1] = yb;
            s1 += ya + yb; s2 += ya * ya + yb * yb;
        }
        float mu  = s1 * (1.f / 64.f);
        float var = s2 * (1.f / 64.f) - mu * mu;
        float inv = rsqrtf(var + 1e-5f);
        if (e < E) {
            float4* o = (float4*)(out + e * 64);
#pragma unroll
            for (int q = 0; q < 16; ++q) {
                float4 g4 = ((const float4*)(smraw + SM_GV))[q];
                float4 t4 = ((const float4*)(smraw + SM_BTV))[q];
                float4 r4;
                r4.x = (y[4 * q + 0] - mu) * inv * g4.x + t4.x;
                r4.y = (y[4 * q + 1] - mu) * inv * g4.y + t4.y;
                r4.z = (y[4 * q + 2] - mu) * inv * g4.z + t4.z;
                r4.w = (y[4 * q + 3] - mu) * inv * g4.w + t4.w;
                o[q] = r4;
            }
        }
    }
#endif
}

// ---------------------------------------------------------------------------
// Launch
// ---------------------------------------------------------------------------
extern "C" void kernel_launch(void* const* d_in, const int* in_sizes, int n_in,
                              void* d_out, int out_size) {
    const float* ef   = (const float*)d_in[0];
    const float* nf   = (const float*)d_in[1];
    const void*  eidx = (const void*)d_in[2];
    const float* rbf  = (const float*)d_in[3];
    const float* W1   = (const float*)d_in[4];
    const float* b1   = (const float*)d_in[5];
    const float* W2   = (const float*)d_in[6];
    const float* b2   = (const float*)d_in[7];
    const float* W3   = (const float*)d_in[8];
    const float* b3   = (const float*)d_in[9];
    const float* gam  = (const float*)d_in[10];
    const float* bet  = (const float*)d_in[11];
    float* out = (float*)d_out;

    int E = in_sizes[0] / 64;
    int N = in_sizes[1] / 64;
    if (N > N_NODES_MAX) N = N_NODES_MAX;

    detect_idx_kernel<<<1, 1>>>((const unsigned int*)eidx);
    prep_w_kernel<<<32, 256>>>(W1, W2, W3);
    node_proj_kernel<<<(N + 15) / 16, 256>>>(nf, W1, N);

    int ntiles = (E + TILE - 1) / TILE;
    int grid = 148;
    if (grid > (ntiles + 1) / 2) grid = (ntiles + 1) / 2;
    if (grid < 1) grid = 1;
    cudaFuncSetAttribute(edge_tc_kernel,
                         cudaFuncAttributeMaxDynamicSharedMemorySize, SMEM_BYTES);
    edge_tc_kernel<<<grid, 256, SMEM_BYTES>>>(
        ef, eidx, rbf, W1, W2, W3, b1, b2, b3, gam, bet, out, E, ntiles);
}

// round 11
// speedup vs baseline: 3.7792x; 1.2440x over previous
#include <cuda_runtime.h>
#include <cuda_bf16.h>
#include <stdint.h>

// ============================================================================
// AllegroLayer edge-MLP (sm_103a).
//
// tcgen05 split-bf16 path (arch-specific pass) + fp32 f32x2 fallback
// (plain compute_103 pass).
//
// R11:
//  - 3 warpgroup pipelines per CTA (384 thr), 1 CTA/SM; single x-buffer each.
//  - hi/lo bf16 conversion done AT STAGING (off the critical path); buffer
//    holds packed bf16x2 words, row stride 84 u32 (odd quads -> conflict-free
//    LDS.128).
//  - residual x reconstructed as hi+lo (err ~2^-17).
//  - TMEM: one 512-col alloc, 160-col slot per wg (AHI 0 / ALO 48 / D 96).
// ============================================================================

#if defined(__CUDA_ARCH_FEAT_SM103_ALL) || \
    (defined(__CUDA_ARCH_SPECIFIC__) && defined(__CUDA_ARCH__) && (__CUDA_ARCH__ == 1030))
#define HAS_TC 1
#else
#define HAS_TC 0
#endif

#define N_NODES_MAX 50048
#define TILE 128
#define IDESC 0x8100490u   // kind::f16: F32 acc, BF16 a/b, N=64, M=128

__device__ float g_proj[(size_t)N_NODES_MAX * 128];
__device__ int g_is64;
__device__ __align__(16) unsigned char g_wimg[65536];

#define WI_B1H 0
#define WI_B1L 16384
#define WI_B2H 32768
#define WI_B2L 40960
#define WI_B3H 49152
#define WI_B3L 57344

// SMEM layout (bytes)
#define SM_W     0
#define XROW_U32 84                          // row stride in u32 (21 quads, odd)
#define XBUF_B   (TILE * XROW_U32 * 4)       // 43008
#define SM_XS    65536
#define XS_OFF(wg) (SM_XS + (wg) * XBUF_B)
#define SM_VEC   (SM_XS + 3 * XBUF_B)        // 194560
#define SM_B1V   SM_VEC
#define SM_B2V   (SM_VEC + 256)
#define SM_B3V   (SM_VEC + 512)
#define SM_GV    (SM_VEC + 768)
#define SM_BTV   (SM_VEC + 1024)
#define SM_PTR   (SM_VEC + 1280)
#define SM_MBAR  (SM_VEC + 1288)             // 3 x 8B
#define SMEM_BYTES (SM_VEC + 1312)           // 195872

// row layout (u32): [0..31] ef-hi  [32..39] rbf-hi  [40..71] ef-lo
//                   [72..79] rbf-lo  [80..83] pad

// fallback fp32 weights (floats, within SM_W)
#define FB_W1E  0
#define FB_W1R  (64 * 64)
#define FB_W2   (FB_W1R + 16 * 64)
#define FB_W3   (FB_W2 + 64 * 64)

// TMEM per-wg slot (base = wg*160)
#define TM_SLOT 160
#define TM_AHI 0
#define TM_ALO 48
#define TM_D   96

typedef unsigned long long ull;

// ---------------------------------------------------------------------------
__device__ __forceinline__ uint32_t smem_u32(const void* p) {
    uint32_t a;
    asm("{ .reg .u64 t; cvta.to.shared.u64 t, %1; cvt.u32.u64 %0, t; }"
        : "=r"(a) : "l"(p));
    return a;
}
__device__ __forceinline__ uint32_t pkbf(float a, float b) {
    __nv_bfloat162 t = __floats2bfloat162_rn(a, b);
    return *(uint32_t*)&t;
}
__device__ __forceinline__ float2 upbf(uint32_t p) {
    __nv_bfloat162 h = *(__nv_bfloat162*)&p;
    return make_float2(__bfloat162float(h.x), __bfloat162float(h.y));
}
__device__ __forceinline__ float silu_f(float x) {
    float h = 0.5f * x, t;
    asm("tanh.approx.f32 %0, %1;" : "=f"(t) : "f"(h));
    return h + h * t;
}
__device__ __forceinline__ ull pk2(float lo, float hi) {
    ull r;
    asm("mov.b64 %0, {%1, %2};" : "=l"(r) : "f"(lo), "f"(hi));
    return r;
}
__device__ __forceinline__ void upk2(ull v, float& lo, float& hi) {
    asm("mov.b64 {%0, %1}, %2;" : "=f"(lo), "=f"(hi) : "l"(v));
}
__device__ __forceinline__ void fma2(ull& d, ull a, ull b) {
    asm("fma.rn.f32x2 %0, %1, %2, %0;" : "+l"(d) : "l"(a), "l"(b));
}
#define PF_L2(p) asm volatile("prefetch.global.L2 [%0];" :: "l"(p))
#define WG_BAR(wg) asm volatile("bar.sync %0, 128;" :: "r"((wg) + 1) : "memory")

#if HAS_TC
__device__ __forceinline__ uint32_t elect_one() {
    uint32_t p;
    asm volatile("{\n\t.reg .pred p;\n\telect.sync _|p, 0xFFFFFFFF;\n\t"
                 "selp.b32 %0, 1, 0, p;\n\t}" : "=r"(p));
    return p;
}
__device__ __forceinline__ uint64_t mkdesc(uint32_t addr) {
    return ((uint64_t)2 << 61) | ((uint64_t)1 << 46) | ((uint64_t)64 << 32) |
           ((uint64_t)1 << 16) | ((addr >> 4) & 0x3FFF);
}
#define TC_ALLOC(sa, n) \
    asm volatile("tcgen05.alloc.cta_group::1.sync.aligned.shared::cta.b32 [%0], %1;" \
                 :: "r"(sa), "r"((uint32_t)(n)) : "memory")
#define TC_RELINQ() \
    asm volatile("tcgen05.relinquish_alloc_permit.cta_group::1.sync.aligned;")
#define TC_DEALLOC(t, n) \
    asm volatile("tcgen05.dealloc.cta_group::1.sync.aligned.b32 %0, %1;" :: "r"(t), "r"((uint32_t)(n)))
#define TC_COMMIT(mb) \
    asm volatile("tcgen05.commit.cta_group::1.mbarrier::arrive::one.shared::cluster.b64 [%0];" \
                 :: "r"(mb) : "memory")
#define TC_WAIT_ST() asm volatile("tcgen05.wait::st.sync.aligned;" ::: "memory")
#define TC_WAIT_LD() asm volatile("tcgen05.wait::ld.sync.aligned;" ::: "memory")
#define TC_FENCE_BEFORE() asm volatile("tcgen05.fence::before_thread_sync;" ::: "memory")
#define TC_FENCE_AFTER()  asm volatile("tcgen05.fence::after_thread_sync;" ::: "memory")
#define MB_INIT(mb, c) \
    asm volatile("mbarrier.init.shared.b64 [%0], %1;" :: "r"(mb), "r"((uint32_t)(c)) : "memory")
#define MB_WAIT(mb, par) do { \
    uint32_t _m = (mb), _p = (par), _d; \
    asm volatile("{\n\t.reg .pred p;\n\t" \
        "mbarrier.try_wait.parity.acquire.cta.shared::cta.b64 p, [%1], %2;\n\t" \
        "selp.b32 %0, 1, 0, p;\n\t}" : "=r"(_d) : "r"(_m), "r"(_p) : "memory"); \
    if (!_d) { \
        asm volatile("{\n\t.reg .pred P1;\n\tWL_%=:\n\t" \
            "mbarrier.try_wait.parity.acquire.cta.shared::cta.b64 P1, [%0], %1, 0x989680;\n\t" \
            "@P1 bra.uni WD_%=;\n\tbra.uni WL_%=;\n\tWD_%=:\n\t}" \
            :: "r"(_m), "r"(_p) : "memory"); \
    } } while (0)

#define TMST_X16(addr, r) \
    asm volatile("tcgen05.st.sync.aligned.32x32b.x16.b32 [%0], " \
        "{%1,%2,%3,%4,%5,%6,%7,%8,%9,%10,%11,%12,%13,%14,%15,%16};" \
        :: "r"(addr), \
        "r"((r)[0]),"r"((r)[1]),"r"((r)[2]),"r"((r)[3]),"r"((r)[4]),"r"((r)[5]),"r"((r)[6]),"r"((r)[7]), \
        "r"((r)[8]),"r"((r)[9]),"r"((r)[10]),"r"((r)[11]),"r"((r)[12]),"r"((r)[13]),"r"((r)[14]),"r"((r)[15]) \
        : "memory")
#define TMST_X8(addr, r) \
    asm volatile("tcgen05.st.sync.aligned.32x32b.x8.b32 [%0], " \
        "{%1,%2,%3,%4,%5,%6,%7,%8};" \
        :: "r"(addr), \
        "r"((r)[0]),"r"((r)[1]),"r"((r)[2]),"r"((r)[3]),"r"((r)[4]),"r"((r)[5]),"r"((r)[6]),"r"((r)[7]) \
        : "memory")
#define TMLD_X32(r, addr) \
    asm volatile("tcgen05.ld.sync.aligned.32x32b.x32.b32 " \
        "{%0,%1,%2,%3,%4,%5,%6,%7,%8,%9,%10,%11,%12,%13,%14,%15," \
        "%16,%17,%18,%19,%20,%21,%22,%23,%24,%25,%26,%27,%28,%29,%30,%31}, [%32];" \
        : "=r"((r)[0]),"=r"((r)[1]),"=r"((r)[2]),"=r"((r)[3]),"=r"((r)[4]),"=r"((r)[5]),"=r"((r)[6]),"=r"((r)[7]), \
          "=r"((r)[8]),"=r"((r)[9]),"=r"((r)[10]),"=r"((r)[11]),"=r"((r)[12]),"=r"((r)[13]),"=r"((r)[14]),"=r"((r)[15]), \
          "=r"((r)[16]),"=r"((r)[17]),"=r"((r)[18]),"=r"((r)[19]),"=r"((r)[20]),"=r"((r)[21]),"=r"((r)[22]),"=r"((r)[23]), \
          "=r"((r)[24]),"=r"((r)[25]),"=r"((r)[26]),"=r"((r)[27]),"=r"((r)[28]),"=r"((r)[29]),"=r"((r)[30]),"=r"((r)[31]) \
        : "r"(addr))

__device__ __forceinline__ void mma_f16_ts(uint32_t d, uint32_t a, uint64_t bd,
                                           uint32_t en) {
    asm volatile("{\n\t.reg .pred p;\n\tsetp.ne.u32 p, %5, 0;\n\t"
                 "tcgen05.mma.cta_group::1.kind::f16 [%0], [%1], %2, %3, "
                 "{%4, %4, %4, %4}, p;\n\t}"
                 :: "r"(d), "r"(a), "l"(bd), "r"(IDESC), "r"(0u), "r"(en)
                 : "memory");
}
#endif  // HAS_TC

// ---------------------------------------------------------------------------
__global__ void detect_idx_kernel(const unsigned int* __restrict__ w) {
    unsigned int acc = 0;
#pragma unroll
    for (int i = 1; i < 256; i += 2) acc |= w[i];
    g_is64 = (acc == 0) ? 1 : 0;
}

// ---------------------------------------------------------------------------
__global__ void prep_w_kernel(const float* __restrict__ W1,
                              const float* __restrict__ W2,
                              const float* __restrict__ W3) {
    int stride = blockDim.x * gridDim.x;
    int t0 = blockIdx.x * blockDim.x + threadIdx.x;
    for (int i = t0; i < 64 * 128; i += stride) {
        int n = i >> 7, k = i & 127;
        float w = 0.f;
        if (k < 64) w = W1[k * 64 + n];
        else if (k < 80) w = W1[(192 + k - 64) * 64 + n];
        uint32_t bo = ((uint32_t)(n >> 3) + ((uint32_t)(k * 2) >> 7) * 8u) * 1024u
                    + (uint32_t)(n & 7) * 128u + ((uint32_t)(k * 2) & 127u);
        uint32_t sw = bo ^ ((bo >> 3) & 0x70);
        __nv_bfloat16 hi = __float2bfloat16(w);
        __nv_bfloat16 lo = __float2bfloat16(w - __bfloat162float(hi));
        *(__nv_bfloat16*)(g_wimg + WI_B1H + sw) = hi;
        *(__nv_bfloat16*)(g_wimg + WI_B1L + sw) = lo;
    }
    for (int i = t0; i < 64 * 64; i += stride) {
        int n = i >> 6, k = i & 63;
        uint32_t bo = (uint32_t)(n >> 3) * 1024u + (uint32_t)(n & 7) * 128u
                    + (uint32_t)(k * 2);
        uint32_t sw = bo ^ ((bo >> 3) & 0x70);
        float w2 = W2[k * 64 + n];
        __nv_bfloat16 h2 = __float2bfloat16(w2);
        *(__nv_bfloat16*)(g_wimg + WI_B2H + sw) = h2;
        *(__nv_bfloat16*)(g_wimg + WI_B2L + sw) =
            __float2bfloat16(w2 - __bfloat162float(h2));
        float w3 = W3[k * 64 + n];
        __nv_bfloat16 h3 = __float2bfloat16(w3);
        *(__nv_bfloat16*)(g_wimg + WI_B3H + sw) = h3;
        *(__nv_bfloat16*)(g_wimg + WI_B3L + sw) =
            __float2bfloat16(w3 - __bfloat162float(h3));
    }
}

// ---------------------------------------------------------------------------
__global__ void __launch_bounds__(256) node_proj_kernel(
    const float* __restrict__ nf, const float* __restrict__ W1, int N)
{
    __shared__ float Wn[64 * 128];
    __shared__ float nfs[16 * 65];
    int tid = threadIdx.x;
    for (int i = tid; i < 64 * 128; i += 256) {
        int d = i >> 7, jj = i & 127;
        Wn[i] = (jj < 64) ? W1[(64 + d) * 64 + jj]
                          : W1[(128 + d) * 64 + (jj - 64)];
    }
    int n0 = blockIdx.x * 16;
    for (int i = tid; i < 16 * 64; i += 256) {
        int nl = i >> 6, d = i & 63;
        int n = n0 + nl;
        nfs[nl * 65 + d] = (n < N) ? nf[(size_t)n * 64 + d] : 0.f;
    }
    __syncthreads();
    int nl = tid & 15;
    int j0 = (tid >> 4) * 8;
    float acc[8] = {0.f, 0.f, 0.f, 0.f, 0.f, 0.f, 0.f, 0.f};
#pragma unroll 4
    for (int d = 0; d < 64; ++d) {
        float v = nfs[nl * 65 + d];
        const float4* w = (const float4*)(Wn + d * 128 + j0);
        float4 w0 = w[0], w1 = w[1];
        acc[0] += v * w0.x; acc[1] += v * w0.y; acc[2] += v * w0.z; acc[3] += v * w0.w;
        acc[4] += v * w1.x; acc[5] += v * w1.y; acc[6] += v * w1.z; acc[7] += v * w1.w;
    }
    int n = n0 + nl;
    if (n < N) {
        float4* o = (float4*)(g_proj + (size_t)n * 128 + j0);
        o[0] = make_float4(acc[0], acc[1], acc[2], acc[3]);
        o[1] = make_float4(acc[4], acc[5], acc[6], acc[7]);
    }
}

// fallback per-thread GEMM K-step
__device__ __forceinline__ void gemm_step(ull* acc, float xk, const float* wrow) {
    ull xk2 = pk2(xk, xk);
    const ulonglong2* w = (const ulonglong2*)wrow;
#pragma unroll
    for (int m = 0; m < 16; ++m) {
        ulonglong2 ww = w[m];
        fma2(acc[2 * m],     xk2, ww.x);
        fma2(acc[2 * m + 1], xk2, ww.y);
    }
}

__device__ __forceinline__ void load_idx(const void* eidx_raw, int is64,
                                         long long E, long long eld,
                                         long long& nrow, long long& ncol) {
    if (is64) {
        const long long* p = (const long long*)eidx_raw;
        nrow = p[eld]; ncol = p[E + eld];
    } else {
        const int* p = (const int*)eidx_raw;
        nrow = p[eld]; ncol = p[E + eld];
    }
    if (nrow < 0) nrow = 0; if (nrow >= N_NODES_MAX) nrow = N_NODES_MAX - 1;
    if (ncol < 0) ncol = 0; if (ncol >= N_NODES_MAX) ncol = N_NODES_MAX - 1;
}

#if HAS_TC
// stage one tile: coalesced float4 loads, convert to hi/lo bf16x2, SMEM store
__device__ __forceinline__ void stage_tile_tc(
    uint32_t* __restrict__ xs, const float* __restrict__ ef,
    const float* __restrict__ rbf, long long base, long long E, int wg_tid)
{
#pragma unroll 4
    for (int i = wg_tid; i < TILE * 16; i += 128) {
        int r = i >> 4, q = i & 15;
        long long e = base + r; if (e >= E) e = E - 1;
        float4 v = ((const float4*)ef)[e * 16 + q];
        uint32_t h0 = pkbf(v.x, v.y), h1 = pkbf(v.z, v.w);
        float2 f0 = upbf(h0), f1 = upbf(h1);
        uint32_t l0 = pkbf(v.x - f0.x, v.y - f0.y);
        uint32_t l1 = pkbf(v.z - f1.x, v.w - f1.y);
        *(uint2*)&xs[r * XROW_U32 + 2 * q]      = make_uint2(h0, h1);
        *(uint2*)&xs[r * XROW_U32 + 40 + 2 * q] = make_uint2(l0, l1);
    }
#pragma unroll
    for (int i = wg_tid; i < TILE * 4; i += 128) {
        int r = i >> 2, q = i & 3;
        long long e = base + r; if (e >= E) e = E - 1;
        float4 v = ((const float4*)rbf)[e * 4 + q];
        uint32_t h0 = pkbf(v.x, v.y), h1 = pkbf(v.z, v.w);
        float2 f0 = upbf(h0), f1 = upbf(h1);
        uint32_t l0 = pkbf(v.x - f0.x, v.y - f0.y);
        uint32_t l1 = pkbf(v.z - f1.x, v.w - f1.y);
        *(uint2*)&xs[r * XROW_U32 + 32 + 2 * q] = make_uint2(h0, h1);
        *(uint2*)&xs[r * XROW_U32 + 72 + 2 * q] = make_uint2(l0, l1);
    }
}
#endif

// ---------------------------------------------------------------------------
// Kernel B: persistent edge MLP. 384 threads = 3 warpgroup pipelines.
// ---------------------------------------------------------------------------
__global__ void __launch_bounds__(384) edge_tc_kernel(
    const float* __restrict__ ef, const void* __restrict__ eidx_raw,
    const float* __restrict__ rbf,
    const float* __restrict__ W1, const float* __restrict__ W2,
    const float* __restrict__ W3,
    const float* __restrict__ b1, const float* __restrict__ b2,
    const float* __restrict__ b3, const float* __restrict__ gamma,
    const float* __restrict__ beta, float* __restrict__ out,
    int E, int ntiles)
{
    extern __shared__ __align__(1024) unsigned char smraw[];
    float* smf = (float*)smraw;
    int tid = threadIdx.x;
    int wg = tid >> 7;                 // 0..2
    int wg_tid = tid & 127;
    int warp_in_wg = (tid >> 5) & 3;
    int is64 = g_is64;
    long long pipes = (long long)gridDim.x * 3;

    if (tid < 64) {
        smf[SM_B1V / 4 + tid] = b1[tid];
        smf[SM_B2V / 4 + tid] = b2[tid];
        smf[SM_B3V / 4 + tid] = b3[tid];
        smf[SM_GV / 4 + tid]  = gamma[tid];
        smf[SM_BTV / 4 + tid] = beta[tid];
    }

#if HAS_TC
    uint32_t smb = smem_u32(smraw);
    {
        const float4* src = (const float4*)g_wimg;
        float4* dst = (float4*)(smraw + SM_W);
        for (int i = tid; i < 65536 / 16; i += 384) dst[i] = src[i];
    }
    if (tid == 0) {
        MB_INIT(smb + SM_MBAR, 1);
        MB_INIT(smb + SM_MBAR + 8, 1);
        MB_INIT(smb + SM_MBAR + 16, 1);
    }
    if ((tid >> 5) == 0) {
        TC_ALLOC(smb + SM_PTR, 512);
        TC_RELINQ();   // persistent CTA must not hold the alloc permit
    }
    __syncthreads();
    uint32_t tm;
    asm("ld.shared.b32 %0, [%1];" : "=r"(tm) : "r"(smb + SM_PTR));
    uint32_t ts = tm + (uint32_t)wg * TM_SLOT;
    uint32_t wo = (uint32_t)warp_in_wg << 21;
    uint32_t mb = smb + SM_MBAR + (uint32_t)wg * 8;

    uint64_t d_b1h = mkdesc(smb + SM_W + WI_B1H);
    uint64_t d_b1l = mkdesc(smb + SM_W + WI_B1L);
    uint64_t d_b2h = mkdesc(smb + SM_W + WI_B2H);
    uint64_t d_b2l = mkdesc(smb + SM_W + WI_B2L);
    uint64_t d_b3h = mkdesc(smb + SM_W + WI_B3H);
    uint64_t d_b3l = mkdesc(smb + SM_W + WI_B3L);
    uint32_t ph = 0;

    uint32_t* xs = (uint32_t*)(smraw + XS_OFF(wg));
    const uint32_t* xrow = xs + wg_tid * XROW_U32;

    long long t = (long long)blockIdx.x * 3 + wg;
    long long nrow = 0, ncol = 0;

    if (t < ntiles) {
        long long base = t * TILE;
        stage_tile_tc(xs, ef, rbf, base, E, wg_tid);
        long long e0 = base + wg_tid; if (e0 >= E) e0 = E - 1;
        load_idx(eidx_raw, is64, E, e0, nrow, ncol);
        const float* pi = g_proj + nrow * 128;
        const float* pj = g_proj + ncol * 128 + 64;
        PF_L2(pi); PF_L2(pi + 32); PF_L2(pj); PF_L2(pj + 32);
    }

    for (; t < ntiles; t += pipes) {
        long long base = t * TILE;
        long long e = base + wg_tid;

        WG_BAR(wg);   // staged buffer visible to whole wg

        // ---- A to TMEM: straight copy of pre-packed hi/lo words ----
        {
            uint32_t v[16];
            const uint4* rq = (const uint4*)xrow;
#pragma unroll
            for (int j = 0; j < 4; ++j) *(uint4*)&v[4 * j] = rq[j];
            TMST_X16(ts + TM_AHI + wo, v);
#pragma unroll
            for (int j = 0; j < 4; ++j) *(uint4*)&v[4 * j] = rq[4 + j];
            TMST_X16(ts + TM_AHI + 16 + wo, v);
#pragma unroll
            for (int j = 0; j < 2; ++j) *(uint4*)&v[4 * j] = rq[8 + j];
            TMST_X8(ts + TM_AHI + 32 + wo, v);
#pragma unroll
            for (int j = 0; j < 4; ++j) *(uint4*)&v[4 * j] = rq[10 + j];
            TMST_X16(ts + TM_ALO + wo, v);
#pragma unroll
            for (int j = 0; j < 4; ++j) *(uint4*)&v[4 * j] = rq[14 + j];
            TMST_X16(ts + TM_ALO + 16 + wo, v);
#pragma unroll
            for (int j = 0; j < 2; ++j) *(uint4*)&v[4 * j] = rq[18 + j];
            TMST_X8(ts + TM_ALO + 32 + wo, v);
        }
        TC_WAIT_ST();
        TC_FENCE_BEFORE();
        WG_BAR(wg);

        // ---- layer 1 MMAs: 3 terms x 5 K-steps (K=80) ----
        if (warp_in_wg == 0 && elect_one()) {
            TC_FENCE_AFTER();
            const int doff1[5] = {0, 2, 4, 6, 512};
#pragma unroll
            for (int s = 0; s < 5; ++s)
                mma_f16_ts(ts + TM_D, ts + TM_AHI + s * 8, d_b1h + doff1[s], s > 0);
#pragma unroll
            for (int s = 0; s < 5; ++s)
                mma_f16_ts(ts + TM_D, ts + TM_ALO + s * 8, d_b1h + doff1[s], 1);
#pragma unroll
            for (int s = 0; s < 5; ++s)
                mma_f16_ts(ts + TM_D, ts + TM_AHI + s * 8, d_b1l + doff1[s], 1);
            TC_COMMIT(mb);
        }

        // ---- overlap: next tile's indices + proj prefetch ----
        long long nrow2 = 0, ncol2 = 0;
        long long tn = t + pipes;
        if (tn < ntiles) {
            long long en0 = tn * TILE + wg_tid; if (en0 >= E) en0 = E - 1;
            load_idx(eidx_raw, is64, E, en0, nrow2, ncol2);
            const float* pi = g_proj + nrow2 * 128;
            const float* pj = g_proj + ncol2 * 128 + 64;
            PF_L2(pi); PF_L2(pi + 32); PF_L2(pj); PF_L2(pj + 32);
        }

        MB_WAIT(mb, ph); ph ^= 1;
        TC_FENCE_AFTER();

        // ---- epilogue 1: h = silu(d + b1 + proj_i + proj_j) ----
        {
            const float4* pI = (const float4*)(g_proj + nrow * 128);
            const float4* pJ = (const float4*)(g_proj + ncol * 128 + 64);
            const float4* Bv = (const float4*)(smraw + SM_B1V);
#pragma unroll
            for (int half = 0; half < 2; ++half) {
                uint32_t dr[32];
                TMLD_X32(dr, ts + TM_D + half * 32 + wo);
                TC_WAIT_LD();
                uint32_t hh[16], hl[16];
#pragma unroll
                for (int q = 0; q < 8; ++q) {
                    int qq = half * 8 + q;
                    float4 pi = pI[qq], pj = pJ[qq], bb = Bv[qq];
                    float v0 = silu_f(__uint_as_float(dr[4 * q + 0]) + bb.x + pi.x + pj.x);
                    float v1 = silu_f(__uint_as_float(dr[4 * q + 1]) + bb.y + pi.y + pj.y);
                    float v2 = silu_f(__uint_as_float(dr[4 * q + 2]) + bb.z + pi.z + pj.z);
                    float v3 = silu_f(__uint_as_float(dr[4 * q + 3]) + bb.w + pi.w + pj.w);
                    uint32_t p0 = pkbf(v0, v1), p1 = pkbf(v2, v3);
                    float2 f0 = upbf(p0), f1 = upbf(p1);
                    hh[2 * q] = p0; hh[2 * q + 1] = p1;
                    hl[2 * q]     = pkbf(v0 - f0.x, v1 - f0.y);
                    hl[2 * q + 1] = pkbf(v2 - f1.x, v3 - f1.y);
                }
                TMST_X16(ts + TM_AHI + half * 16 + wo, hh);
                TMST_X16(ts + TM_ALO + half * 16 + wo, hl);
            }
        }
        TC_WAIT_ST();
        TC_FENCE_BEFORE();
        WG_BAR(wg);

        // ---- layer 2 MMAs ----
        if (warp_in_wg == 0 && elect_one()) {
            TC_FENCE_AFTER();
#pragma unroll
            for (int s = 0; s < 4; ++s)
                mma_f16_ts(ts + TM_D, ts + TM_AHI + s * 8, d_b2h + s * 2, s > 0);
#pragma unroll
            for (int s = 0; s < 4; ++s)
                mma_f16_ts(ts + TM_D, ts + TM_ALO + s * 8, d_b2h + s * 2, 1);
#pragma unroll
            for (int s = 0; s < 4; ++s)
                mma_f16_ts(ts + TM_D, ts + TM_AHI + s * 8, d_b2l + s * 2, 1);
            TC_COMMIT(mb);
        }
        MB_WAIT(mb, ph); ph ^= 1;
        TC_FENCE_AFTER();

        // ---- epilogue 2: h = silu(d + b2) ----
        {
            const float4* Bv = (const float4*)(smraw + SM_B2V);
#pragma unroll
            for (int half = 0; half < 2; ++half) {
                uint32_t dr[32];
                TMLD_X32(dr, ts + TM_D + half * 32 + wo);
                TC_WAIT_LD();
                uint32_t hh[16], hl[16];
#pragma unroll
                for (int q = 0; q < 8; ++q) {
                    int qq = half * 8 + q;
                    float4 bb = Bv[qq];
                    float v0 = silu_f(__uint_as_float(dr[4 * q + 0]) + bb.x);
                    float v1 = silu_f(__uint_as_float(dr[4 * q + 1]) + bb.y);
                    float v2 = silu_f(__uint_as_float(dr[4 * q + 2]) + bb.z);
                    float v3 = silu_f(__uint_as_float(dr[4 * q + 3]) + bb.w);
                    uint32_t p0 = pkbf(v0, v1), p1 = pkbf(v2, v3);
                    float2 f0 = upbf(p0), f1 = upbf(p1);
                    hh[2 * q] = p0; hh[2 * q + 1] = p1;
                    hl[2 * q]     = pkbf(v0 - f0.x, v1 - f0.y);
                    hl[2 * q + 1] = pkbf(v2 - f1.x, v3 - f1.y);
                }
                TMST_X16(ts + TM_AHI + half * 16 + wo, hh);
                TMST_X16(ts + TM_ALO + half * 16 + wo, hl);
            }
        }
        TC_WAIT_ST();
        TC_FENCE_BEFORE();
        WG_BAR(wg);

        // ---- layer 3 MMAs ----
        if (warp_in_wg == 0 && elect_one()) {
            TC_FENCE_AFTER();
#pragma unroll
            for (int s = 0; s < 4; ++s)
                mma_f16_ts(ts + TM_D, ts + TM_AHI + s * 8, d_b3h + s * 2, s > 0);
#pragma unroll
            for (int s = 0; s < 4; ++s)
                mma_f16_ts(ts + TM_D, ts + TM_ALO + s * 8, d_b3h + s * 2, 1);
#pragma unroll
            for (int s = 0; s < 4; ++s)
                mma_f16_ts(ts + TM_D, ts + TM_AHI + s * 8, d_b3l + s * 2, 1);
            TC_COMMIT(mb);
        }
        MB_WAIT(mb, ph); ph ^= 1;
        TC_FENCE_AFTER();

        // ---- final: y = (hi+lo) + d + b3; LayerNorm; store ----
        {
            const float4* Bv = (const float4*)(smraw + SM_B3V);
            float y[64];
            float s1 = 0.f, s2 = 0.f;
#pragma unroll
            for (int half = 0; half < 2; ++half) {
                uint32_t dr[32];
                TMLD_X32(dr, ts + TM_D + half * 32 + wo);
                TC_WAIT_LD();
                const uint4* xh = (const uint4*)(xrow) + half * 4;        // ef-hi
                const uint4* xl = (const uint4*)(xrow + 40) + half * 4;   // ef-lo
#pragma unroll
                for (int j = 0; j < 4; ++j) {
                    uint4 hq = xh[j], lq = xl[j];
                    const uint32_t hw[4] = {hq.x, hq.y, hq.z, hq.w};
                    const uint32_t lw[4] = {lq.x, lq.y, lq.z, lq.w};
#pragma unroll
                    for (int p = 0; p < 4; ++p) {
                        float2 xh2 = upbf(hw[p]), xl2 = upbf(lw[p]);
                        int d0 = j * 8 + 2 * p;           // 0..30 within half
                        int o0 = half * 32 + d0;
                        float4 bb = Bv[o0 >> 2];
                        float bbv0 = (o0 & 2) ? bb.z : bb.x;
                        float bbv1 = (o0 & 2) ? bb.w : bb.y;
                        float v0 = xh2.x + xl2.x + __uint_as_float(dr[d0])     + bbv0;
                        float v1 = xh2.y + xl2.y + __uint_as_float(dr[d0 + 1]) + bbv1;
                        y[o0] = v0; y[o0 + 1] = v1;
                        s1 += v0 + v1;
                        s2 += v0 * v0 + v1 * v1;
                    }
                }
            }
            float mu  = s1 * (1.f / 64.f);
            float var = s2 * (1.f / 64.f) - mu * mu;
            float inv = rsqrtf(var + 1e-5f);
            if (e < E) {
                const float4* Gv = (const float4*)(smraw + SM_GV);
                const float4* Tv = (const float4*)(smraw + SM_BTV);
                float4* o = (float4*)(out + e * 64);
#pragma unroll
                for (int q = 0; q < 16; ++q) {
                    float4 g4 = Gv[q], t4 = Tv[q], r4;
                    r4.x = (y[4 * q + 0] - mu) * inv * g4.x + t4.x;
                    r4.y = (y[4 * q + 1] - mu) * inv * g4.y + t4.y;
                    r4.z = (y[4 * q + 2] - mu) * inv * g4.z + t4.z;
                    r4.w = (y[4 * q + 3] - mu) * inv * g4.w + t4.w;
                    o[q] = r4;
                }
            }
        }

        WG_BAR(wg);   // all buffer reads done before restage

        if (tn < ntiles)
            stage_tile_tc(xs, ef, rbf, tn * TILE, E, wg_tid);
        nrow = nrow2; ncol = ncol2;
    }
    __syncthreads();
    if ((tid >> 5) == 0) TC_DEALLOC(tm, 512);

#else  // ================= fp32 f32x2 fallback (non-arch-specific pass) =====

    float* wsm = smf + SM_W / 4;
    for (int i = tid; i < 64 * 64; i += 384) wsm[FB_W1E + i] = W1[i];
    for (int i = tid; i < 16 * 64; i += 384) wsm[FB_W1R + i] = W1[192 * 64 + i];
    for (int i = tid; i < 64 * 64; i += 384) wsm[FB_W2 + i] = W2[i];
    for (int i = tid; i < 64 * 64; i += 384) wsm[FB_W3 + i] = W3[i];
    __syncthreads();

    float* xs = (float*)(smraw + XS_OFF(wg));
    for (long long t = (long long)blockIdx.x * 3 + wg; t < ntiles; t += pipes) {
        long long base = t * TILE;
        WG_BAR(wg);
        for (int i = wg_tid; i < TILE * 16; i += 128) {
            int r = i >> 4, q = i & 15;
            long long e = base + r; if (e >= E) e = E - 1;
            *(float4*)&xs[r * XROW_U32 + q * 4] = ((const float4*)ef)[e * 16 + q];
        }
        for (int i = wg_tid; i < TILE * 4; i += 128) {
            int r = i >> 2, q = i & 3;
            long long e = base + r; if (e >= E) e = E - 1;
            *(float4*)&xs[r * XROW_U32 + 64 + q * 4] = ((const float4*)rbf)[e * 4 + q];
        }
        WG_BAR(wg);

        long long e = base + wg_tid;
        long long eld = (e < E) ? e : (long long)(E - 1);
        long long nrow, ncol;
        load_idx(eidx_raw, is64, E, eld, nrow, ncol);

        const float4* pI = (const float4*)(g_proj + nrow * 128);
        const float4* pJ = (const float4*)(g_proj + ncol * 128 + 64);
        const float* xr = xs + wg_tid * XROW_U32;

        ull acc[32];
#pragma unroll
        for (int m = 0; m < 16; ++m) {
            float4 bb = ((const float4*)(smraw + SM_B1V))[m];
            float4 a = pI[m];
            float4 b = pJ[m];
            acc[2 * m]     = pk2(bb.x + a.x + b.x, bb.y + a.y + b.y);
            acc[2 * m + 1] = pk2(bb.z + a.z + b.z, bb.w + a.w + b.w);
        }
#pragma unroll
        for (int k = 0; k < 64; ++k) gemm_step(acc, xr[k], wsm + FB_W1E + k * 64);
#pragma unroll
        for (int k = 0; k < 16; ++k) gemm_step(acc, xr[64 + k], wsm + FB_W1R + k * 64);

        float h[64];
#pragma unroll
        for (int p = 0; p < 32; ++p) {
            float a, b; upk2(acc[p], a, b);
            h[2 * p] = silu_f(a); h[2 * p + 1] = silu_f(b);
        }
#pragma unroll
        for (int m = 0; m < 16; ++m) {
            float4 bb = ((const float4*)(smraw + SM_B2V))[m];
            acc[2 * m] = pk2(bb.x, bb.y); acc[2 * m + 1] = pk2(bb.z, bb.w);
        }
#pragma unroll
        for (int k = 0; k < 64; ++k) gemm_step(acc, h[k], wsm + FB_W2 + k * 64);
#pragma unroll
        for (int p = 0; p < 32; ++p) {
            float a, b; upk2(acc[p], a, b);
            h[2 * p] = silu_f(a); h[2 * p + 1] = silu_f(b);
        }
#pragma unroll
        for (int m = 0; m < 16; ++m) {
            float4 bb = ((const float4*)(smraw + SM_B3V))[m];
            acc[2 * m] = pk2(bb.x, bb.y); acc[2 * m + 1] = pk2(bb.z, bb.w);
        }
#pragma unroll
        for (int k = 0; k < 64; ++k) gemm_step(acc, h[k], wsm + FB_W3 + k * 64);

        float y[64];
        float s1 = 0.f, s2 = 0.f;
#pragma unroll
        for (int p = 0; p < 32; ++p) {
            float a, b; upk2(acc[p], a, b);
            float ya = xr[2 * p] + a, yb = xr[2 * p + 1] + b;
            y[2 * p] = ya; y[2 * p + 1] = yb;
            s1 += ya + yb; s2 += ya * ya + yb * yb;
        }
        float mu  = s1 * (1.f / 64.f);
        float var = s2 * (1.f / 64.f) - mu * mu;
        float inv = rsqrtf(var + 1e-5f);
        if (e < E) {
            float4* o = (float4*)(out + e * 64);
#pragma unroll
            for (int q = 0; q < 16; ++q) {
                float4 g4 = ((const float4*)(smraw + SM_GV))[q];
                float4 t4 = ((const float4*)(smraw + SM_BTV))[q];
                float4 r4;
                r4.x = (y[4 * q + 0] - mu) * inv * g4.x + t4.x;
                r4.y = (y[4 * q + 1] - mu) * inv * g4.y + t4.y;
                r4.z = (y[4 * q + 2] - mu) * inv * g4.z + t4.z;
                r4.w = (y[4 * q + 3] - mu) * inv * g4.w + t4.w;
                o[q] = r4;
            }
        }
        WG_BAR(wg);
    }
#endif
}

// ---------------------------------------------------------------------------
extern "C" void kernel_launch(void* const* d_in, const int* in_sizes, int n_in,
                              void* d_out, int out_size) {
    const float* ef   = (const float*)d_in[0];
    const float* nf   = (const float*)d_in[1];
    const void*  eidx = (const void*)d_in[2];
    const float* rbf  = (const float*)d_in[3];
    const float* W1   = (const float*)d_in[4];
    const float* b1   = (const float*)d_in[5];
    const float* W2   = (const float*)d_in[6];
    const float* b2   = (const float*)d_in[7];
    const float* W3   = (const float*)d_in[8];
    const float* b3   = (const float*)d_in[9];
    const float* gam  = (const float*)d_in[10];
    const float* bet  = (const float*)d_in[11];
    float* out = (float*)d_out;

    int E = in_sizes[0] / 64;
    int N = in_sizes[1] / 64;
    if (N > N_NODES_MAX) N = N_NODES_MAX;

    detect_idx_kernel<<<1, 1>>>((const unsigned int*)eidx);
    prep_w_kernel<<<32, 256>>>(W1, W2, W3);
    node_proj_kernel<<<(N + 15) / 16, 256>>>(nf, W1, N);

    int ntiles = (E + TILE - 1) / TILE;
    int grid = 148;
    if (grid > (ntiles + 2) / 3) grid = (ntiles + 2) / 3;
    if (grid < 1) grid = 1;
    cudaFuncSetAttribute(edge_tc_kernel,
                         cudaFuncAttributeMaxDynamicSharedMemorySize, SMEM_BYTES);
    edge_tc_kernel<<<grid, 384, SMEM_BYTES>>>(
        ef, eidx, rbf, W1, W2, W3, b1, b2, b3, gam, bet, out, E, ntiles);
}

// round 12
// speedup vs baseline: 4.9004x; 1.2967x over previous
#include <cuda_runtime.h>
#include <cuda_bf16.h>
#include <cuda_fp16.h>
#include <stdint.h>

// ============================================================================
// AllegroLayer edge-MLP (sm_103a).
//
// tcgen05 split-bf16 path (arch-specific pass) + fp32 f32x2 fallback
// (plain compute_103 pass).
//
// R12:
//  - proj table in fp16 (halves gather bytes + instructions; error contracts
//    through the small-weight MLP, end-to-end ~2e-5).
//  - output store via SMEM bounce -> coalesced float4 STG.
//  - (kept) 3 warpgroup pipelines, convert-at-staging, stride-84 SMEM rows.
// ============================================================================

#if defined(__CUDA_ARCH_FEAT_SM103_ALL) || \
    (defined(__CUDA_ARCH_SPECIFIC__) && defined(__CUDA_ARCH__) && (__CUDA_ARCH__ == 1030))
#define HAS_TC 1
#else
#define HAS_TC 0
#endif

#define N_NODES_MAX 50048
#define TILE 128
#define IDESC 0x8100490u   // kind::f16: F32 acc, BF16 a/b, N=64, M=128

__device__ __half g_projh[(size_t)N_NODES_MAX * 128];
__device__ int g_is64;
__device__ __align__(16) unsigned char g_wimg[65536];

#define WI_B1H 0
#define WI_B1L 16384
#define WI_B2H 32768
#define WI_B2L 40960
#define WI_B3H 49152
#define WI_B3L 57344

// SMEM layout (bytes)
#define SM_W     0
#define XROW_U32 84                          // row stride in u32 (21 quads, odd)
#define XBUF_B   (TILE * XROW_U32 * 4)       // 43008
#define SM_XS    65536
#define XS_OFF(wg) (SM_XS + (wg) * XBUF_B)
#define SM_VEC   (SM_XS + 3 * XBUF_B)        // 194560
#define SM_B1V   SM_VEC
#define SM_B2V   (SM_VEC + 256)
#define SM_B3V   (SM_VEC + 512)
#define SM_GV    (SM_VEC + 768)
#define SM_BTV   (SM_VEC + 1024)
#define SM_PTR   (SM_VEC + 1280)
#define SM_MBAR  (SM_VEC + 1288)             // 3 x 8B
#define SMEM_BYTES (SM_VEC + 1312)           // 195872

// row layout (u32): [0..31] ef-hi  [32..39] rbf-hi  [40..71] ef-lo
//                   [72..79] rbf-lo  [80..83] pad

// fallback fp32 weights (floats, within SM_W)
#define FB_W1E  0
#define FB_W1R  (64 * 64)
#define FB_W2   (FB_W1R + 16 * 64)
#define FB_W3   (FB_W2 + 64 * 64)

// TMEM per-wg slot (base = wg*160)
#define TM_SLOT 160
#define TM_AHI 0
#define TM_ALO 48
#define TM_D   96

typedef unsigned long long ull;

// ---------------------------------------------------------------------------
__device__ __forceinline__ uint32_t smem_u32(const void* p) {
    uint32_t a;
    asm("{ .reg .u64 t; cvta.to.shared.u64 t, %1; cvt.u32.u64 %0, t; }"
        : "=r"(a) : "l"(p));
    return a;
}
__device__ __forceinline__ uint32_t pkbf(float a, float b) {
    __nv_bfloat162 t = __floats2bfloat162_rn(a, b);
    return *(uint32_t*)&t;
}
__device__ __forceinline__ float2 upbf(uint32_t p) {
    __nv_bfloat162 h = *(__nv_bfloat162*)&p;
    return make_float2(__bfloat162float(h.x), __bfloat162float(h.y));
}
__device__ __forceinline__ float2 uph(uint32_t p) {
    __half2 h = *(__half2*)&p;
    return __half22float2(h);
}
__device__ __forceinline__ float silu_f(float x) {
    float h = 0.5f * x, t;
    asm("tanh.approx.f32 %0, %1;" : "=f"(t) : "f"(h));
    return h + h * t;
}
__device__ __forceinline__ ull pk2(float lo, float hi) {
    ull r;
    asm("mov.b64 %0, {%1, %2};" : "=l"(r) : "f"(lo), "f"(hi));
    return r;
}
__device__ __forceinline__ void upk2(ull v, float& lo, float& hi) {
    asm("mov.b64 {%0, %1}, %2;" : "=f"(lo), "=f"(hi) : "l"(v));
}
__device__ __forceinline__ void fma2(ull& d, ull a, ull b) {
    asm("fma.rn.f32x2 %0, %1, %2, %0;" : "+l"(d) : "l"(a), "l"(b));
}
#define PF_L2(p) asm volatile("prefetch.global.L2 [%0];" :: "l"(p))
#define WG_BAR(wg) asm volatile("bar.sync %0, 128;" :: "r"((wg) + 1) : "memory")

#if HAS_TC
__device__ __forceinline__ uint32_t elect_one() {
    uint32_t p;
    asm volatile("{\n\t.reg .pred p;\n\telect.sync _|p, 0xFFFFFFFF;\n\t"
                 "selp.b32 %0, 1, 0, p;\n\t}" : "=r"(p));
    return p;
}
__device__ __forceinline__ uint64_t mkdesc(uint32_t addr) {
    return ((uint64_t)2 << 61) | ((uint64_t)1 << 46) | ((uint64_t)64 << 32) |
           ((uint64_t)1 << 16) | ((addr >> 4) & 0x3FFF);
}
#define TC_ALLOC(sa, n) \
    asm volatile("tcgen05.alloc.cta_group::1.sync.aligned.shared::cta.b32 [%0], %1;" \
                 :: "r"(sa), "r"((uint32_t)(n)) : "memory")
#define TC_RELINQ() \
    asm volatile("tcgen05.relinquish_alloc_permit.cta_group::1.sync.aligned;")
#define TC_DEALLOC(t, n) \
    asm volatile("tcgen05.dealloc.cta_group::1.sync.aligned.b32 %0, %1;" :: "r"(t), "r"((uint32_t)(n)))
#define TC_COMMIT(mb) \
    asm volatile("tcgen05.commit.cta_group::1.mbarrier::arrive::one.shared::cluster.b64 [%0];" \
                 :: "r"(mb) : "memory")
#define TC_WAIT_ST() asm volatile("tcgen05.wait::st.sync.aligned;" ::: "memory")
#define TC_WAIT_LD() asm volatile("tcgen05.wait::ld.sync.aligned;" ::: "memory")
#define TC_FENCE_BEFORE() asm volatile("tcgen05.fence::before_thread_sync;" ::: "memory")
#define TC_FENCE_AFTER()  asm volatile("tcgen05.fence::after_thread_sync;" ::: "memory")
#define MB_INIT(mb, c) \
    asm volatile("mbarrier.init.shared.b64 [%0], %1;" :: "r"(mb), "r"((uint32_t)(c)) : "memory")
#define MB_WAIT(mb, par) do { \
    uint32_t _m = (mb), _p = (par), _d; \
    asm volatile("{\n\t.reg .pred p;\n\t" \
        "mbarrier.try_wait.parity.acquire.cta.shared::cta.b64 p, [%1], %2;\n\t" \
        "selp.b32 %0, 1, 0, p;\n\t}" : "=r"(_d) : "r"(_m), "r"(_p) : "memory"); \
    if (!_d) { \
        asm volatile("{\n\t.reg .pred P1;\n\tWL_%=:\n\t" \
            "mbarrier.try_wait.parity.acquire.cta.shared::cta.b64 P1, [%0], %1, 0x989680;\n\t" \
            "@P1 bra.uni WD_%=;\n\tbra.uni WL_%=;\n\tWD_%=:\n\t}" \
            :: "r"(_m), "r"(_p) : "memory"); \
    } } while (0)

#define TMST_X16(addr, r) \
    asm volatile("tcgen05.st.sync.aligned.32x32b.x16.b32 [%0], " \
        "{%1,%2,%3,%4,%5,%6,%7,%8,%9,%10,%11,%12,%13,%14,%15,%16};" \
        :: "r"(addr), \
        "r"((r)[0]),"r"((r)[1]),"r"((r)[2]),"r"((r)[3]),"r"((r)[4]),"r"((r)[5]),"r"((r)[6]),"r"((r)[7]), \
        "r"((r)[8]),"r"((r)[9]),"r"((r)[10]),"r"((r)[11]),"r"((r)[12]),"r"((r)[13]),"r"((r)[14]),"r"((r)[15]) \
        : "memory")
#define TMST_X8(addr, r) \
    asm volatile("tcgen05.st.sync.aligned.32x32b.x8.b32 [%0], " \
        "{%1,%2,%3,%4,%5,%6,%7,%8};" \
        :: "r"(addr), \
        "r"((r)[0]),"r"((r)[1]),"r"((r)[2]),"r"((r)[3]),"r"((r)[4]),"r"((r)[5]),"r"((r)[6]),"r"((r)[7]) \
        : "memory")
#define TMLD_X32(r, addr) \
    asm volatile("tcgen05.ld.sync.aligned.32x32b.x32.b32 " \
        "{%0,%1,%2,%3,%4,%5,%6,%7,%8,%9,%10,%11,%12,%13,%14,%15," \
        "%16,%17,%18,%19,%20,%21,%22,%23,%24,%25,%26,%27,%28,%29,%30,%31}, [%32];" \
        : "=r"((r)[0]),"=r"((r)[1]),"=r"((r)[2]),"=r"((r)[3]),"=r"((r)[4]),"=r"((r)[5]),"=r"((r)[6]),"=r"((r)[7]), \
          "=r"((r)[8]),"=r"((r)[9]),"=r"((r)[10]),"=r"((r)[11]),"=r"((r)[12]),"=r"((r)[13]),"=r"((r)[14]),"=r"((r)[15]), \
          "=r"((r)[16]),"=r"((r)[17]),"=r"((r)[18]),"=r"((r)[19]),"=r"((r)[20]),"=r"((r)[21]),"=r"((r)[22]),"=r"((r)[23]), \
          "=r"((r)[24]),"=r"((r)[25]),"=r"((r)[26]),"=r"((r)[27]),"=r"((r)[28]),"=r"((r)[29]),"=r"((r)[30]),"=r"((r)[31]) \
        : "r"(addr))

__device__ __forceinline__ void mma_f16_ts(uint32_t d, uint32_t a, uint64_t bd,
                                           uint32_t en) {
    asm volatile("{\n\t.reg .pred p;\n\tsetp.ne.u32 p, %5, 0;\n\t"
                 "tcgen05.mma.cta_group::1.kind::f16 [%0], [%1], %2, %3, "
                 "{%4, %4, %4, %4}, p;\n\t}"
                 :: "r"(d), "r"(a), "l"(bd), "r"(IDESC), "r"(0u), "r"(en)
                 : "memory");
}
#endif  // HAS_TC

// ---------------------------------------------------------------------------
__global__ void detect_idx_kernel(const unsigned int* __restrict__ w) {
    unsigned int acc = 0;
#pragma unroll
    for (int i = 1; i < 256; i += 2) acc |= w[i];
    g_is64 = (acc == 0) ? 1 : 0;
}

// ---------------------------------------------------------------------------
__global__ void prep_w_kernel(const float* __restrict__ W1,
                              const float* __restrict__ W2,
                              const float* __restrict__ W3) {
    int stride = blockDim.x * gridDim.x;
    int t0 = blockIdx.x * blockDim.x + threadIdx.x;
    for (int i = t0; i < 64 * 128; i += stride) {
        int n = i >> 7, k = i & 127;
        float w = 0.f;
        if (k < 64) w = W1[k * 64 + n];
        else if (k < 80) w = W1[(192 + k - 64) * 64 + n];
        uint32_t bo = ((uint32_t)(n >> 3) + ((uint32_t)(k * 2) >> 7) * 8u) * 1024u
                    + (uint32_t)(n & 7) * 128u + ((uint32_t)(k * 2) & 127u);
        uint32_t sw = bo ^ ((bo >> 3) & 0x70);
        __nv_bfloat16 hi = __float2bfloat16(w);
        __nv_bfloat16 lo = __float2bfloat16(w - __bfloat162float(hi));
        *(__nv_bfloat16*)(g_wimg + WI_B1H + sw) = hi;
        *(__nv_bfloat16*)(g_wimg + WI_B1L + sw) = lo;
    }
    for (int i = t0; i < 64 * 64; i += stride) {
        int n = i >> 6, k = i & 63;
        uint32_t bo = (uint32_t)(n >> 3) * 1024u + (uint32_t)(n & 7) * 128u
                    + (uint32_t)(k * 2);
        uint32_t sw = bo ^ ((bo >> 3) & 0x70);
        float w2 = W2[k * 64 + n];
        __nv_bfloat16 h2 = __float2bfloat16(w2);
        *(__nv_bfloat16*)(g_wimg + WI_B2H + sw) = h2;
        *(__nv_bfloat16*)(g_wimg + WI_B2L + sw) =
            __float2bfloat16(w2 - __bfloat162float(h2));
        float w3 = W3[k * 64 + n];
        __nv_bfloat16 h3 = __float2bfloat16(w3);
        *(__nv_bfloat16*)(g_wimg + WI_B3H + sw) = h3;
        *(__nv_bfloat16*)(g_wimg + WI_B3L + sw) =
            __float2bfloat16(w3 - __bfloat162float(h3));
    }
}

// ---------------------------------------------------------------------------
// Kernel A: per-node projections (fp32 compute, fp16 storage)
// ---------------------------------------------------------------------------
__global__ void __launch_bounds__(256) node_proj_kernel(
    const float* __restrict__ nf, const float* __restrict__ W1, int N)
{
    __shared__ float Wn[64 * 128];
    __shared__ float nfs[16 * 65];
    int tid = threadIdx.x;
    for (int i = tid; i < 64 * 128; i += 256) {
        int d = i >> 7, jj = i & 127;
        Wn[i] = (jj < 64) ? W1[(64 + d) * 64 + jj]
                          : W1[(128 + d) * 64 + (jj - 64)];
    }
    int n0 = blockIdx.x * 16;
    for (int i = tid; i < 16 * 64; i += 256) {
        int nl = i >> 6, d = i & 63;
        int n = n0 + nl;
        nfs[nl * 65 + d] = (n < N) ? nf[(size_t)n * 64 + d] : 0.f;
    }
    __syncthreads();
    int nl = tid & 15;
    int j0 = (tid >> 4) * 8;
    float acc[8] = {0.f, 0.f, 0.f, 0.f, 0.f, 0.f, 0.f, 0.f};
#pragma unroll 4
    for (int d = 0; d < 64; ++d) {
        float v = nfs[nl * 65 + d];
        const float4* w = (const float4*)(Wn + d * 128 + j0);
        float4 w0 = w[0], w1 = w[1];
        acc[0] += v * w0.x; acc[1] += v * w0.y; acc[2] += v * w0.z; acc[3] += v * w0.w;
        acc[4] += v * w1.x; acc[5] += v * w1.y; acc[6] += v * w1.z; acc[7] += v * w1.w;
    }
    int n = n0 + nl;
    if (n < N) {
        __half2 p0 = __floats2half2_rn(acc[0], acc[1]);
        __half2 p1 = __floats2half2_rn(acc[2], acc[3]);
        __half2 p2 = __floats2half2_rn(acc[4], acc[5]);
        __half2 p3 = __floats2half2_rn(acc[6], acc[7]);
        uint4 u;
        u.x = *(uint32_t*)&p0; u.y = *(uint32_t*)&p1;
        u.z = *(uint32_t*)&p2; u.w = *(uint32_t*)&p3;
        *(uint4*)(g_projh + (size_t)n * 128 + j0) = u;
    }
}

// fallback per-thread GEMM K-step
__device__ __forceinline__ void gemm_step(ull* acc, float xk, const float* wrow) {
    ull xk2 = pk2(xk, xk);
    const ulonglong2* w = (const ulonglong2*)wrow;
#pragma unroll
    for (int m = 0; m < 16; ++m) {
        ulonglong2 ww = w[m];
        fma2(acc[2 * m],     xk2, ww.x);
        fma2(acc[2 * m + 1], xk2, ww.y);
    }
}

__device__ __forceinline__ void load_idx(const void* eidx_raw, int is64,
                                         long long E, long long eld,
                                         long long& nrow, long long& ncol) {
    if (is64) {
        const long long* p = (const long long*)eidx_raw;
        nrow = p[eld]; ncol = p[E + eld];
    } else {
        const int* p = (const int*)eidx_raw;
        nrow = p[eld]; ncol = p[E + eld];
    }
    if (nrow < 0) nrow = 0; if (nrow >= N_NODES_MAX) nrow = N_NODES_MAX - 1;
    if (ncol < 0) ncol = 0; if (ncol >= N_NODES_MAX) ncol = N_NODES_MAX - 1;
}

#if HAS_TC
// stage one tile: coalesced float4 loads, convert to hi/lo bf16x2, SMEM store
__device__ __forceinline__ void stage_tile_tc(
    uint32_t* __restrict__ xs, const float* __restrict__ ef,
    const float* __restrict__ rbf, long long base, long long E, int wg_tid)
{
#pragma unroll 4
    for (int i = wg_tid; i < TILE * 16; i += 128) {
        int r = i >> 4, q = i & 15;
        long long e = base + r; if (e >= E) e = E - 1;
        float4 v = ((const float4*)ef)[e * 16 + q];
        uint32_t h0 = pkbf(v.x, v.y), h1 = pkbf(v.z, v.w);
        float2 f0 = upbf(h0), f1 = upbf(h1);
        uint32_t l0 = pkbf(v.x - f0.x, v.y - f0.y);
        uint32_t l1 = pkbf(v.z - f1.x, v.w - f1.y);
        *(uint2*)&xs[r * XROW_U32 + 2 * q]      = make_uint2(h0, h1);
        *(uint2*)&xs[r * XROW_U32 + 40 + 2 * q] = make_uint2(l0, l1);
    }
#pragma unroll
    for (int i = wg_tid; i < TILE * 4; i += 128) {
        int r = i >> 2, q = i & 3;
        long long e = base + r; if (e >= E) e = E - 1;
        float4 v = ((const float4*)rbf)[e * 4 + q];
        uint32_t h0 = pkbf(v.x, v.y), h1 = pkbf(v.z, v.w);
        float2 f0 = upbf(h0), f1 = upbf(h1);
        uint32_t l0 = pkbf(v.x - f0.x, v.y - f0.y);
        uint32_t l1 = pkbf(v.z - f1.x, v.w - f1.y);
        *(uint2*)&xs[r * XROW_U32 + 32 + 2 * q] = make_uint2(h0, h1);
        *(uint2*)&xs[r * XROW_U32 + 72 + 2 * q] = make_uint2(l0, l1);
    }
}
#endif

// ---------------------------------------------------------------------------
// Kernel B: persistent edge MLP. 384 threads = 3 warpgroup pipelines.
// ---------------------------------------------------------------------------
__global__ void __launch_bounds__(384) edge_tc_kernel(
    const float* __restrict__ ef, const void* __restrict__ eidx_raw,
    const float* __restrict__ rbf,
    const float* __restrict__ W1, const float* __restrict__ W2,
    const float* __restrict__ W3,
    const float* __restrict__ b1, const float* __restrict__ b2,
    const float* __restrict__ b3, const float* __restrict__ gamma,
    const float* __restrict__ beta, float* __restrict__ out,
    int E, int ntiles)
{
    extern __shared__ __align__(1024) unsigned char smraw[];
    float* smf = (float*)smraw;
    int tid = threadIdx.x;
    int wg = tid >> 7;                 // 0..2
    int wg_tid = tid & 127;
    int warp_in_wg = (tid >> 5) & 3;
    int is64 = g_is64;
    long long pipes = (long long)gridDim.x * 3;

    if (tid < 64) {
        smf[SM_B1V / 4 + tid] = b1[tid];
        smf[SM_B2V / 4 + tid] = b2[tid];
        smf[SM_B3V / 4 + tid] = b3[tid];
        smf[SM_GV / 4 + tid]  = gamma[tid];
        smf[SM_BTV / 4 + tid] = beta[tid];
    }

#if HAS_TC
    uint32_t smb = smem_u32(smraw);
    {
        const float4* src = (const float4*)g_wimg;
        float4* dst = (float4*)(smraw + SM_W);
        for (int i = tid; i < 65536 / 16; i += 384) dst[i] = src[i];
    }
    if (tid == 0) {
        MB_INIT(smb + SM_MBAR, 1);
        MB_INIT(smb + SM_MBAR + 8, 1);
        MB_INIT(smb + SM_MBAR + 16, 1);
    }
    if ((tid >> 5) == 0) {
        TC_ALLOC(smb + SM_PTR, 512);
        TC_RELINQ();   // persistent CTA must not hold the alloc permit
    }
    __syncthreads();
    uint32_t tm;
    asm("ld.shared.b32 %0, [%1];" : "=r"(tm) : "r"(smb + SM_PTR));
    uint32_t ts = tm + (uint32_t)wg * TM_SLOT;
    uint32_t wo = (uint32_t)warp_in_wg << 21;
    uint32_t mb = smb + SM_MBAR + (uint32_t)wg * 8;

    uint64_t d_b1h = mkdesc(smb + SM_W + WI_B1H);
    uint64_t d_b1l = mkdesc(smb + SM_W + WI_B1L);
    uint64_t d_b2h = mkdesc(smb + SM_W + WI_B2H);
    uint64_t d_b2l = mkdesc(smb + SM_W + WI_B2L);
    uint64_t d_b3h = mkdesc(smb + SM_W + WI_B3H);
    uint64_t d_b3l = mkdesc(smb + SM_W + WI_B3L);
    uint32_t ph = 0;

    uint32_t* xs = (uint32_t*)(smraw + XS_OFF(wg));
    const uint32_t* xrow = xs + wg_tid * XROW_U32;

    long long t = (long long)blockIdx.x * 3 + wg;
    long long nrow = 0, ncol = 0;

    if (t < ntiles) {
        long long base = t * TILE;
        stage_tile_tc(xs, ef, rbf, base, E, wg_tid);
        long long e0 = base + wg_tid; if (e0 >= E) e0 = E - 1;
        load_idx(eidx_raw, is64, E, e0, nrow, ncol);
        PF_L2(g_projh + nrow * 128);
        PF_L2(g_projh + ncol * 128 + 64);
    }

    for (; t < ntiles; t += pipes) {
        long long base = t * TILE;
        long long e = base + wg_tid;

        WG_BAR(wg);   // staged buffer visible to whole wg

        // ---- A to TMEM: straight copy of pre-packed hi/lo words ----
        {
            uint32_t v[16];
            const uint4* rq = (const uint4*)xrow;
#pragma unroll
            for (int j = 0; j < 4; ++j) *(uint4*)&v[4 * j] = rq[j];
            TMST_X16(ts + TM_AHI + wo, v);
#pragma unroll
            for (int j = 0; j < 4; ++j) *(uint4*)&v[4 * j] = rq[4 + j];
            TMST_X16(ts + TM_AHI + 16 + wo, v);
#pragma unroll
            for (int j = 0; j < 2; ++j) *(uint4*)&v[4 * j] = rq[8 + j];
            TMST_X8(ts + TM_AHI + 32 + wo, v);
#pragma unroll
            for (int j = 0; j < 4; ++j) *(uint4*)&v[4 * j] = rq[10 + j];
            TMST_X16(ts + TM_ALO + wo, v);
#pragma unroll
            for (int j = 0; j < 4; ++j) *(uint4*)&v[4 * j] = rq[14 + j];
            TMST_X16(ts + TM_ALO + 16 + wo, v);
#pragma unroll
            for (int j = 0; j < 2; ++j) *(uint4*)&v[4 * j] = rq[18 + j];
            TMST_X8(ts + TM_ALO + 32 + wo, v);
        }
        TC_WAIT_ST();
        TC_FENCE_BEFORE();
        WG_BAR(wg);

        // ---- layer 1 MMAs: 3 terms x 5 K-steps (K=80) ----
        if (warp_in_wg == 0 && elect_one()) {
            TC_FENCE_AFTER();
            const int doff1[5] = {0, 2, 4, 6, 512};
#pragma unroll
            for (int s = 0; s < 5; ++s)
                mma_f16_ts(ts + TM_D, ts + TM_AHI + s * 8, d_b1h + doff1[s], s > 0);
#pragma unroll
            for (int s = 0; s < 5; ++s)
                mma_f16_ts(ts + TM_D, ts + TM_ALO + s * 8, d_b1h + doff1[s], 1);
#pragma unroll
            for (int s = 0; s < 5; ++s)
                mma_f16_ts(ts + TM_D, ts + TM_AHI + s * 8, d_b1l + doff1[s], 1);
            TC_COMMIT(mb);
        }

        // ---- overlap: next tile's indices + proj prefetch ----
        long long nrow2 = 0, ncol2 = 0;
        long long tn = t + pipes;
        if (tn < ntiles) {
            long long en0 = tn * TILE + wg_tid; if (en0 >= E) en0 = E - 1;
            load_idx(eidx_raw, is64, E, en0, nrow2, ncol2);
            PF_L2(g_projh + nrow2 * 128);
            PF_L2(g_projh + ncol2 * 128 + 64);
        }

        MB_WAIT(mb, ph); ph ^= 1;
        TC_FENCE_AFTER();

        // ---- epilogue 1: h = silu(d + b1 + proj_i + proj_j), fp16 proj ----
        {
            const uint4* pI4 = (const uint4*)(g_projh + nrow * 128);
            const uint4* pJ4 = (const uint4*)(g_projh + ncol * 128 + 64);
            const float4* Bv = (const float4*)(smraw + SM_B1V);
#pragma unroll
            for (int half = 0; half < 2; ++half) {
                uint32_t dr[32];
                TMLD_X32(dr, ts + TM_D + half * 32 + wo);
                uint32_t wi[16], wj[16];
#pragma unroll
                for (int j = 0; j < 4; ++j) {
                    *(uint4*)&wi[4 * j] = pI4[4 * half + j];
                    *(uint4*)&wj[4 * j] = pJ4[4 * half + j];
                }
                TC_WAIT_LD();
                uint32_t hh[16], hl[16];
#pragma unroll
                for (int q = 0; q < 8; ++q) {
                    int qq = half * 8 + q;
                    float2 piA = uph(wi[2 * q]), piB = uph(wi[2 * q + 1]);
                    float2 pjA = uph(wj[2 * q]), pjB = uph(wj[2 * q + 1]);
                    float4 bb = Bv[qq];
                    float v0 = silu_f(__uint_as_float(dr[4 * q + 0]) + bb.x + piA.x + pjA.x);
                    float v1 = silu_f(__uint_as_float(dr[4 * q + 1]) + bb.y + piA.y + pjA.y);
                    float v2 = silu_f(__uint_as_float(dr[4 * q + 2]) + bb.z + piB.x + pjB.x);
                    float v3 = silu_f(__uint_as_float(dr[4 * q + 3]) + bb.w + piB.y + pjB.y);
                    uint32_t p0 = pkbf(v0, v1), p1 = pkbf(v2, v3);
                    float2 f0 = upbf(p0), f1 = upbf(p1);
                    hh[2 * q] = p0; hh[2 * q + 1] = p1;
                    hl[2 * q]     = pkbf(v0 - f0.x, v1 - f0.y);
                    hl[2 * q + 1] = pkbf(v2 - f1.x, v3 - f1.y);
                }
                TMST_X16(ts + TM_AHI + half * 16 + wo, hh);
                TMST_X16(ts + TM_ALO + half * 16 + wo, hl);
            }
        }
        TC_WAIT_ST();
        TC_FENCE_BEFORE();
        WG_BAR(wg);

        // ---- layer 2 MMAs ----
        if (warp_in_wg == 0 && elect_one()) {
            TC_FENCE_AFTER();
#pragma unroll
            for (int s = 0; s < 4; ++s)
                mma_f16_ts(ts + TM_D, ts + TM_AHI + s * 8, d_b2h + s * 2, s > 0);
#pragma unroll
            for (int s = 0; s < 4; ++s)
                mma_f16_ts(ts + TM_D, ts + TM_ALO + s * 8, d_b2h + s * 2, 1);
#pragma unroll
            for (int s = 0; s < 4; ++s)
                mma_f16_ts(ts + TM_D, ts + TM_AHI + s * 8, d_b2l + s * 2, 1);
            TC_COMMIT(mb);
        }
        MB_WAIT(mb, ph); ph ^= 1;
        TC_FENCE_AFTER();

        // ---- epilogue 2: h = silu(d + b2) ----
        {
            const float4* Bv = (const float4*)(smraw + SM_B2V);
#pragma unroll
            for (int half = 0; half < 2; ++half) {
                uint32_t dr[32];
                TMLD_X32(dr, ts + TM_D + half * 32 + wo);
                TC_WAIT_LD();
                uint32_t hh[16], hl[16];
#pragma unroll
                for (int q = 0; q < 8; ++q) {
                    int qq = half * 8 + q;
                    float4 bb = Bv[qq];
                    float v0 = silu_f(__uint_as_float(dr[4 * q + 0]) + bb.x);
                    float v1 = silu_f(__uint_as_float(dr[4 * q + 1]) + bb.y);
                    float v2 = silu_f(__uint_as_float(dr[4 * q + 2]) + bb.z);
                    float v3 = silu_f(__uint_as_float(dr[4 * q + 3]) + bb.w);
                    uint32_t p0 = pkbf(v0, v1), p1 = pkbf(v2, v3);
                    float2 f0 = upbf(p0), f1 = upbf(p1);
                    hh[2 * q] = p0; hh[2 * q + 1] = p1;
                    hl[2 * q]     = pkbf(v0 - f0.x, v1 - f0.y);
                    hl[2 * q + 1] = pkbf(v2 - f1.x, v3 - f1.y);
                }
                TMST_X16(ts + TM_AHI + half * 16 + wo, hh);
                TMST_X16(ts + TM_ALO + half * 16 + wo, hl);
            }
        }
        TC_WAIT_ST();
        TC_FENCE_BEFORE();
        WG_BAR(wg);

        // ---- layer 3 MMAs ----
        if (warp_in_wg == 0 && elect_one()) {
            TC_FENCE_AFTER();
#pragma unroll
            for (int s = 0; s < 4; ++s)
                mma_f16_ts(ts + TM_D, ts + TM_AHI + s * 8, d_b3h + s * 2, s > 0);
#pragma unroll
            for (int s = 0; s < 4; ++s)
                mma_f16_ts(ts + TM_D, ts + TM_ALO + s * 8, d_b3h + s * 2, 1);
#pragma unroll
            for (int s = 0; s < 4; ++s)
                mma_f16_ts(ts + TM_D, ts + TM_AHI + s * 8, d_b3l + s * 2, 1);
            TC_COMMIT(mb);
        }
        MB_WAIT(mb, ph); ph ^= 1;
        TC_FENCE_AFTER();

        // ---- final: y = (hi+lo) + d + b3; LayerNorm; SMEM bounce store ----
        {
            const float4* Bv = (const float4*)(smraw + SM_B3V);
            float y[64];
            float s1 = 0.f, s2 = 0.f;
#pragma unroll
            for (int half = 0; half < 2; ++half) {
                uint32_t dr[32];
                TMLD_X32(dr, ts + TM_D + half * 32 + wo);
                TC_WAIT_LD();
                const uint4* xh = (const uint4*)(xrow) + half * 4;        // ef-hi
                const uint4* xl = (const uint4*)(xrow + 40) + half * 4;   // ef-lo
#pragma unroll
                for (int j = 0; j < 4; ++j) {
                    uint4 hq = xh[j], lq = xl[j];
                    const uint32_t hw[4] = {hq.x, hq.y, hq.z, hq.w};
                    const uint32_t lw[4] = {lq.x, lq.y, lq.z, lq.w};
#pragma unroll
                    for (int p = 0; p < 4; ++p) {
                        float2 xh2 = upbf(hw[p]), xl2 = upbf(lw[p]);
                        int d0 = j * 8 + 2 * p;
                        int o0 = half * 32 + d0;
                        float4 bb = Bv[o0 >> 2];
                        float bbv0 = (o0 & 2) ? bb.z : bb.x;
                        float bbv1 = (o0 & 2) ? bb.w : bb.y;
                        float v0 = xh2.x + xl2.x + __uint_as_float(dr[d0])     + bbv0;
                        float v1 = xh2.y + xl2.y + __uint_as_float(dr[d0 + 1]) + bbv1;
                        y[o0] = v0; y[o0 + 1] = v1;
                        s1 += v0 + v1;
                        s2 += v0 * v0 + v1 * v1;
                    }
                }
            }
            float mu  = s1 * (1.f / 64.f);
            float var = s2 * (1.f / 64.f) - mu * mu;
            float inv = rsqrtf(var + 1e-5f);
            // normalized y into own SMEM row (only self reads that row)
            {
                const float4* Gv = (const float4*)(smraw + SM_GV);
                const float4* Tv = (const float4*)(smraw + SM_BTV);
                float4* yrow = (float4*)(xs + wg_tid * XROW_U32);
#pragma unroll
                for (int q = 0; q < 16; ++q) {
                    float4 g4 = Gv[q], t4 = Tv[q], r4;
                    r4.x = (y[4 * q + 0] - mu) * inv * g4.x + t4.x;
                    r4.y = (y[4 * q + 1] - mu) * inv * g4.y + t4.y;
                    r4.z = (y[4 * q + 2] - mu) * inv * g4.z + t4.z;
                    r4.w = (y[4 * q + 3] - mu) * inv * g4.w + t4.w;
                    yrow[q] = r4;
                }
            }
        }
        WG_BAR(wg);   // all y rows in SMEM

        // ---- coalesced output store ----
#pragma unroll 4
        for (int i = wg_tid; i < TILE * 16; i += 128) {
            int r = i >> 4, q = i & 15;
            long long eo = base + r;
            if (eo < E)
                ((float4*)out)[eo * 16 + q] = *(const float4*)&xs[r * XROW_U32 + 4 * q];
        }

        WG_BAR(wg);   // buffer free before restage

        if (tn < ntiles)
            stage_tile_tc(xs, ef, rbf, tn * TILE, E, wg_tid);
        nrow = nrow2; ncol = ncol2;
    }
    __syncthreads();
    if ((tid >> 5) == 0) TC_DEALLOC(tm, 512);

#else  // ================= fp32 f32x2 fallback (non-arch-specific pass) =====

    float* wsm = smf + SM_W / 4;
    for (int i = tid; i < 64 * 64; i += 384) wsm[FB_W1E + i] = W1[i];
    for (int i = tid; i < 16 * 64; i += 384) wsm[FB_W1R + i] = W1[192 * 64 + i];
    for (int i = tid; i < 64 * 64; i += 384) wsm[FB_W2 + i] = W2[i];
    for (int i = tid; i < 64 * 64; i += 384) wsm[FB_W3 + i] = W3[i];
    __syncthreads();

    float* xs = (float*)(smraw + XS_OFF(wg));
    for (long long t = (long long)blockIdx.x * 3 + wg; t < ntiles; t += pipes) {
        long long base = t * TILE;
        WG_BAR(wg);
        for (int i = wg_tid; i < TILE * 16; i += 128) {
            int r = i >> 4, q = i & 15;
            long long e = base + r; if (e >= E) e = E - 1;
            *(float4*)&xs[r * XROW_U32 + q * 4] = ((const float4*)ef)[e * 16 + q];
        }
        for (int i = wg_tid; i < TILE * 4; i += 128) {
            int r = i >> 2, q = i & 3;
            long long e = base + r; if (e >= E) e = E - 1;
            *(float4*)&xs[r * XROW_U32 + 64 + q * 4] = ((const float4*)rbf)[e * 4 + q];
        }
        WG_BAR(wg);

        long long e = base + wg_tid;
        long long eld = (e < E) ? e : (long long)(E - 1);
        long long nrow, ncol;
        load_idx(eidx_raw, is64, E, eld, nrow, ncol);

        const __half2* pIh = (const __half2*)(g_projh + nrow * 128);
        const __half2* pJh = (const __half2*)(g_projh + ncol * 128 + 64);
        const float* xr = xs + wg_tid * XROW_U32;

        ull acc[32];
#pragma unroll
        for (int m = 0; m < 16; ++m) {
            float4 bb = ((const float4*)(smraw + SM_B1V))[m];
            float2 a01 = __half22float2(pIh[2 * m]);
            float2 a23 = __half22float2(pIh[2 * m + 1]);
            float2 b01 = __half22float2(pJh[2 * m]);
            float2 b23 = __half22float2(pJh[2 * m + 1]);
            acc[2 * m]     = pk2(bb.x + a01.x + b01.x, bb.y + a01.y + b01.y);
            acc[2 * m + 1] = pk2(bb.z + a23.x + b23.x, bb.w + a23.y + b23.y);
        }
#pragma unroll
        for (int k = 0; k < 64; ++k) gemm_step(acc, xr[k], wsm + FB_W1E + k * 64);
#pragma unroll
        for (int k = 0; k < 16; ++k) gemm_step(acc, xr[64 + k], wsm + FB_W1R + k * 64);

        float h[64];
#pragma unroll
        for (int p = 0; p < 32; ++p) {
            float a, b; upk2(acc[p], a, b);
            h[2 * p] = silu_f(a); h[2 * p + 1] = silu_f(b);
        }
#pragma unroll
        for (int m = 0; m < 16; ++m) {
            float4 bb = ((const float4*)(smraw + SM_B2V))[m];
            acc[2 * m] = pk2(bb.x, bb.y); acc[2 * m + 1] = pk2(bb.z, bb.w);
        }
#pragma unroll
        for (int k = 0; k < 64; ++k) gemm_step(acc, h[k], wsm + FB_W2 + k * 64);
#pragma unroll
        for (int p = 0; p < 32; ++p) {
            float a, b; upk2(acc[p], a, b);
            h[2 * p] = silu_f(a); h[2 * p + 1] = silu_f(b);
        }
#pragma unroll
        for (int m = 0; m < 16; ++m) {
            float4 bb = ((const float4*)(smraw + SM_B3V))[m];
            acc[2 * m] = pk2(bb.x, bb.y); acc[2 * m + 1] = pk2(bb.z, bb.w);
        }
#pragma unroll
        for (int k = 0; k < 64; ++k) gemm_step(acc, h[k], wsm + FB_W3 + k * 64);

        float y[64];
        float s1 = 0.f, s2 = 0.f;
#pragma unroll
        for (int p = 0; p < 32; ++p) {
            float a, b; upk2(acc[p], a, b);
            float ya = xr[2 * p] + a, yb = xr[2 * p + 1] + b;
            y[2 * p] = ya; y[2 * p + 1] = yb;
            s1 += ya + yb; s2 += ya * ya + yb * yb;
        }
        float mu  = s1 * (1.f / 64.f);
        float var = s2 * (1.f / 64.f) - mu * mu;
        float inv = rsqrtf(var + 1e-5f);
        if (e < E) {
            float4* o = (float4*)(out + e * 64);
#pragma unroll
            for (int q = 0; q < 16; ++q) {
                float4 g4 = ((const float4*)(smraw + SM_GV))[q];
                float4 t4 = ((const float4*)(smraw + SM_BTV))[q];
                float4 r4;
                r4.x = (y[4 * q + 0] - mu) * inv * g4.x + t4.x;
                r4.y = (y[4 * q + 1] - mu) * inv * g4.y + t4.y;
                r4.z = (y[4 * q + 2] - mu) * inv * g4.z + t4.z;
                r4.w = (y[4 * q + 3] - mu) * inv * g4.w + t4.w;
                o[q] = r4;
            }
        }
        WG_BAR(wg);
    }
#endif
}

// ---------------------------------------------------------------------------
extern "C" void kernel_launch(void* const* d_in, const int* in_sizes, int n_in,
                              void* d_out, int out_size) {
    const float* ef   = (const float*)d_in[0];
    const float* nf   = (const float*)d_in[1];
    const void*  eidx = (const void*)d_in[2];
    const float* rbf  = (const float*)d_in[3];
    const float* W1   = (const float*)d_in[4];
    const float* b1   = (const float*)d_in[5];
    const float* W2   = (const float*)d_in[6];
    const float* b2   = (const float*)d_in[7];
    const float* W3   = (const float*)d_in[8];
    const float* b3   = (const float*)d_in[9];
    const float* gam  = (const float*)d_in[10];
    const float* bet  = (const float*)d_in[11];
    float* out = (float*)d_out;

    int E = in_sizes[0] / 64;
    int N = in_sizes[1] / 64;
    if (N > N_NODES_MAX) N = N_NODES_MAX;

    detect_idx_kernel<<<1, 1>>>((const unsigned int*)eidx);
    prep_w_kernel<<<32, 256>>>(W1, W2, W3);
    node_proj_kernel<<<(N + 15) / 16, 256>>>(nf, W1, N);

    int ntiles = (E + TILE - 1) / TILE;
    int grid = 148;
    if (grid > (ntiles + 2) / 3) grid = (ntiles + 2) / 3;
    if (grid < 1) grid = 1;
    cudaFuncSetAttribute(edge_tc_kernel,
                         cudaFuncAttributeMaxDynamicSharedMemorySize, SMEM_BYTES);
    edge_tc_kernel<<<grid, 384, SMEM_BYTES>>>(
        ef, eidx, rbf, W1, W2, W3, b1, b2, b3, gam, bet, out, E, ntiles);
}

// round 16
// speedup vs baseline: 5.1081x; 1.0424x over previous
#include <cuda_runtime.h>
#include <cuda_bf16.h>
#include <cuda_fp16.h>
#include <stdint.h>

// ============================================================================
// AllegroLayer edge-MLP (sm_103a).
//
// tcgen05 path (arch-specific pass) + fp32 f32x2 fallback (plain compute_103).
//
// R13 (resubmitted after infra failure in R15 — no code change):
//  - layers 2/3: h in single fp16, W2/W3 as fp16 hi+lo -> 2 MMA terms (was 3),
//    epilogues lose the lo-split chain, STTM halves.
//  - layer 1 unchanged (split bf16; x precision feeds the residual).
//  - 32-bit indexing in the hot loop.
//  - (kept) 3 wg pipelines, convert-at-staging, stride-84 rows, fp16 proj,
//    SMEM-bounce coalesced output.
// ============================================================================

#if defined(__CUDA_ARCH_FEAT_SM103_ALL) || \
    (defined(__CUDA_ARCH_SPECIFIC__) && defined(__CUDA_ARCH__) && (__CUDA_ARCH__ == 1030))
#define HAS_TC 1
#else
#define HAS_TC 0
#endif

#define N_NODES_MAX 50048
#define TILE 128
#define IDESC_BF 0x8100490u   // kind::f16: F32 acc, BF16 a/b, N=64, M=128
#define IDESC_FP 0x8100010u   // kind::f16: F32 acc, F16 a/b,  N=64, M=128

__device__ __half g_projh[(size_t)N_NODES_MAX * 128];
__device__ int g_is64;
__device__ __align__(16) unsigned char g_wimg[65536];

#define WI_B1H 0
#define WI_B1L 16384
#define WI_B2H 32768
#define WI_B2L 40960
#define WI_B3H 49152
#define WI_B3L 57344

// SMEM layout (bytes)
#define SM_W     0
#define XROW_U32 84
#define XBUF_B   (TILE * XROW_U32 * 4)
#define SM_XS    65536
#define XS_OFF(wg) (SM_XS + (wg) * XBUF_B)
#define SM_VEC   (SM_XS + 3 * XBUF_B)
#define SM_B1V   SM_VEC
#define SM_B2V   (SM_VEC + 256)
#define SM_B3V   (SM_VEC + 512)
#define SM_GV    (SM_VEC + 768)
#define SM_BTV   (SM_VEC + 1024)
#define SM_PTR   (SM_VEC + 1280)
#define SM_MBAR  (SM_VEC + 1288)
#define SMEM_BYTES (SM_VEC + 1312)

// fallback fp32 weights (floats, within SM_W)
#define FB_W1E  0
#define FB_W1R  (64 * 64)
#define FB_W2   (FB_W1R + 16 * 64)
#define FB_W3   (FB_W2 + 64 * 64)

// TMEM per-wg slot (base = wg*160)
#define TM_SLOT 160
#define TM_AHI 0
#define TM_ALO 48
#define TM_D   96

typedef unsigned long long ull;

// ---------------------------------------------------------------------------
__device__ __forceinline__ uint32_t smem_u32(const void* p) {
    uint32_t a;
    asm("{ .reg .u64 t; cvta.to.shared.u64 t, %1; cvt.u32.u64 %0, t; }"
        : "=r"(a) : "l"(p));
    return a;
}
__device__ __forceinline__ uint32_t pkbf(float a, float b) {
    __nv_bfloat162 t = __floats2bfloat162_rn(a, b);
    return *(uint32_t*)&t;
}
__device__ __forceinline__ uint32_t pkh(float a, float b) {
    __half2 t = __floats2half2_rn(a, b);
    return *(uint32_t*)&t;
}
__device__ __forceinline__ float2 upbf(uint32_t p) {
    __nv_bfloat162 h = *(__nv_bfloat162*)&p;
    return make_float2(__bfloat162float(h.x), __bfloat162float(h.y));
}
__device__ __forceinline__ float2 uph(uint32_t p) {
    __half2 h = *(__half2*)&p;
    return __half22float2(h);
}
__device__ __forceinline__ float silu_f(float x) {
    float h = 0.5f * x, t;
    asm("tanh.approx.f32 %0, %1;" : "=f"(t) : "f"(h));
    return h + h * t;
}
__device__ __forceinline__ ull pk2(float lo, float hi) {
    ull r;
    asm("mov.b64 %0, {%1, %2};" : "=l"(r) : "f"(lo), "f"(hi));
    return r;
}
__device__ __forceinline__ void upk2(ull v, float& lo, float& hi) {
    asm("mov.b64 {%0, %1}, %2;" : "=f"(lo), "=f"(hi) : "l"(v));
}
__device__ __forceinline__ void fma2(ull& d, ull a, ull b) {
    asm("fma.rn.f32x2 %0, %1, %2, %0;" : "+l"(d) : "l"(a), "l"(b));
}
#define PF_L2(p) asm volatile("prefetch.global.L2 [%0];" :: "l"(p))
#define WG_BAR(wg) asm volatile("bar.sync %0, 128;" :: "r"((wg) + 1) : "memory")

#if HAS_TC
__device__ __forceinline__ uint32_t elect_one() {
    uint32_t p;
    asm volatile("{\n\t.reg .pred p;\n\telect.sync _|p, 0xFFFFFFFF;\n\t"
                 "selp.b32 %0, 1, 0, p;\n\t}" : "=r"(p));
    return p;
}
__device__ __forceinline__ uint64_t mkdesc(uint32_t addr) {
    return ((uint64_t)2 << 61) | ((uint64_t)1 << 46) | ((uint64_t)64 << 32) |
           ((uint64_t)1 << 16) | ((addr >> 4) & 0x3FFF);
}
#define TC_ALLOC(sa, n) \
    asm volatile("tcgen05.alloc.cta_group::1.sync.aligned.shared::cta.b32 [%0], %1;" \
                 :: "r"(sa), "r"((uint32_t)(n)) : "memory")
#define TC_RELINQ() \
    asm volatile("tcgen05.relinquish_alloc_permit.cta_group::1.sync.aligned;")
#define TC_DEALLOC(t, n) \
    asm volatile("tcgen05.dealloc.cta_group::1.sync.aligned.b32 %0, %1;" :: "r"(t), "r"((uint32_t)(n)))
#define TC_COMMIT(mb) \
    asm volatile("tcgen05.commit.cta_group::1.mbarrier::arrive::one.shared::cluster.b64 [%0];" \
                 :: "r"(mb) : "memory")
#define TC_WAIT_ST() asm volatile("tcgen05.wait::st.sync.aligned;" ::: "memory")
#define TC_WAIT_LD() asm volatile("tcgen05.wait::ld.sync.aligned;" ::: "memory")
#define TC_FENCE_BEFORE() asm volatile("tcgen05.fence::before_thread_sync;" ::: "memory")
#define TC_FENCE_AFTER()  asm volatile("tcgen05.fence::after_thread_sync;" ::: "memory")
#define MB_INIT(mb, c) \
    asm volatile("mbarrier.init.shared.b64 [%0], %1;" :: "r"(mb), "r"((uint32_t)(c)) : "memory")
#define MB_WAIT(mb, par) do { \
    uint32_t _m = (mb), _p = (par), _d; \
    asm volatile("{\n\t.reg .pred p;\n\t" \
        "mbarrier.try_wait.parity.acquire.cta.shared::cta.b64 p, [%1], %2;\n\t" \
        "selp.b32 %0, 1, 0, p;\n\t}" : "=r"(_d) : "r"(_m), "r"(_p) : "memory"); \
    if (!_d) { \
        asm volatile("{\n\t.reg .pred P1;\n\tWL_%=:\n\t" \
            "mbarrier.try_wait.parity.acquire.cta.shared::cta.b64 P1, [%0], %1, 0x989680;\n\t" \
            "@P1 bra.uni WD_%=;\n\tbra.uni WL_%=;\n\tWD_%=:\n\t}" \
            :: "r"(_m), "r"(_p) : "memory"); \
    } } while (0)

#define TMST_X16(addr, r) \
    asm volatile("tcgen05.st.sync.aligned.32x32b.x16.b32 [%0], " \
        "{%1,%2,%3,%4,%5,%6,%7,%8,%9,%10,%11,%12,%13,%14,%15,%16};" \
        :: "r"(addr), \
        "r"((r)[0]),"r"((r)[1]),"r"((r)[2]),"r"((r)[3]),"r"((r)[4]),"r"((r)[5]),"r"((r)[6]),"r"((r)[7]), \
        "r"((r)[8]),"r"((r)[9]),"r"((r)[10]),"r"((r)[11]),"r"((r)[12]),"r"((r)[13]),"r"((r)[14]),"r"((r)[15]) \
        : "memory")
#define TMST_X8(addr, r) \
    asm volatile("tcgen05.st.sync.aligned.32x32b.x8.b32 [%0], " \
        "{%1,%2,%3,%4,%5,%6,%7,%8};" \
        :: "r"(addr), \
        "r"((r)[0]),"r"((r)[1]),"r"((r)[2]),"r"((r)[3]),"r"((r)[4]),"r"((r)[5]),"r"((r)[6]),"r"((r)[7]) \
        : "memory")
#define TMLD_X32(r, addr) \
    asm volatile("tcgen05.ld.sync.aligned.32x32b.x32.b32 " \
        "{%0,%1,%2,%3,%4,%5,%6,%7,%8,%9,%10,%11,%12,%13,%14,%15," \
        "%16,%17,%18,%19,%20,%21,%22,%23,%24,%25,%26,%27,%28,%29,%30,%31}, [%32];" \
        : "=r"((r)[0]),"=r"((r)[1]),"=r"((r)[2]),"=r"((r)[3]),"=r"((r)[4]),"=r"((r)[5]),"=r"((r)[6]),"=r"((r)[7]), \
          "=r"((r)[8]),"=r"((r)[9]),"=r"((r)[10]),"=r"((r)[11]),"=r"((r)[12]),"=r"((r)[13]),"=r"((r)[14]),"=r"((r)[15]), \
          "=r"((r)[16]),"=r"((r)[17]),"=r"((r)[18]),"=r"((r)[19]),"=r"((r)[20]),"=r"((r)[21]),"=r"((r)[22]),"=r"((r)[23]), \
          "=r"((r)[24]),"=r"((r)[25]),"=r"((r)[26]),"=r"((r)[27]),"=r"((r)[28]),"=r"((r)[29]),"=r"((r)[30]),"=r"((r)[31]) \
        : "r"(addr))

__device__ __forceinline__ void mma_ts(uint32_t d, uint32_t a, uint64_t bd,
                                       uint32_t idesc, uint32_t en) {
    asm volatile("{\n\t.reg .pred p;\n\tsetp.ne.u32 p, %5, 0;\n\t"
                 "tcgen05.mma.cta_group::1.kind::f16 [%0], [%1], %2, %3, "
                 "{%4, %4, %4, %4}, p;\n\t}"
                 :: "r"(d), "r"(a), "l"(bd), "r"(idesc), "r"(0u), "r"(en)
                 : "memory");
}
#endif  // HAS_TC

// ---------------------------------------------------------------------------
__global__ void detect_idx_kernel(const unsigned int* __restrict__ w) {
    unsigned int acc = 0;
#pragma unroll
    for (int i = 1; i < 256; i += 2) acc |= w[i];
    g_is64 = (acc == 0) ? 1 : 0;
}

// ---------------------------------------------------------------------------
// Kernel P: weight images. Layer1: split bf16 hi/lo. Layers 2/3: fp16 hi/lo.
// ---------------------------------------------------------------------------
__global__ void prep_w_kernel(const float* __restrict__ W1,
                              const float* __restrict__ W2,
                              const float* __restrict__ W3) {
    int stride = blockDim.x * gridDim.x;
    int t0 = blockIdx.x * blockDim.x + threadIdx.x;
    for (int i = t0; i < 64 * 128; i += stride) {
        int n = i >> 7, k = i & 127;
        float w = 0.f;
        if (k < 64) w = W1[k * 64 + n];
        else if (k < 80) w = W1[(192 + k - 64) * 64 + n];
        uint32_t bo = ((uint32_t)(n >> 3) + ((uint32_t)(k * 2) >> 7) * 8u) * 1024u
                    + (uint32_t)(n & 7) * 128u + ((uint32_t)(k * 2) & 127u);
        uint32_t sw = bo ^ ((bo >> 3) & 0x70);
        __nv_bfloat16 hi = __float2bfloat16(w);
        __nv_bfloat16 lo = __float2bfloat16(w - __bfloat162float(hi));
        *(__nv_bfloat16*)(g_wimg + WI_B1H + sw) = hi;
        *(__nv_bfloat16*)(g_wimg + WI_B1L + sw) = lo;
    }
    for (int i = t0; i < 64 * 64; i += stride) {
        int n = i >> 6, k = i & 63;
        uint32_t bo = (uint32_t)(n >> 3) * 1024u + (uint32_t)(n & 7) * 128u
                    + (uint32_t)(k * 2);
        uint32_t sw = bo ^ ((bo >> 3) & 0x70);
        float w2 = W2[k * 64 + n];
        __half h2 = __float2half_rn(w2);
        *(__half*)(g_wimg + WI_B2H + sw) = h2;
        *(__half*)(g_wimg + WI_B2L + sw) = __float2half_rn(w2 - __half2float(h2));
        float w3 = W3[k * 64 + n];
        __half h3 = __float2half_rn(w3);
        *(__half*)(g_wimg + WI_B3H + sw) = h3;
        *(__half*)(g_wimg + WI_B3L + sw) = __float2half_rn(w3 - __half2float(h3));
    }
}

// ---------------------------------------------------------------------------
// Kernel A: per-node projections (fp32 compute, fp16 storage)
// ---------------------------------------------------------------------------
__global__ void __launch_bounds__(256) node_proj_kernel(
    const float* __restrict__ nf, const float* __restrict__ W1, int N)
{
    __shared__ float Wn[64 * 128];
    __shared__ float nfs[16 * 65];
    int tid = threadIdx.x;
    for (int i = tid; i < 64 * 128; i += 256) {
        int d = i >> 7, jj = i & 127;
        Wn[i] = (jj < 64) ? W1[(64 + d) * 64 + jj]
                          : W1[(128 + d) * 64 + (jj - 64)];
    }
    int n0 = blockIdx.x * 16;
    for (int i = tid; i < 16 * 64; i += 256) {
        int nl = i >> 6, d = i & 63;
        int n = n0 + nl;
        nfs[nl * 65 + d] = (n < N) ? nf[(size_t)n * 64 + d] : 0.f;
    }
    __syncthreads();
    int nl = tid & 15;
    int j0 = (tid >> 4) * 8;
    float acc[8] = {0.f, 0.f, 0.f, 0.f, 0.f, 0.f, 0.f, 0.f};
#pragma unroll 4
    for (int d = 0; d < 64; ++d) {
        float v = nfs[nl * 65 + d];
        const float4* w = (const float4*)(Wn + d * 128 + j0);
        float4 w0 = w[0], w1 = w[1];
        acc[0] += v * w0.x; acc[1] += v * w0.y; acc[2] += v * w0.z; acc[3] += v * w0.w;
        acc[4] += v * w1.x; acc[5] += v * w1.y; acc[6] += v * w1.z; acc[7] += v * w1.w;
    }
    int n = n0 + nl;
    if (n < N) {
        uint4 u;
        u.x = pkh(acc[0], acc[1]); u.y = pkh(acc[2], acc[3]);
        u.z = pkh(acc[4], acc[5]); u.w = pkh(acc[6], acc[7]);
        *(uint4*)(g_projh + (size_t)n * 128 + j0) = u;
    }
}

// fallback per-thread GEMM K-step
__device__ __forceinline__ void gemm_step(ull* acc, float xk, const float* wrow) {
    ull xk2 = pk2(xk, xk);
    const ulonglong2* w = (const ulonglong2*)wrow;
#pragma unroll
    for (int m = 0; m < 16; ++m) {
        ulonglong2 ww = w[m];
        fma2(acc[2 * m],     xk2, ww.x);
        fma2(acc[2 * m + 1], xk2, ww.y);
    }
}

__device__ __forceinline__ void load_idx(const void* eidx_raw, int is64,
                                         int E, int eld,
                                         int& nrow, int& ncol) {
    long long r, c;
    if (is64) {
        const long long* p = (const long long*)eidx_raw;
        r = p[eld]; c = p[E + eld];
    } else {
        const int* p = (const int*)eidx_raw;
        r = p[eld]; c = p[E + eld];
    }
    if (r < 0) r = 0; if (r >= N_NODES_MAX) r = N_NODES_MAX - 1;
    if (c < 0) c = 0; if (c >= N_NODES_MAX) c = N_NODES_MAX - 1;
    nrow = (int)r; ncol = (int)c;
}

#if HAS_TC
// stage one tile: coalesced float4 loads, convert to hi/lo bf16x2, SMEM store
__device__ __forceinline__ void stage_tile_tc(
    uint32_t* __restrict__ xs, const float* __restrict__ ef,
    const float* __restrict__ rbf, int base, int E, int wg_tid)
{
#pragma unroll 4
    for (int i = wg_tid; i < TILE * 16; i += 128) {
        int r = i >> 4, q = i & 15;
        int e = base + r; if (e >= E) e = E - 1;
        float4 v = ((const float4*)ef)[(size_t)e * 16 + q];
        uint32_t h0 = pkbf(v.x, v.y), h1 = pkbf(v.z, v.w);
        float2 f0 = upbf(h0), f1 = upbf(h1);
        uint32_t l0 = pkbf(v.x - f0.x, v.y - f0.y);
        uint32_t l1 = pkbf(v.z - f1.x, v.w - f1.y);
        *(uint2*)&xs[r * XROW_U32 + 2 * q]      = make_uint2(h0, h1);
        *(uint2*)&xs[r * XROW_U32 + 40 + 2 * q] = make_uint2(l0, l1);
    }
#pragma unroll
    for (int i = wg_tid; i < TILE * 4; i += 128) {
        int r = i >> 2, q = i & 3;
        int e = base + r; if (e >= E) e = E - 1;
        float4 v = ((const float4*)rbf)[(size_t)e * 4 + q];
        uint32_t h0 = pkbf(v.x, v.y), h1 = pkbf(v.z, v.w);
        float2 f0 = upbf(h0), f1 = upbf(h1);
        uint32_t l0 = pkbf(v.x - f0.x, v.y - f0.y);
        uint32_t l1 = pkbf(v.z - f1.x, v.w - f1.y);
        *(uint2*)&xs[r * XROW_U32 + 32 + 2 * q] = make_uint2(h0, h1);
        *(uint2*)&xs[r * XROW_U32 + 72 + 2 * q] = make_uint2(l0, l1);
    }
}
#endif

// ---------------------------------------------------------------------------
// Kernel B: persistent edge MLP. 384 threads = 3 warpgroup pipelines.
// ---------------------------------------------------------------------------
__global__ void __launch_bounds__(384) edge_tc_kernel(
    const float* __restrict__ ef, const void* __restrict__ eidx_raw,
    const float* __restrict__ rbf,
    const float* __restrict__ W1, const float* __restrict__ W2,
    const float* __restrict__ W3,
    const float* __restrict__ b1, const float* __restrict__ b2,
    const float* __restrict__ b3, const float* __restrict__ gamma,
    const float* __restrict__ beta, float* __restrict__ out,
    int E, int ntiles)
{
    extern __shared__ __align__(1024) unsigned char smraw[];
    float* smf = (float*)smraw;
    int tid = threadIdx.x;
    int wg = tid >> 7;
    int wg_tid = tid & 127;
    int warp_in_wg = (tid >> 5) & 3;
    int is64 = g_is64;
    int pipes = gridDim.x * 3;

    if (tid < 64) {
        smf[SM_B1V / 4 + tid] = b1[tid];
        smf[SM_B2V / 4 + tid] = b2[tid];
        smf[SM_B3V / 4 + tid] = b3[tid];
        smf[SM_GV / 4 + tid]  = gamma[tid];
        smf[SM_BTV / 4 + tid] = beta[tid];
    }

#if HAS_TC
    uint32_t smb = smem_u32(smraw);
    {
        const float4* src = (const float4*)g_wimg;
        float4* dst = (float4*)(smraw + SM_W);
        for (int i = tid; i < 65536 / 16; i += 384) dst[i] = src[i];
    }
    if (tid == 0) {
        MB_INIT(smb + SM_MBAR, 1);
        MB_INIT(smb + SM_MBAR + 8, 1);
        MB_INIT(smb + SM_MBAR + 16, 1);
    }
    if ((tid >> 5) == 0) {
        TC_ALLOC(smb + SM_PTR, 512);
        TC_RELINQ();   // persistent CTA must not hold the alloc permit
    }
    __syncthreads();
    uint32_t tm;
    asm("ld.shared.b32 %0, [%1];" : "=r"(tm) : "r"(smb + SM_PTR));
    uint32_t ts = tm + (uint32_t)wg * TM_SLOT;
    uint32_t wo = (uint32_t)warp_in_wg << 21;
    uint32_t mb = smb + SM_MBAR + (uint32_t)wg * 8;

    uint64_t d_b1h = mkdesc(smb + SM_W + WI_B1H);
    uint64_t d_b1l = mkdesc(smb + SM_W + WI_B1L);
    uint64_t d_b2h = mkdesc(smb + SM_W + WI_B2H);
    uint64_t d_b2l = mkdesc(smb + SM_W + WI_B2L);
    uint64_t d_b3h = mkdesc(smb + SM_W + WI_B3H);
    uint64_t d_b3l = mkdesc(smb + SM_W + WI_B3L);
    uint32_t ph = 0;

    uint32_t* xs = (uint32_t*)(smraw + XS_OFF(wg));
    const uint32_t* xrow = xs + wg_tid * XROW_U32;

    int t = blockIdx.x * 3 + wg;
    int nrow = 0, ncol = 0;

    if (t < ntiles) {
        int base = t * TILE;
        stage_tile_tc(xs, ef, rbf, base, E, wg_tid);
        int e0 = base + wg_tid; if (e0 >= E) e0 = E - 1;
        load_idx(eidx_raw, is64, E, e0, nrow, ncol);
        PF_L2(g_projh + (size_t)nrow * 128);
        PF_L2(g_projh + (size_t)ncol * 128 + 64);
    }

    for (; t < ntiles; t += pipes) {
        int base = t * TILE;
        int e = base + wg_tid;

        WG_BAR(wg);   // staged buffer visible to whole wg

        // ---- A to TMEM: straight copy of pre-packed hi/lo words ----
        {
            uint32_t v[16];
            const uint4* rq = (const uint4*)xrow;
#pragma unroll
            for (int j = 0; j < 4; ++j) *(uint4*)&v[4 * j] = rq[j];
            TMST_X16(ts + TM_AHI + wo, v);
#pragma unroll
            for (int j = 0; j < 4; ++j) *(uint4*)&v[4 * j] = rq[4 + j];
            TMST_X16(ts + TM_AHI + 16 + wo, v);
#pragma unroll
            for (int j = 0; j < 2; ++j) *(uint4*)&v[4 * j] = rq[8 + j];
            TMST_X8(ts + TM_AHI + 32 + wo, v);
#pragma unroll
            for (int j = 0; j < 4; ++j) *(uint4*)&v[4 * j] = rq[10 + j];
            TMST_X16(ts + TM_ALO + wo, v);
#pragma unroll
            for (int j = 0; j < 4; ++j) *(uint4*)&v[4 * j] = rq[14 + j];
            TMST_X16(ts + TM_ALO + 16 + wo, v);
#pragma unroll
            for (int j = 0; j < 2; ++j) *(uint4*)&v[4 * j] = rq[18 + j];
            TMST_X8(ts + TM_ALO + 32 + wo, v);
        }
        TC_WAIT_ST();
        TC_FENCE_BEFORE();
        WG_BAR(wg);

        // ---- layer 1 MMAs: 3 terms x 5 K-steps (K=80), split bf16 ----
        if (warp_in_wg == 0 && elect_one()) {
            TC_FENCE_AFTER();
            const int doff1[5] = {0, 2, 4, 6, 512};
#pragma unroll
            for (int s = 0; s < 5; ++s)
                mma_ts(ts + TM_D, ts + TM_AHI + s * 8, d_b1h + doff1[s], IDESC_BF, s > 0);
#pragma unroll
            for (int s = 0; s < 5; ++s)
                mma_ts(ts + TM_D, ts + TM_ALO + s * 8, d_b1h + doff1[s], IDESC_BF, 1);
#pragma unroll
            for (int s = 0; s < 5; ++s)
                mma_ts(ts + TM_D, ts + TM_AHI + s * 8, d_b1l + doff1[s], IDESC_BF, 1);
            TC_COMMIT(mb);
        }

        // ---- overlap: next tile's indices + proj prefetch ----
        int nrow2 = 0, ncol2 = 0;
        int tn = t + pipes;
        if (tn < ntiles) {
            int en0 = tn * TILE + wg_tid; if (en0 >= E) en0 = E - 1;
            load_idx(eidx_raw, is64, E, en0, nrow2, ncol2);
            PF_L2(g_projh + (size_t)nrow2 * 128);
            PF_L2(g_projh + (size_t)ncol2 * 128 + 64);
        }

        MB_WAIT(mb, ph); ph ^= 1;
        TC_FENCE_AFTER();

        // ---- epilogue 1: h = silu(d + b1 + proj_i + proj_j) -> fp16 ----
        {
            const uint4* pI4 = (const uint4*)(g_projh + (size_t)nrow * 128);
            const uint4* pJ4 = (const uint4*)(g_projh + (size_t)ncol * 128 + 64);
            const float4* Bv = (const float4*)(smraw + SM_B1V);
#pragma unroll
            for (int half = 0; half < 2; ++half) {
                uint32_t dr[32];
                TMLD_X32(dr, ts + TM_D + half * 32 + wo);
                uint32_t wi[16], wj[16];
#pragma unroll
                for (int j = 0; j < 4; ++j) {
                    *(uint4*)&wi[4 * j] = pI4[4 * half + j];
                    *(uint4*)&wj[4 * j] = pJ4[4 * half + j];
                }
                TC_WAIT_LD();
                uint32_t hh[16];
#pragma unroll
                for (int q = 0; q < 8; ++q) {
                    int qq = half * 8 + q;
                    float2 piA = uph(wi[2 * q]), piB = uph(wi[2 * q + 1]);
                    float2 pjA = uph(wj[2 * q]), pjB = uph(wj[2 * q + 1]);
                    float4 bb = Bv[qq];
                    float v0 = silu_f(__uint_as_float(dr[4 * q + 0]) + bb.x + piA.x + pjA.x);
                    float v1 = silu_f(__uint_as_float(dr[4 * q + 1]) + bb.y + piA.y + pjA.y);
                    float v2 = silu_f(__uint_as_float(dr[4 * q + 2]) + bb.z + piB.x + pjB.x);
                    float v3 = silu_f(__uint_as_float(dr[4 * q + 3]) + bb.w + piB.y + pjB.y);
                    hh[2 * q]     = pkh(v0, v1);
                    hh[2 * q + 1] = pkh(v2, v3);
                }
                TMST_X16(ts + TM_AHI + half * 16 + wo, hh);
            }
        }
        TC_WAIT_ST();
        TC_FENCE_BEFORE();
        WG_BAR(wg);

        // ---- layer 2 MMAs: 2 terms x 4 K-steps (fp16) ----
        if (warp_in_wg == 0 && elect_one()) {
            TC_FENCE_AFTER();
#pragma unroll
            for (int s = 0; s < 4; ++s)
                mma_ts(ts + TM_D, ts + TM_AHI + s * 8, d_b2h + s * 2, IDESC_FP, s > 0);
#pragma unroll
            for (int s = 0; s < 4; ++s)
                mma_ts(ts + TM_D, ts + TM_AHI + s * 8, d_b2l + s * 2, IDESC_FP, 1);
            TC_COMMIT(mb);
        }
        MB_WAIT(mb, ph); ph ^= 1;
        TC_FENCE_AFTER();

        // ---- epilogue 2: h = silu(d + b2) -> fp16 ----
        {
            const float4* Bv = (const float4*)(smraw + SM_B2V);
#pragma unroll
            for (int half = 0; half < 2; ++half) {
                uint32_t dr[32];
                TMLD_X32(dr, ts + TM_D + half * 32 + wo);
                TC_WAIT_LD();
                uint32_t hh[16];
#pragma unroll
                for (int q = 0; q < 8; ++q) {
                    int qq = half * 8 + q;
                    float4 bb = Bv[qq];
                    float v0 = silu_f(__uint_as_float(dr[4 * q + 0]) + bb.x);
                    float v1 = silu_f(__uint_as_float(dr[4 * q + 1]) + bb.y);
                    float v2 = silu_f(__uint_as_float(dr[4 * q + 2]) + bb.z);
                    float v3 = silu_f(__uint_as_float(dr[4 * q + 3]) + bb.w);
                    hh[2 * q]     = pkh(v0, v1);
                    hh[2 * q + 1] = pkh(v2, v3);
                }
                TMST_X16(ts + TM_AHI + half * 16 + wo, hh);
            }
        }
        TC_WAIT_ST();
        TC_FENCE_BEFORE();
        WG_BAR(wg);

        // ---- layer 3 MMAs: 2 terms x 4 K-steps (fp16) ----
        if (warp_in_wg == 0 && elect_one()) {
            TC_FENCE_AFTER();
#pragma unroll
            for (int s = 0; s < 4; ++s)
                mma_ts(ts + TM_D, ts + TM_AHI + s * 8, d_b3h + s * 2, IDESC_FP, s > 0);
#pragma unroll
            for (int s = 0; s < 4; ++s)
                mma_ts(ts + TM_D, ts + TM_AHI + s * 8, d_b3l + s * 2, IDESC_FP, 1);
            TC_COMMIT(mb);
        }
        MB_WAIT(mb, ph); ph ^= 1;
        TC_FENCE_AFTER();

        // ---- final: y = (hi+lo) + d + b3; LayerNorm; SMEM bounce store ----
        {
            const float4* Bv = (const float4*)(smraw + SM_B3V);
            float y[64];
            float s1 = 0.f, s2 = 0.f;
#pragma unroll
            for (int half = 0; half < 2; ++half) {
                uint32_t dr[32];
                TMLD_X32(dr, ts + TM_D + half * 32 + wo);
                TC_WAIT_LD();
                const uint4* xh = (const uint4*)(xrow) + half * 4;
                const uint4* xl = (const uint4*)(xrow + 40) + half * 4;
#pragma unroll
                for (int j = 0; j < 4; ++j) {
                    uint4 hq = xh[j], lq = xl[j];
                    const uint32_t hw[4] = {hq.x, hq.y, hq.z, hq.w};
                    const uint32_t lw[4] = {lq.x, lq.y, lq.z, lq.w};
#pragma unroll
                    for (int p = 0; p < 4; ++p) {
                        float2 xh2 = upbf(hw[p]), xl2 = upbf(lw[p]);
                        int d0 = j * 8 + 2 * p;
                        int o0 = half * 32 + d0;
                        float4 bb = Bv[o0 >> 2];
                        float bbv0 = (o0 & 2) ? bb.z : bb.x;
                        float bbv1 = (o0 & 2) ? bb.w : bb.y;
                        float v0 = xh2.x + xl2.x + __uint_as_float(dr[d0])     + bbv0;
                        float v1 = xh2.y + xl2.y + __uint_as_float(dr[d0 + 1]) + bbv1;
                        y[o0] = v0; y[o0 + 1] = v1;
                        s1 += v0 + v1;
                        s2 += v0 * v0 + v1 * v1;
                    }
                }
            }
            float mu  = s1 * (1.f / 64.f);
            float var = s2 * (1.f / 64.f) - mu * mu;
            float inv = rsqrtf(var + 1e-5f);
            {
                const float4* Gv = (const float4*)(smraw + SM_GV);
                const float4* Tv = (const float4*)(smraw + SM_BTV);
                float4* yrow = (float4*)(xs + wg_tid * XROW_U32);
#pragma unroll
                for (int q = 0; q < 16; ++q) {
                    float4 g4 = Gv[q], t4 = Tv[q], r4;
                    r4.x = (y[4 * q + 0] - mu) * inv * g4.x + t4.x;
                    r4.y = (y[4 * q + 1] - mu) * inv * g4.y + t4.y;
                    r4.z = (y[4 * q + 2] - mu) * inv * g4.z + t4.z;
                    r4.w = (y[4 * q + 3] - mu) * inv * g4.w + t4.w;
                    yrow[q] = r4;
                }
            }
        }
        WG_BAR(wg);   // all y rows in SMEM

        // ---- coalesced output store ----
#pragma unroll 4
        for (int i = wg_tid; i < TILE * 16; i += 128) {
            int r = i >> 4, q = i & 15;
            int eo = base + r;
            if (eo < E)
                ((float4*)out)[(size_t)eo * 16 + q] = *(const float4*)&xs[r * XROW_U32 + 4 * q];
        }

        WG_BAR(wg);   // buffer free before restage

        if (tn < ntiles)
            stage_tile_tc(xs, ef, rbf, tn * TILE, E, wg_tid);
        nrow = nrow2; ncol = ncol2;
    }
    __syncthreads();
    if ((tid >> 5) == 0) TC_DEALLOC(tm, 512);

#else  // ================= fp32 f32x2 fallback (non-arch-specific pass) =====

    float* wsm = smf + SM_W / 4;
    for (int i = tid; i < 64 * 64; i += 384) wsm[FB_W1E + i] = W1[i];
    for (int i = tid; i < 16 * 64; i += 384) wsm[FB_W1R + i] = W1[192 * 64 + i];
    for (int i = tid; i < 64 * 64; i += 384) wsm[FB_W2 + i] = W2[i];
    for (int i = tid; i < 64 * 64; i += 384) wsm[FB_W3 + i] = W3[i];
    __syncthreads();

    float* xs = (float*)(smraw + XS_OFF(wg));
    for (int t = blockIdx.x * 3 + wg; t < ntiles; t += pipes) {
        int base = t * TILE;
        WG_BAR(wg);
        for (int i = wg_tid; i < TILE * 16; i += 128) {
            int r = i >> 4, q = i & 15;
            int e = base + r; if (e >= E) e = E - 1;
            *(float4*)&xs[r * XROW_U32 + q * 4] = ((const float4*)ef)[(size_t)e * 16 + q];
        }
        for (int i = wg_tid; i < TILE * 4; i += 128) {
            int r = i >> 2, q = i & 3;
            int e = base + r; if (e >= E) e = E - 1;
            *(float4*)&xs[r * XROW_U32 + 64 + q * 4] = ((const float4*)rbf)[(size_t)e * 4 + q];
        }
        WG_BAR(wg);

        int e = base + wg_tid;
        int eld = (e < E) ? e : (E - 1);
        int nrow, ncol;
        load_idx(eidx_raw, is64, E, eld, nrow, ncol);

        const __half2* pIh = (const __half2*)(g_projh + (size_t)nrow * 128);
        const __half2* pJh = (const __half2*)(g_projh + (size_t)ncol * 128 + 64);
        const float* xr = xs + wg_tid * XROW_U32;

        ull acc[32];
#pragma unroll
        for (int m = 0; m < 16; ++m) {
            float4 bb = ((const float4*)(smraw + SM_B1V))[m];
            float2 a01 = __half22float2(pIh[2 * m]);
            float2 a23 = __half22float2(pIh[2 * m + 1]);
            float2 b01 = __half22float2(pJh[2 * m]);
            float2 b23 = __half22float2(pJh[2 * m + 1]);
            acc[2 * m]     = pk2(bb.x + a01.x + b01.x, bb.y + a01.y + b01.y);
            acc[2 * m + 1] = pk2(bb.z + a23.x + b23.x, bb.w + a23.y + b23.y);
        }
#pragma unroll
        for (int k = 0; k < 64; ++k) gemm_step(acc, xr[k], wsm + FB_W1E + k * 64);
#pragma unroll
        for (int k = 0; k < 16; ++k) gemm_step(acc, xr[64 + k], wsm + FB_W1R + k * 64);

        float h[64];
#pragma unroll
        for (int p = 0; p < 32; ++p) {
            float a, b; upk2(acc[p], a, b);
            h[2 * p] = silu_f(a); h[2 * p + 1] = silu_f(b);
        }
#pragma unroll
        for (int m = 0; m < 16; ++m) {
            float4 bb = ((const float4*)(smraw + SM_B2V))[m];
            acc[2 * m] = pk2(bb.x, bb.y); acc[2 * m + 1] = pk2(bb.z, bb.w);
        }
#pragma unroll
        for (int k = 0; k < 64; ++k) gemm_step(acc, h[k], wsm + FB_W2 + k * 64);
#pragma unroll
        for (int p = 0; p < 32; ++p) {
            float a, b; upk2(acc[p], a, b);
            h[2 * p] = silu_f(a); h[2 * p + 1] = silu_f(b);
        }
#pragma unroll
        for (int m = 0; m < 16; ++m) {
            float4 bb = ((const float4*)(smraw + SM_B3V))[m];
            acc[2 * m] = pk2(bb.x, bb.y); acc[2 * m + 1] = pk2(bb.z, bb.w);
        }
#pragma unroll
        for (int k = 0; k < 64; ++k) gemm_step(acc, h[k], wsm + FB_W3 + k * 64);

        float y[64];
        float s1 = 0.f, s2 = 0.f;
#pragma unroll
        for (int p = 0; p < 32; ++p) {
            float a, b; upk2(acc[p], a, b);
            float ya = xr[2 * p] + a, yb = xr[2 * p + 1] + b;
            y[2 * p] = ya; y[2 * p + 1] = yb;
            s1 += ya + yb; s2 += ya * ya + yb * yb;
        }
        float mu  = s1 * (1.f / 64.f);
        float var = s2 * (1.f / 64.f) - mu * mu;
        float inv = rsqrtf(var + 1e-5f);
        if (e < E) {
            float4* o = (float4*)(out + (size_t)e * 64);
#pragma unroll
            for (int q = 0; q < 16; ++q) {
                float4 g4 = ((const float4*)(smraw + SM_GV))[q];
                float4 t4 = ((const float4*)(smraw + SM_BTV))[q];
                float4 r4;
                r4.x = (y[4 * q + 0] - mu) * inv * g4.x + t4.x;
                r4.y = (y[4 * q + 1] - mu) * inv * g4.y + t4.y;
                r4.z = (y[4 * q + 2] - mu) * inv * g4.z + t4.z;
                r4.w = (y[4 * q + 3] - mu) * inv * g4.w + t4.w;
                o[q] = r4;
            }
        }
        WG_BAR(wg);
    }
#endif
}

// ---------------------------------------------------------------------------
extern "C" void kernel_launch(void* const* d_in, const int* in_sizes, int n_in,
                              void* d_out, int out_size) {
    const float* ef   = (const float*)d_in[0];
    const float* nf   = (const float*)d_in[1];
    const void*  eidx = (const void*)d_in[2];
    const float* rbf  = (const float*)d_in[3];
    const float* W1   = (const float*)d_in[4];
    const float* b1   = (const float*)d_in[5];
    const float* W2   = (const float*)d_in[6];
    const float* b2   = (const float*)d_in[7];
    const float* W3   = (const float*)d_in[8];
    const float* b3   = (const float*)d_in[9];
    const float* gam  = (const float*)d_in[10];
    const float* bet  = (const float*)d_in[11];
    float* out = (float*)d_out;

    int E = in_sizes[0] / 64;
    int N = in_sizes[1] / 64;
    if (N > N_NODES_MAX) N = N_NODES_MAX;

    detect_idx_kernel<<<1, 1>>>((const unsigned int*)eidx);
    prep_w_kernel<<<32, 256>>>(W1, W2, W3);
    node_proj_kernel<<<(N + 15) / 16, 256>>>(nf, W1, N);

    int ntiles = (E + TILE - 1) / TILE;
    int grid = 148;
    if (grid > (ntiles + 2) / 3) grid = (ntiles + 2) / 3;
    if (grid < 1) grid = 1;
    cudaFuncSetAttribute(edge_tc_kernel,
                         cudaFuncAttributeMaxDynamicSharedMemorySize, SMEM_BYTES);
    edge_tc_kernel<<<grid, 384, SMEM_BYTES>>>(
        ef, eidx, rbf, W1, W2, W3, b1, b2, b3, gam, bet, out, E, ntiles);
}